// round 1
// baseline (speedup 1.0000x reference)
#include <cuda_runtime.h>
#include <math.h>

#define H_ 56
#define W_ 56
#define HW_ 3136
#define N_ 16
#define C_ 256
#define EPSBN 1e-3f

// Scratch: stacked GEMM output y[n][o][hw], o in [0,96):
//   rows  0..15  = x1 (conv1_w @ x)
//   rows 16..31  = x2 (conv2_w @ x)
//   rows 32..95  = x3 (conv3_w @ x)
__device__ float g_y[N_ * 96 * HW_];

// -------------------------------------------------------------------------
// Kernel 1: fused GEMM for the three 1x1 convs.
// y[n, 0:96, hw] = W[96,256] @ x[n, :, hw]
// Block: 256 threads, tile = 96 outputs x 64 pixels, BK=16.
// -------------------------------------------------------------------------
__global__ __launch_bounds__(256) void sam_gemm96_kernel(
    const float* __restrict__ x,
    const float* __restrict__ w1,
    const float* __restrict__ w2,
    const float* __restrict__ w3) {
    __shared__ float Ws[96][17];   // +1 pad to avoid bank conflicts
    __shared__ float Xs[16][64];

    const int n  = blockIdx.y;
    const int p0 = blockIdx.x * 64;        // 3136 / 64 = 49 exact
    const int tid = threadIdx.x;
    const int tx = tid & 15;               // pixel sub-index
    const int ty = tid >> 4;               // output sub-index

    const float* xn = x + (size_t)n * C_ * HW_;

    float acc[6][4];
#pragma unroll
    for (int r = 0; r < 6; r++)
#pragma unroll
        for (int s = 0; s < 4; s++) acc[r][s] = 0.0f;

    for (int k0 = 0; k0 < C_; k0 += 16) {
        // Load weight tile: 96x16 = 1536 elems, 6 per thread
#pragma unroll
        for (int i = 0; i < 6; i++) {
            int idx = tid + i * 256;
            int o = idx >> 4;
            int k = idx & 15;
            float v;
            if (o < 16)       v = w1[o * C_ + k0 + k];
            else if (o < 32)  v = w2[(o - 16) * C_ + k0 + k];
            else              v = w3[(o - 32) * C_ + k0 + k];
            Ws[o][k] = v;
        }
        // Load X tile: 16x64 = 1024 elems, 4 per thread (coalesced over pixels)
#pragma unroll
        for (int i = 0; i < 4; i++) {
            int idx = tid + i * 256;
            int k = idx >> 6;
            int p = idx & 63;
            Xs[k][p] = xn[(size_t)(k0 + k) * HW_ + p0 + p];
        }
        __syncthreads();

#pragma unroll
        for (int k = 0; k < 16; k++) {
            float xr[4], wr[6];
#pragma unroll
            for (int s = 0; s < 4; s++) xr[s] = Xs[k][tx + 16 * s];
#pragma unroll
            for (int r = 0; r < 6; r++) wr[r] = Ws[ty + 16 * r][k];
#pragma unroll
            for (int r = 0; r < 6; r++)
#pragma unroll
                for (int s = 0; s < 4; s++)
                    acc[r][s] = fmaf(wr[r], xr[s], acc[r][s]);
        }
        __syncthreads();
    }

    float* yn = g_y + (size_t)n * 96 * HW_;
#pragma unroll
    for (int r = 0; r < 6; r++) {
        int o = ty + 16 * r;
#pragma unroll
        for (int s = 0; s < 4; s++) {
            yn[(size_t)o * HW_ + p0 + tx + 16 * s] = acc[r][s];
        }
    }
}

// -------------------------------------------------------------------------
// Kernel 2: fused attention. One thread per (n, hw).
//   rel = [x1 - unfold(x2); p - unfold(p)]  (18 ch x 9 window)
//   h   = relu(bn1(rel));  h1 = W1[16,18] @ h
//   h   = relu(bn2(h1));   h2 = W2[8,16]  @ h
//   w   = softmax over window axis (9)
//   out[g*8+c] = sum_j w[c][j] * x3u[g*8+c][j]
// BN params are per-hw scalars (broadcast over channel & window axes).
// -------------------------------------------------------------------------
__global__ __launch_bounds__(256) void sam_attn_kernel(
    const float* __restrict__ convp,   // [2,2]
    const float* __restrict__ w1c,     // [16,18]
    const float* __restrict__ w2c,     // [8,16]
    const float* __restrict__ g1, const float* __restrict__ b1,
    const float* __restrict__ m1, const float* __restrict__ v1,
    const float* __restrict__ g2, const float* __restrict__ b2,
    const float* __restrict__ m2, const float* __restrict__ v2,
    float* __restrict__ out) {
    __shared__ float sw1[16][18];
    __shared__ float sw2[8][16];
    __shared__ float scp[4];

    const int tid = threadIdx.x;
    for (int i = tid; i < 288; i += 256) sw1[i / 18][i % 18] = w1c[i];
    if (tid < 128) sw2[tid / 16][tid % 16] = w2c[tid];
    if (tid < 4)   scp[tid] = convp[tid];
    __syncthreads();

    const int n  = blockIdx.y;
    const int hw = blockIdx.x * 256 + tid;
    if (hw >= HW_) return;

    const int h = hw / W_;
    const int w = hw % W_;

    const float* yn = g_y + (size_t)n * 96 * HW_;

    // Per-pixel BN affine: y = x*s + o
    const float s1 = g1[hw] * rsqrtf(v1[hw] + EPSBN);
    const float o1 = b1[hw] - m1[hw] * s1;
    const float s2 = g2[hw] * rsqrtf(v2[hw] + EPSBN);
    const float o2 = b2[hw] - m2[hw] * s2;

    // Center features x1[16]
    float x1v[16];
#pragma unroll
    for (int c = 0; c < 16; c++) x1v[c] = yn[(size_t)c * HW_ + hw];

    // Center position features
    const float lw = -1.0f + 2.0f * (float)w / 55.0f;
    const float lh = -1.0f + 2.0f * (float)h / 55.0f;
    const float p0 = scp[0] * lw + scp[1] * lh;
    const float p1 = scp[2] * lw + scp[3] * lh;

    // Precompute reflected neighbor offsets for the 9 window positions
    int nhw9[9];
    int nw9[9], nh9[9];
#pragma unroll
    for (int jj = 0; jj < 9; jj++) {
        int di = jj / 3 - 1;
        int dj = jj % 3 - 1;
        int nh = h + di;
        nh = (nh < 0) ? -nh : ((nh >= H_) ? 2 * H_ - 2 - nh : nh);
        int nw = w + dj;
        nw = (nw < 0) ? -nw : ((nw >= W_) ? 2 * W_ - 2 - nw : nw);
        nh9[jj] = nh; nw9[jj] = nw;
        nhw9[jj] = nh * W_ + nw;
    }

    // Phase 1: attention logits sc[q][jj], q in [0,8)
    float sc[8][9];
#pragma unroll
    for (int jj = 0; jj < 9; jj++) {
        const int nhw = nhw9[jj];
        float a[18];
#pragma unroll
        for (int c = 0; c < 16; c++) {
            float r = x1v[c] - yn[(size_t)(16 + c) * HW_ + nhw];
            a[c] = fmaxf(fmaf(r, s1, o1), 0.0f);
        }
        const float nlw = -1.0f + 2.0f * (float)nw9[jj] / 55.0f;
        const float nlh = -1.0f + 2.0f * (float)nh9[jj] / 55.0f;
        const float pn0 = scp[0] * nlw + scp[1] * nlh;
        const float pn1 = scp[2] * nlw + scp[3] * nlh;
        a[16] = fmaxf(fmaf(p0 - pn0, s1, o1), 0.0f);
        a[17] = fmaxf(fmaf(p1 - pn1, s1, o1), 0.0f);

        float hb[16];
#pragma unroll
        for (int o = 0; o < 16; o++) {
            float t = 0.0f;
#pragma unroll
            for (int c = 0; c < 18; c++) t = fmaf(sw1[o][c], a[c], t);
            hb[o] = fmaxf(fmaf(t, s2, o2), 0.0f);
        }
#pragma unroll
        for (int q = 0; q < 8; q++) {
            float t = 0.0f;
#pragma unroll
            for (int o = 0; o < 16; o++) t = fmaf(sw2[q][o], hb[o], t);
            sc[q][jj] = t;
        }
    }

    // Softmax over the 9-window axis, per q
#pragma unroll
    for (int q = 0; q < 8; q++) {
        float mx = sc[q][0];
#pragma unroll
        for (int jj = 1; jj < 9; jj++) mx = fmaxf(mx, sc[q][jj]);
        float sum = 0.0f;
#pragma unroll
        for (int jj = 0; jj < 9; jj++) {
            float e = __expf(sc[q][jj] - mx);
            sc[q][jj] = e;
            sum += e;
        }
        float inv = 1.0f / sum;
#pragma unroll
        for (int jj = 0; jj < 9; jj++) sc[q][jj] *= inv;
    }

    // Aggregation: out[g*8+c] = sum_j sc[c][j] * x3u[g*8+c][j]
    float* on = out + (size_t)n * 64 * HW_;
#pragma unroll
    for (int g = 0; g < 8; g++) {
        float acc[8];
#pragma unroll
        for (int c = 0; c < 8; c++) acc[c] = 0.0f;
#pragma unroll
        for (int jj = 0; jj < 9; jj++) {
            const int nhw = nhw9[jj];
#pragma unroll
            for (int c = 0; c < 8; c++) {
                float xv = yn[(size_t)(32 + g * 8 + c) * HW_ + nhw];
                acc[c] = fmaf(sc[c][jj], xv, acc[c]);
            }
        }
#pragma unroll
        for (int c = 0; c < 8; c++) {
            on[(size_t)(g * 8 + c) * HW_ + hw] = acc[c];
        }
    }
}

// -------------------------------------------------------------------------
// Launcher. Input order (metadata.txt):
// 0 x, 1 conv1_w, 2 conv2_w, 3 conv3_w, 4 convp_w, 5 convw1_w, 6 convw2_w,
// 7 bn1_gamma, 8 bn1_beta, 9 bn1_mean, 10 bn1_var,
// 11 bn2_gamma, 12 bn2_beta, 13 bn2_mean, 14 bn2_var
// -------------------------------------------------------------------------
extern "C" void kernel_launch(void* const* d_in, const int* in_sizes, int n_in,
                              void* d_out, int out_size) {
    const float* x   = (const float*)d_in[0];
    const float* w1  = (const float*)d_in[1];
    const float* w2  = (const float*)d_in[2];
    const float* w3  = (const float*)d_in[3];
    const float* cp  = (const float*)d_in[4];
    const float* cw1 = (const float*)d_in[5];
    const float* cw2 = (const float*)d_in[6];
    const float* g1  = (const float*)d_in[7];
    const float* b1  = (const float*)d_in[8];
    const float* m1  = (const float*)d_in[9];
    const float* v1  = (const float*)d_in[10];
    const float* g2  = (const float*)d_in[11];
    const float* b2  = (const float*)d_in[12];
    const float* m2  = (const float*)d_in[13];
    const float* v2  = (const float*)d_in[14];
    float* out = (float*)d_out;

    dim3 gg(HW_ / 64, N_);            // 49 x 16
    sam_gemm96_kernel<<<gg, 256>>>(x, w1, w2, w3);

    dim3 ga((HW_ + 255) / 256, N_);   // 13 x 16
    sam_attn_kernel<<<ga, 256>>>(cp, cw1, cw2,
                                 g1, b1, m1, v1,
                                 g2, b2, m2, v2, out);
}

// round 2
// speedup vs baseline: 1.3138x; 1.3138x over previous
#include <cuda_runtime.h>
#include <math.h>

#define H_ 56
#define W_ 56
#define HW_ 3136
#define N_ 16
#define C_ 256
#define EPSBN 1e-3f

// Scratch: stacked GEMM output y[n][o][hw], o in [0,96):
//   rows  0..15  = x1, rows 16..31 = x2, rows 32..95 = x3
__device__ float g_y[N_ * 96 * HW_];

// f32x2 packed FMA: d.lo = a.lo*b.lo + c.lo ; d.hi = a.hi*b.hi + c.hi (RN)
__device__ __forceinline__ void ffma2(unsigned long long& acc,
                                      unsigned long long a,
                                      unsigned long long b) {
    asm("fma.rn.f32x2 %0, %1, %2, %0;" : "+l"(acc) : "l"(a), "l"(b));
}

// -------------------------------------------------------------------------
// Kernel 1: fused GEMM for the three 1x1 convs via packed f32x2 FMA.
// y[n, 0:96, hw] = W[96,256] @ x[n, :, hw]
// Block: 128 threads, tile = 96 outputs x 64 pixels, BK=16.
// Thread tile: 6 output rows x 8 pixels (4 packed pairs).
// -------------------------------------------------------------------------
__global__ __launch_bounds__(128) void sam_gemm96_kernel(
    const float* __restrict__ x,
    const float* __restrict__ w1,
    const float* __restrict__ w2,
    const float* __restrict__ w3) {
    __shared__ alignas(16) unsigned long long Wd[96][16]; // weight dup-packed (w,w)
    __shared__ alignas(16) float Xs[16][64];

    const int n   = blockIdx.y;
    const int p0  = blockIdx.x * 64;      // 3136/64 = 49 exact
    const int tid = threadIdx.x;
    const int tx  = tid & 7;              // pixel-octet index (8 px)
    const int ty  = tid >> 3;             // 0..15, rows ty + 16*r

    const float* xn = x + (size_t)n * C_ * HW_;

    unsigned long long acc[6][4];
#pragma unroll
    for (int r = 0; r < 6; r++)
#pragma unroll
        for (int s = 0; s < 4; s++) acc[r][s] = 0ull;

    for (int k0 = 0; k0 < C_; k0 += 16) {
        // Fill Wd: 96x16 u64 = 1536, 12 per thread. Duplicate into both lanes.
#pragma unroll
        for (int i = 0; i < 12; i++) {
            int idx = tid + i * 128;
            int o = idx >> 4;
            int k = idx & 15;
            float v;
            if (o < 16)       v = w1[o * C_ + k0 + k];
            else if (o < 32)  v = w2[(o - 16) * C_ + k0 + k];
            else              v = w3[(o - 32) * C_ + k0 + k];
            unsigned int b = __float_as_uint(v);
            Wd[o][k] = ((unsigned long long)b << 32) | (unsigned long long)b;
        }
        // Fill Xs: 16x64 floats, 2 float4 per thread, coalesced.
#pragma unroll
        for (int i = 0; i < 2; i++) {
            int f4 = tid + i * 128;
            int k  = f4 >> 4;
            int p4 = f4 & 15;
            float4 v = *(const float4*)(xn + (size_t)(k0 + k) * HW_ + p0 + p4 * 4);
            *(float4*)&Xs[k][p4 * 4] = v;
        }
        __syncthreads();

#pragma unroll
        for (int k = 0; k < 16; k++) {
            ulonglong2 xa = *(const ulonglong2*)&Xs[k][tx * 8];
            ulonglong2 xb = *(const ulonglong2*)&Xs[k][tx * 8 + 4];
            unsigned long long xp[4] = {xa.x, xa.y, xb.x, xb.y};
            unsigned long long wv[6];
#pragma unroll
            for (int r = 0; r < 6; r++) wv[r] = Wd[ty + 16 * r][k];
#pragma unroll
            for (int r = 0; r < 6; r++)
#pragma unroll
                for (int s = 0; s < 4; s++)
                    ffma2(acc[r][s], wv[r], xp[s]);
        }
        __syncthreads();
    }

    float* yn = g_y + (size_t)n * 96 * HW_;
#pragma unroll
    for (int r = 0; r < 6; r++) {
        int o = ty + 16 * r;
        ulonglong2 va; va.x = acc[r][0]; va.y = acc[r][1];
        ulonglong2 vb; vb.x = acc[r][2]; vb.y = acc[r][3];
        *(ulonglong2*)&yn[(size_t)o * HW_ + p0 + tx * 8]     = va;
        *(ulonglong2*)&yn[(size_t)o * HW_ + p0 + tx * 8 + 4] = vb;
    }
}

// -------------------------------------------------------------------------
// Kernel 2: fused attention, 3 phases per 32-pixel block, 288 threads.
//   P1 (t=(jj,pix)): rel -> bn1 -> relu -> W1 -> bn2 -> relu -> W2 -> smem
//   P2 (t=(q,pix)):  softmax over 9 window positions
//   P3 (t=(g,pix)):  weighted aggregation of x3 neighbors
// -------------------------------------------------------------------------
__global__ __launch_bounds__(288) void sam_attn_kernel(
    const float* __restrict__ convp,   // [2,2]
    const float* __restrict__ w1c,     // [16,18]
    const float* __restrict__ w2c,     // [8,16]
    const float* __restrict__ g1, const float* __restrict__ b1,
    const float* __restrict__ m1, const float* __restrict__ v1,
    const float* __restrict__ g2, const float* __restrict__ b2,
    const float* __restrict__ m2, const float* __restrict__ v2,
    float* __restrict__ out) {
    __shared__ alignas(16) float sw1[16][20];  // rows 16B-aligned (18 used)
    __shared__ alignas(16) float sw2[8][16];
    __shared__ float scp[4];
    __shared__ float sc_s[32 * 73];            // [pix][jj*8+q], stride 73 (odd)

    const int t = threadIdx.x;
    if (t < 288) sw1[t / 18][t % 18] = w1c[t];
    if (t < 128) sw2[t / 16][t % 16] = w2c[t];
    if (t < 4)   scp[t] = convp[t];
    __syncthreads();

    const int n   = blockIdx.y;
    const int hw0 = blockIdx.x * 32;           // 3136/32 = 98 exact
    const int pix = t & 31;
    const int jj  = t >> 5;                    // 0..8
    const int hw  = hw0 + pix;
    const int h   = hw / W_;
    const int w   = hw % W_;

    const float* yn = g_y + (size_t)n * 96 * HW_;

    // Per-pixel BN affine: y = x*s + o
    const float s1 = g1[hw] * rsqrtf(v1[hw] + EPSBN);
    const float o1 = b1[hw] - m1[hw] * s1;
    const float s2 = g2[hw] * rsqrtf(v2[hw] + EPSBN);
    const float o2 = b2[hw] - m2[hw] * s2;

    // ---- Phase 1: logits for this (pix, jj) ----
    {
        int di = jj / 3 - 1, dj = jj % 3 - 1;
        int nh = h + di;
        nh = (nh < 0) ? -nh : ((nh >= H_) ? 2 * H_ - 2 - nh : nh);
        int nw = w + dj;
        nw = (nw < 0) ? -nw : ((nw >= W_) ? 2 * W_ - 2 - nw : nw);
        const int nhw = nh * W_ + nw;

        float a[18];
#pragma unroll
        for (int c = 0; c < 16; c++) {
            float r = yn[(size_t)c * HW_ + hw] - yn[(size_t)(16 + c) * HW_ + nhw];
            a[c] = fmaxf(fmaf(r, s1, o1), 0.0f);
        }
        const float lw  = -1.0f + 2.0f * (float)w  / 55.0f;
        const float lh  = -1.0f + 2.0f * (float)h  / 55.0f;
        const float nlw = -1.0f + 2.0f * (float)nw / 55.0f;
        const float nlh = -1.0f + 2.0f * (float)nh / 55.0f;
        const float dp0 = scp[0] * (lw - nlw) + scp[1] * (lh - nlh);
        const float dp1 = scp[2] * (lw - nlw) + scp[3] * (lh - nlh);
        a[16] = fmaxf(fmaf(dp0, s1, o1), 0.0f);
        a[17] = fmaxf(fmaf(dp1, s1, o1), 0.0f);

        float hb[16];
#pragma unroll
        for (int o = 0; o < 16; o++) {
            const float4* wr = (const float4*)&sw1[o][0];
            float4 w0 = wr[0], w1v = wr[1], w2v = wr[2], w3v = wr[3];
            float tacc = 0.0f;
            tacc = fmaf(w0.x,  a[0],  tacc); tacc = fmaf(w0.y,  a[1],  tacc);
            tacc = fmaf(w0.z,  a[2],  tacc); tacc = fmaf(w0.w,  a[3],  tacc);
            tacc = fmaf(w1v.x, a[4],  tacc); tacc = fmaf(w1v.y, a[5],  tacc);
            tacc = fmaf(w1v.z, a[6],  tacc); tacc = fmaf(w1v.w, a[7],  tacc);
            tacc = fmaf(w2v.x, a[8],  tacc); tacc = fmaf(w2v.y, a[9],  tacc);
            tacc = fmaf(w2v.z, a[10], tacc); tacc = fmaf(w2v.w, a[11], tacc);
            tacc = fmaf(w3v.x, a[12], tacc); tacc = fmaf(w3v.y, a[13], tacc);
            tacc = fmaf(w3v.z, a[14], tacc); tacc = fmaf(w3v.w, a[15], tacc);
            tacc = fmaf(sw1[o][16], a[16], tacc);
            tacc = fmaf(sw1[o][17], a[17], tacc);
            hb[o] = fmaxf(fmaf(tacc, s2, o2), 0.0f);
        }
        float* dst = &sc_s[pix * 73 + jj * 8];
#pragma unroll
        for (int q = 0; q < 8; q++) {
            const float4* wr = (const float4*)&sw2[q][0];
            float4 w0 = wr[0], w1v = wr[1], w2v = wr[2], w3v = wr[3];
            float tacc = 0.0f;
            tacc = fmaf(w0.x,  hb[0],  tacc); tacc = fmaf(w0.y,  hb[1],  tacc);
            tacc = fmaf(w0.z,  hb[2],  tacc); tacc = fmaf(w0.w,  hb[3],  tacc);
            tacc = fmaf(w1v.x, hb[4],  tacc); tacc = fmaf(w1v.y, hb[5],  tacc);
            tacc = fmaf(w1v.z, hb[6],  tacc); tacc = fmaf(w1v.w, hb[7],  tacc);
            tacc = fmaf(w2v.x, hb[8],  tacc); tacc = fmaf(w2v.y, hb[9],  tacc);
            tacc = fmaf(w2v.z, hb[10], tacc); tacc = fmaf(w2v.w, hb[11], tacc);
            tacc = fmaf(w3v.x, hb[12], tacc); tacc = fmaf(w3v.y, hb[13], tacc);
            tacc = fmaf(w3v.z, hb[14], tacc); tacc = fmaf(w3v.w, hb[15], tacc);
            dst[q] = tacc;
        }
    }
    __syncthreads();

    // ---- Phase 2: softmax over jj, thread = (q, pix) ----
    if (t < 256) {
        const int q = t >> 5;
        float* base = &sc_s[pix * 73 + q];
        float v[9];
#pragma unroll
        for (int j = 0; j < 9; j++) v[j] = base[j * 8];
        float mx = v[0];
#pragma unroll
        for (int j = 1; j < 9; j++) mx = fmaxf(mx, v[j]);
        float sum = 0.0f;
#pragma unroll
        for (int j = 0; j < 9; j++) { v[j] = __expf(v[j] - mx); sum += v[j]; }
        float inv = 1.0f / sum;
#pragma unroll
        for (int j = 0; j < 9; j++) base[j * 8] = v[j] * inv;
    }
    __syncthreads();

    // ---- Phase 3: aggregation, thread = (g, pix) ----
    if (t < 256) {
        const int g = t >> 5;
        int nhw9[9];
#pragma unroll
        for (int j = 0; j < 9; j++) {
            int nh = h + j / 3 - 1;
            nh = (nh < 0) ? -nh : ((nh >= H_) ? 2 * H_ - 2 - nh : nh);
            int nw = w + j % 3 - 1;
            nw = (nw < 0) ? -nw : ((nw >= W_) ? 2 * W_ - 2 - nw : nw);
            nhw9[j] = nh * W_ + nw;
        }
        const float* ws = &sc_s[pix * 73];
        const float* y3 = yn + (size_t)(32 + g * 8) * HW_;
        float acc[8];
#pragma unroll
        for (int c = 0; c < 8; c++) acc[c] = 0.0f;
#pragma unroll
        for (int j = 0; j < 9; j++) {
            const int nhw = nhw9[j];
#pragma unroll
            for (int c = 0; c < 8; c++)
                acc[c] = fmaf(ws[j * 8 + c], y3[(size_t)c * HW_ + nhw], acc[c]);
        }
        float* on = out + (size_t)n * 64 * HW_ + (size_t)g * 8 * HW_ + hw;
#pragma unroll
        for (int c = 0; c < 8; c++) on[(size_t)c * HW_] = acc[c];
    }
}

// -------------------------------------------------------------------------
// Launcher.
// -------------------------------------------------------------------------
extern "C" void kernel_launch(void* const* d_in, const int* in_sizes, int n_in,
                              void* d_out, int out_size) {
    const float* x   = (const float*)d_in[0];
    const float* w1  = (const float*)d_in[1];
    const float* w2  = (const float*)d_in[2];
    const float* w3  = (const float*)d_in[3];
    const float* cp  = (const float*)d_in[4];
    const float* cw1 = (const float*)d_in[5];
    const float* cw2 = (const float*)d_in[6];
    const float* g1  = (const float*)d_in[7];
    const float* b1  = (const float*)d_in[8];
    const float* m1  = (const float*)d_in[9];
    const float* v1  = (const float*)d_in[10];
    const float* g2  = (const float*)d_in[11];
    const float* b2  = (const float*)d_in[12];
    const float* m2  = (const float*)d_in[13];
    const float* v2  = (const float*)d_in[14];
    float* out = (float*)d_out;

    dim3 gg(HW_ / 64, N_);            // 49 x 16
    sam_gemm96_kernel<<<gg, 128>>>(x, w1, w2, w3);

    dim3 ga(HW_ / 32, N_);            // 98 x 16
    sam_attn_kernel<<<ga, 288>>>(cp, cw1, cw2,
                                 g1, b1, m1, v1,
                                 g2, b2, m2, v2, out);
}

// round 3
// speedup vs baseline: 1.7654x; 1.3437x over previous
#include <cuda_runtime.h>
#include <math.h>

#define H_ 56
#define W_ 56
#define HW_ 3136
#define N_ 16
#define C_ 256
#define EPSBN 1e-3f

// Scratch: stacked GEMM output y[n][o][hw], o in [0,96):
//   rows  0..15  = x1, rows 16..31 = x2, rows 32..95 = x3
__device__ float g_y[N_ * 96 * HW_];

// f32x2 packed FMA: d.lo = a.lo*b.lo + c.lo ; d.hi = a.hi*b.hi + c.hi (RN)
__device__ __forceinline__ void ffma2(unsigned long long& acc,
                                      unsigned long long a,
                                      unsigned long long b) {
    asm("fma.rn.f32x2 %0, %1, %2, %0;" : "+l"(acc) : "l"(a), "l"(b));
}

// -------------------------------------------------------------------------
// Kernel 1: fused GEMM for the three 1x1 convs via packed f32x2 FMA.
// y[n, 0:96, hw] = W[96,256] @ x[n, :, hw]
// Block: 256 threads. Tile: 96 rows x 128 px. BK=16.
// Thread: 6 rows (ty+16r) x 8 px (chunks at 4tx and 64+4tx).
// Conflict-free smem: Wd padded to 17 u64/row (2 distinct rows/warp, diff
// banks, broadcast = 1 wf); X chunk LDS.128 at 16B thread stride = 2 wf (min).
// -------------------------------------------------------------------------
__global__ __launch_bounds__(256) void sam_gemm96_kernel(
    const float* __restrict__ x,
    const float* __restrict__ w1,
    const float* __restrict__ w2,
    const float* __restrict__ w3) {
    __shared__ alignas(16) unsigned long long Wd[96][17]; // dup-packed (w,w)
    __shared__ alignas(16) float Xs[16][128];

    const int n   = blockIdx.y;
    const int p0  = blockIdx.x * 128;     // 25 tiles, last partial
    const int tid = threadIdx.x;
    const int tx  = tid & 15;
    const int ty  = tid >> 4;             // 0..15

    const float* xn = x + (size_t)n * C_ * HW_;

    unsigned long long acc[6][4];
#pragma unroll
    for (int r = 0; r < 6; r++)
#pragma unroll
        for (int s = 0; s < 4; s++) acc[r][s] = 0ull;

    for (int k0 = 0; k0 < C_; k0 += 16) {
        // Fill Wd: 96x16 u64 = 1536, 6 per thread, dup both lanes.
#pragma unroll
        for (int i = 0; i < 6; i++) {
            int idx = tid + i * 256;
            int o = idx >> 4;
            int k = idx & 15;
            float v;
            if (o < 16)       v = w1[o * C_ + k0 + k];
            else if (o < 32)  v = w2[(o - 16) * C_ + k0 + k];
            else              v = w3[(o - 32) * C_ + k0 + k];
            unsigned int b = __float_as_uint(v);
            Wd[o][k] = ((unsigned long long)b << 32) | (unsigned long long)b;
        }
        // Fill Xs: 16x128 floats = 512 float4, 2 per thread, coalesced.
#pragma unroll
        for (int i = 0; i < 2; i++) {
            int f4 = tid + i * 256;
            int k  = f4 >> 5;
            int c  = f4 & 31;
            int p  = p0 + c * 4;
            if (p > HW_ - 4) p = HW_ - 4;   // clamp (OOB lanes unused)
            float4 v = *(const float4*)(xn + (size_t)(k0 + k) * HW_ + p);
            *(float4*)&Xs[k][c * 4] = v;
        }
        __syncthreads();

#pragma unroll
        for (int k = 0; k < 16; k++) {
            ulonglong2 xa = *(const ulonglong2*)&Xs[k][4 * tx];
            ulonglong2 xb = *(const ulonglong2*)&Xs[k][64 + 4 * tx];
            unsigned long long wv[6];
#pragma unroll
            for (int r = 0; r < 6; r++) wv[r] = Wd[ty + 16 * r][k];
#pragma unroll
            for (int r = 0; r < 6; r++) {
                ffma2(acc[r][0], wv[r], xa.x);
                ffma2(acc[r][1], wv[r], xa.y);
                ffma2(acc[r][2], wv[r], xb.x);
                ffma2(acc[r][3], wv[r], xb.y);
            }
        }
        __syncthreads();
    }

    float* yn = g_y + (size_t)n * 96 * HW_;
    const int pA = p0 + 4 * tx;            // always <= 3132, in-bounds
    const int pB = pA + 64;                // may be OOB on last tile
#pragma unroll
    for (int r = 0; r < 6; r++) {
        int o = ty + 16 * r;
        ulonglong2 va; va.x = acc[r][0]; va.y = acc[r][1];
        *(ulonglong2*)&yn[(size_t)o * HW_ + pA] = va;
        if (pB < HW_) {
            ulonglong2 vb; vb.x = acc[r][2]; vb.y = acc[r][3];
            *(ulonglong2*)&yn[(size_t)o * HW_ + pB] = vb;
        }
    }
}

// -------------------------------------------------------------------------
// Kernel 2: fused attention, 3 phases per 32-pixel block, 288 threads.
// (unchanged from round 2 — 32us, not the bottleneck)
// -------------------------------------------------------------------------
__global__ __launch_bounds__(288) void sam_attn_kernel(
    const float* __restrict__ convp,   // [2,2]
    const float* __restrict__ w1c,     // [16,18]
    const float* __restrict__ w2c,     // [8,16]
    const float* __restrict__ g1, const float* __restrict__ b1,
    const float* __restrict__ m1, const float* __restrict__ v1,
    const float* __restrict__ g2, const float* __restrict__ b2,
    const float* __restrict__ m2, const float* __restrict__ v2,
    float* __restrict__ out) {
    __shared__ alignas(16) float sw1[16][20];
    __shared__ alignas(16) float sw2[8][16];
    __shared__ float scp[4];
    __shared__ float sc_s[32 * 73];            // [pix][jj*8+q], stride 73

    const int t = threadIdx.x;
    if (t < 288) sw1[t / 18][t % 18] = w1c[t];
    if (t < 128) sw2[t / 16][t % 16] = w2c[t];
    if (t < 4)   scp[t] = convp[t];
    __syncthreads();

    const int n   = blockIdx.y;
    const int hw0 = blockIdx.x * 32;
    const int pix = t & 31;
    const int jj  = t >> 5;                    // 0..8
    const int hw  = hw0 + pix;
    const int h   = hw / W_;
    const int w   = hw % W_;

    const float* yn = g_y + (size_t)n * 96 * HW_;

    const float s1 = g1[hw] * rsqrtf(v1[hw] + EPSBN);
    const float o1 = b1[hw] - m1[hw] * s1;
    const float s2 = g2[hw] * rsqrtf(v2[hw] + EPSBN);
    const float o2 = b2[hw] - m2[hw] * s2;

    // ---- Phase 1: logits for this (pix, jj) ----
    {
        int di = jj / 3 - 1, dj = jj % 3 - 1;
        int nh = h + di;
        nh = (nh < 0) ? -nh : ((nh >= H_) ? 2 * H_ - 2 - nh : nh);
        int nw = w + dj;
        nw = (nw < 0) ? -nw : ((nw >= W_) ? 2 * W_ - 2 - nw : nw);
        const int nhw = nh * W_ + nw;

        float a[18];
#pragma unroll
        for (int c = 0; c < 16; c++) {
            float r = yn[(size_t)c * HW_ + hw] - yn[(size_t)(16 + c) * HW_ + nhw];
            a[c] = fmaxf(fmaf(r, s1, o1), 0.0f);
        }
        const float lw  = -1.0f + 2.0f * (float)w  / 55.0f;
        const float lh  = -1.0f + 2.0f * (float)h  / 55.0f;
        const float nlw = -1.0f + 2.0f * (float)nw / 55.0f;
        const float nlh = -1.0f + 2.0f * (float)nh / 55.0f;
        const float dp0 = scp[0] * (lw - nlw) + scp[1] * (lh - nlh);
        const float dp1 = scp[2] * (lw - nlw) + scp[3] * (lh - nlh);
        a[16] = fmaxf(fmaf(dp0, s1, o1), 0.0f);
        a[17] = fmaxf(fmaf(dp1, s1, o1), 0.0f);

        float hb[16];
#pragma unroll
        for (int o = 0; o < 16; o++) {
            const float4* wr = (const float4*)&sw1[o][0];
            float4 w0 = wr[0], w1v = wr[1], w2v = wr[2], w3v = wr[3];
            float tacc = 0.0f;
            tacc = fmaf(w0.x,  a[0],  tacc); tacc = fmaf(w0.y,  a[1],  tacc);
            tacc = fmaf(w0.z,  a[2],  tacc); tacc = fmaf(w0.w,  a[3],  tacc);
            tacc = fmaf(w1v.x, a[4],  tacc); tacc = fmaf(w1v.y, a[5],  tacc);
            tacc = fmaf(w1v.z, a[6],  tacc); tacc = fmaf(w1v.w, a[7],  tacc);
            tacc = fmaf(w2v.x, a[8],  tacc); tacc = fmaf(w2v.y, a[9],  tacc);
            tacc = fmaf(w2v.z, a[10], tacc); tacc = fmaf(w2v.w, a[11], tacc);
            tacc = fmaf(w3v.x, a[12], tacc); tacc = fmaf(w3v.y, a[13], tacc);
            tacc = fmaf(w3v.z, a[14], tacc); tacc = fmaf(w3v.w, a[15], tacc);
            tacc = fmaf(sw1[o][16], a[16], tacc);
            tacc = fmaf(sw1[o][17], a[17], tacc);
            hb[o] = fmaxf(fmaf(tacc, s2, o2), 0.0f);
        }
        float* dst = &sc_s[pix * 73 + jj * 8];
#pragma unroll
        for (int q = 0; q < 8; q++) {
            const float4* wr = (const float4*)&sw2[q][0];
            float4 w0 = wr[0], w1v = wr[1], w2v = wr[2], w3v = wr[3];
            float tacc = 0.0f;
            tacc = fmaf(w0.x,  hb[0],  tacc); tacc = fmaf(w0.y,  hb[1],  tacc);
            tacc = fmaf(w0.z,  hb[2],  tacc); tacc = fmaf(w0.w,  hb[3],  tacc);
            tacc = fmaf(w1v.x, hb[4],  tacc); tacc = fmaf(w1v.y, hb[5],  tacc);
            tacc = fmaf(w1v.z, hb[6],  tacc); tacc = fmaf(w1v.w, hb[7],  tacc);
            tacc = fmaf(w2v.x, hb[8],  tacc); tacc = fmaf(w2v.y, hb[9],  tacc);
            tacc = fmaf(w2v.z, hb[10], tacc); tacc = fmaf(w2v.w, hb[11], tacc);
            tacc = fmaf(w3v.x, hb[12], tacc); tacc = fmaf(w3v.y, hb[13], tacc);
            tacc = fmaf(w3v.z, hb[14], tacc); tacc = fmaf(w3v.w, hb[15], tacc);
            dst[q] = tacc;
        }
    }
    __syncthreads();

    // ---- Phase 2: softmax over jj, thread = (q, pix) ----
    if (t < 256) {
        const int q = t >> 5;
        float* base = &sc_s[pix * 73 + q];
        float v[9];
#pragma unroll
        for (int j = 0; j < 9; j++) v[j] = base[j * 8];
        float mx = v[0];
#pragma unroll
        for (int j = 1; j < 9; j++) mx = fmaxf(mx, v[j]);
        float sum = 0.0f;
#pragma unroll
        for (int j = 0; j < 9; j++) { v[j] = __expf(v[j] - mx); sum += v[j]; }
        float inv = 1.0f / sum;
#pragma unroll
        for (int j = 0; j < 9; j++) base[j * 8] = v[j] * inv;
    }
    __syncthreads();

    // ---- Phase 3: aggregation, thread = (g, pix) ----
    if (t < 256) {
        const int g = t >> 5;
        int nhw9[9];
#pragma unroll
        for (int j = 0; j < 9; j++) {
            int nh = h + j / 3 - 1;
            nh = (nh < 0) ? -nh : ((nh >= H_) ? 2 * H_ - 2 - nh : nh);
            int nw = w + j % 3 - 1;
            nw = (nw < 0) ? -nw : ((nw >= W_) ? 2 * W_ - 2 - nw : nw);
            nhw9[j] = nh * W_ + nw;
        }
        const float* ws = &sc_s[pix * 73];
        const float* y3 = yn + (size_t)(32 + g * 8) * HW_;
        float acc[8];
#pragma unroll
        for (int c = 0; c < 8; c++) acc[c] = 0.0f;
#pragma unroll
        for (int j = 0; j < 9; j++) {
            const int nhw = nhw9[j];
#pragma unroll
            for (int c = 0; c < 8; c++)
                acc[c] = fmaf(ws[j * 8 + c], y3[(size_t)c * HW_ + nhw], acc[c]);
        }
        float* on = out + (size_t)n * 64 * HW_ + (size_t)g * 8 * HW_ + hw;
#pragma unroll
        for (int c = 0; c < 8; c++) on[(size_t)c * HW_] = acc[c];
    }
}

// -------------------------------------------------------------------------
// Launcher.
// -------------------------------------------------------------------------
extern "C" void kernel_launch(void* const* d_in, const int* in_sizes, int n_in,
                              void* d_out, int out_size) {
    const float* x   = (const float*)d_in[0];
    const float* w1  = (const float*)d_in[1];
    const float* w2  = (const float*)d_in[2];
    const float* w3  = (const float*)d_in[3];
    const float* cp  = (const float*)d_in[4];
    const float* cw1 = (const float*)d_in[5];
    const float* cw2 = (const float*)d_in[6];
    const float* g1  = (const float*)d_in[7];
    const float* b1  = (const float*)d_in[8];
    const float* m1  = (const float*)d_in[9];
    const float* v1  = (const float*)d_in[10];
    const float* g2  = (const float*)d_in[11];
    const float* b2  = (const float*)d_in[12];
    const float* m2  = (const float*)d_in[13];
    const float* v2  = (const float*)d_in[14];
    float* out = (float*)d_out;

    dim3 gg((HW_ + 127) / 128, N_);   // 25 x 16
    sam_gemm96_kernel<<<gg, 256>>>(x, w1, w2, w3);

    dim3 ga(HW_ / 32, N_);            // 98 x 16
    sam_attn_kernel<<<ga, 288>>>(cp, cw1, cw2,
                                 g1, b1, m1, v1,
                                 g2, b2, m2, v2, out);
}

// round 4
// speedup vs baseline: 2.0277x; 1.1486x over previous
#include <cuda_runtime.h>
#include <math.h>

#define H_ 56
#define W_ 56
#define HW_ 3136
#define N_ 16
#define C_ 256
#define EPSBN 1e-3f

// Scratch: stacked GEMM output y[n][o][hw], o in [0,96):
//   rows  0..15  = x1, rows 16..31 = x2, rows 32..95 = x3
__device__ float g_y[N_ * 96 * HW_];

// f32x2 packed FMA: d.lo = a.lo*b.lo + c.lo ; d.hi = a.hi*b.hi + c.hi (RN)
__device__ __forceinline__ void ffma2(unsigned long long& acc,
                                      unsigned long long a,
                                      unsigned long long b) {
    asm("fma.rn.f32x2 %0, %1, %2, %0;" : "+l"(acc) : "l"(a), "l"(b));
}

__device__ __forceinline__ unsigned long long dup2(float w) {
    unsigned long long r;
    asm("mov.b64 %0, {%1, %1};" : "=l"(r) : "r"(__float_as_uint(w)));
    return r;
}

__device__ __forceinline__ void cp_async16(void* smem_dst, const void* gsrc) {
    unsigned s = (unsigned)__cvta_generic_to_shared(smem_dst);
    asm volatile("cp.async.cg.shared.global [%0], [%1], 16;" :: "r"(s), "l"(gsrc));
}

// -------------------------------------------------------------------------
// Kernel 1: fused GEMM for the three 1x1 convs, packed f32x2 FMA +
// cp.async double-buffered pipeline.
// y[n, 0:96, hw] = W[96,256] @ x[n, :, hw]
// Block: 256 threads. Tile: 96 rows x 128 px. BK=16.
// Thread: 6 rows (ty+16r) x 8 px (chunks at 4tx and 64+4tx).
// -------------------------------------------------------------------------
__global__ __launch_bounds__(256) void sam_gemm96_kernel(
    const float* __restrict__ x,
    const float* __restrict__ w1,
    const float* __restrict__ w2,
    const float* __restrict__ w3) {
    __shared__ alignas(16) float Ws[2][96][20];   // plain fp32, pad 20 (80B)
    __shared__ alignas(16) float Xs[2][16][128];

    const int n   = blockIdx.y;
    const int p0  = blockIdx.x * 128;     // 25 tiles, last partial
    const int tid = threadIdx.x;
    const int tx  = tid & 15;
    const int ty  = tid >> 4;             // 0..15

    const float* xn = x + (size_t)n * C_ * HW_;

    // Per-thread prefetch coordinates (constant across tiles)
    // X: 512 chunks of 16B; chunk c: k=c>>5, p4=c&31
    const int xk0 = tid >> 5,        xp0 = (tid & 31) * 4;
    const int xk1 = (tid + 256) >> 5, xp1 = ((tid + 256) & 31) * 4;
    int xg0 = p0 + xp0; if (xg0 > HW_ - 4) xg0 = HW_ - 4;
    int xg1 = p0 + xp1; if (xg1 > HW_ - 4) xg1 = HW_ - 4;
    // W: 384 chunks; chunk c: o=c>>2, q=c&3 (only c<384 active)
    const int wo = tid >> 2, wq = tid & 3;
    const float* wrow = (wo < 16) ? (w1 + wo * C_)
                      : (wo < 32) ? (w2 + (wo - 16) * C_)
                                  : (w3 + (wo - 32) * C_);
    const int wo2 = (tid + 256) >> 2, wq2 = (tid + 256) & 3;  // 64..127 only
    const float* wrow2 = (tid < 128)
        ? ((wo2 < 96) ? (w3 + (wo2 - 32) * C_) : (const float*)0) : (const float*)0;

    unsigned long long acc[6][4];
#pragma unroll
    for (int r = 0; r < 6; r++)
#pragma unroll
        for (int s = 0; s < 4; s++) acc[r][s] = 0ull;

    // ---- prefetch tile 0 ----
    {
        const int k0 = 0;
        cp_async16(&Xs[0][xk0][xp0], xn + (size_t)(k0 + xk0) * HW_ + xg0);
        cp_async16(&Xs[0][xk1][xp1], xn + (size_t)(k0 + xk1) * HW_ + xg1);
        cp_async16(&Ws[0][wo][wq * 4], wrow + k0 + wq * 4);
        if (wrow2) cp_async16(&Ws[0][wo2][wq2 * 4], wrow2 + k0 + wq2 * 4);
        asm volatile("cp.async.commit_group;");
    }

    for (int t = 0; t < 16; t++) {
        const int b = t & 1;
        if (t < 15) {
            const int k0 = (t + 1) * 16;
            const int bn = b ^ 1;
            cp_async16(&Xs[bn][xk0][xp0], xn + (size_t)(k0 + xk0) * HW_ + xg0);
            cp_async16(&Xs[bn][xk1][xp1], xn + (size_t)(k0 + xk1) * HW_ + xg1);
            cp_async16(&Ws[bn][wo][wq * 4], wrow + k0 + wq * 4);
            if (wrow2) cp_async16(&Ws[bn][wo2][wq2 * 4], wrow2 + k0 + wq2 * 4);
            asm volatile("cp.async.commit_group;");
            asm volatile("cp.async.wait_group 1;");
        } else {
            asm volatile("cp.async.wait_group 0;");
        }
        __syncthreads();

#pragma unroll
        for (int k = 0; k < 16; k++) {
            ulonglong2 xa = *(const ulonglong2*)&Xs[b][k][4 * tx];
            ulonglong2 xb = *(const ulonglong2*)&Xs[b][k][64 + 4 * tx];
#pragma unroll
            for (int r = 0; r < 6; r++) {
                unsigned long long wd = dup2(Ws[b][ty + 16 * r][k]);
                ffma2(acc[r][0], wd, xa.x);
                ffma2(acc[r][1], wd, xa.y);
                ffma2(acc[r][2], wd, xb.x);
                ffma2(acc[r][3], wd, xb.y);
            }
        }
        __syncthreads();
    }

    float* yn = g_y + (size_t)n * 96 * HW_;
    const int pA = p0 + 4 * tx;            // always in-bounds
    const int pB = pA + 64;                // may be OOB on last tile
#pragma unroll
    for (int r = 0; r < 6; r++) {
        int o = ty + 16 * r;
        ulonglong2 va; va.x = acc[r][0]; va.y = acc[r][1];
        *(ulonglong2*)&yn[(size_t)o * HW_ + pA] = va;
        if (pB < HW_) {
            ulonglong2 vb; vb.x = acc[r][2]; vb.y = acc[r][3];
            *(ulonglong2*)&yn[(size_t)o * HW_ + pB] = vb;
        }
    }
}

// -------------------------------------------------------------------------
// Kernel 2: fused attention, 3 phases per 32-pixel block, 288 threads.
// (unchanged — 32us)
// -------------------------------------------------------------------------
__global__ __launch_bounds__(288) void sam_attn_kernel(
    const float* __restrict__ convp,   // [2,2]
    const float* __restrict__ w1c,     // [16,18]
    const float* __restrict__ w2c,     // [8,16]
    const float* __restrict__ g1, const float* __restrict__ b1,
    const float* __restrict__ m1, const float* __restrict__ v1,
    const float* __restrict__ g2, const float* __restrict__ b2,
    const float* __restrict__ m2, const float* __restrict__ v2,
    float* __restrict__ out) {
    __shared__ alignas(16) float sw1[16][20];
    __shared__ alignas(16) float sw2[8][16];
    __shared__ float scp[4];
    __shared__ float sc_s[32 * 73];            // [pix][jj*8+q], stride 73

    const int t = threadIdx.x;
    if (t < 288) sw1[t / 18][t % 18] = w1c[t];
    if (t < 128) sw2[t / 16][t % 16] = w2c[t];
    if (t < 4)   scp[t] = convp[t];
    __syncthreads();

    const int n   = blockIdx.y;
    const int hw0 = blockIdx.x * 32;
    const int pix = t & 31;
    const int jj  = t >> 5;                    // 0..8
    const int hw  = hw0 + pix;
    const int h   = hw / W_;
    const int w   = hw % W_;

    const float* yn = g_y + (size_t)n * 96 * HW_;

    const float s1 = g1[hw] * rsqrtf(v1[hw] + EPSBN);
    const float o1 = b1[hw] - m1[hw] * s1;
    const float s2 = g2[hw] * rsqrtf(v2[hw] + EPSBN);
    const float o2 = b2[hw] - m2[hw] * s2;

    // ---- Phase 1: logits for this (pix, jj) ----
    {
        int di = jj / 3 - 1, dj = jj % 3 - 1;
        int nh = h + di;
        nh = (nh < 0) ? -nh : ((nh >= H_) ? 2 * H_ - 2 - nh : nh);
        int nw = w + dj;
        nw = (nw < 0) ? -nw : ((nw >= W_) ? 2 * W_ - 2 - nw : nw);
        const int nhw = nh * W_ + nw;

        float a[18];
#pragma unroll
        for (int c = 0; c < 16; c++) {
            float r = yn[(size_t)c * HW_ + hw] - yn[(size_t)(16 + c) * HW_ + nhw];
            a[c] = fmaxf(fmaf(r, s1, o1), 0.0f);
        }
        const float lw  = -1.0f + 2.0f * (float)w  / 55.0f;
        const float lh  = -1.0f + 2.0f * (float)h  / 55.0f;
        const float nlw = -1.0f + 2.0f * (float)nw / 55.0f;
        const float nlh = -1.0f + 2.0f * (float)nh / 55.0f;
        const float dp0 = scp[0] * (lw - nlw) + scp[1] * (lh - nlh);
        const float dp1 = scp[2] * (lw - nlw) + scp[3] * (lh - nlh);
        a[16] = fmaxf(fmaf(dp0, s1, o1), 0.0f);
        a[17] = fmaxf(fmaf(dp1, s1, o1), 0.0f);

        float hb[16];
#pragma unroll
        for (int o = 0; o < 16; o++) {
            const float4* wr = (const float4*)&sw1[o][0];
            float4 w0 = wr[0], w1v = wr[1], w2v = wr[2], w3v = wr[3];
            float tacc = 0.0f;
            tacc = fmaf(w0.x,  a[0],  tacc); tacc = fmaf(w0.y,  a[1],  tacc);
            tacc = fmaf(w0.z,  a[2],  tacc); tacc = fmaf(w0.w,  a[3],  tacc);
            tacc = fmaf(w1v.x, a[4],  tacc); tacc = fmaf(w1v.y, a[5],  tacc);
            tacc = fmaf(w1v.z, a[6],  tacc); tacc = fmaf(w1v.w, a[7],  tacc);
            tacc = fmaf(w2v.x, a[8],  tacc); tacc = fmaf(w2v.y, a[9],  tacc);
            tacc = fmaf(w2v.z, a[10], tacc); tacc = fmaf(w2v.w, a[11], tacc);
            tacc = fmaf(w3v.x, a[12], tacc); tacc = fmaf(w3v.y, a[13], tacc);
            tacc = fmaf(w3v.z, a[14], tacc); tacc = fmaf(w3v.w, a[15], tacc);
            tacc = fmaf(sw1[o][16], a[16], tacc);
            tacc = fmaf(sw1[o][17], a[17], tacc);
            hb[o] = fmaxf(fmaf(tacc, s2, o2), 0.0f);
        }
        float* dst = &sc_s[pix * 73 + jj * 8];
#pragma unroll
        for (int q = 0; q < 8; q++) {
            const float4* wr = (const float4*)&sw2[q][0];
            float4 w0 = wr[0], w1v = wr[1], w2v = wr[2], w3v = wr[3];
            float tacc = 0.0f;
            tacc = fmaf(w0.x,  hb[0],  tacc); tacc = fmaf(w0.y,  hb[1],  tacc);
            tacc = fmaf(w0.z,  hb[2],  tacc); tacc = fmaf(w0.w,  hb[3],  tacc);
            tacc = fmaf(w1v.x, hb[4],  tacc); tacc = fmaf(w1v.y, hb[5],  tacc);
            tacc = fmaf(w1v.z, hb[6],  tacc); tacc = fmaf(w1v.w, hb[7],  tacc);
            tacc = fmaf(w2v.x, hb[8],  tacc); tacc = fmaf(w2v.y, hb[9],  tacc);
            tacc = fmaf(w2v.z, hb[10], tacc); tacc = fmaf(w2v.w, hb[11], tacc);
            tacc = fmaf(w3v.x, hb[12], tacc); tacc = fmaf(w3v.y, hb[13], tacc);
            tacc = fmaf(w3v.z, hb[14], tacc); tacc = fmaf(w3v.w, hb[15], tacc);
            dst[q] = tacc;
        }
    }
    __syncthreads();

    // ---- Phase 2: softmax over jj, thread = (q, pix) ----
    if (t < 256) {
        const int q = t >> 5;
        float* base = &sc_s[pix * 73 + q];
        float v[9];
#pragma unroll
        for (int j = 0; j < 9; j++) v[j] = base[j * 8];
        float mx = v[0];
#pragma unroll
        for (int j = 1; j < 9; j++) mx = fmaxf(mx, v[j]);
        float sum = 0.0f;
#pragma unroll
        for (int j = 0; j < 9; j++) { v[j] = __expf(v[j] - mx); sum += v[j]; }
        float inv = 1.0f / sum;
#pragma unroll
        for (int j = 0; j < 9; j++) base[j * 8] = v[j] * inv;
    }
    __syncthreads();

    // ---- Phase 3: aggregation, thread = (g, pix) ----
    if (t < 256) {
        const int g = t >> 5;
        int nhw9[9];
#pragma unroll
        for (int j = 0; j < 9; j++) {
            int nh = h + j / 3 - 1;
            nh = (nh < 0) ? -nh : ((nh >= H_) ? 2 * H_ - 2 - nh : nh);
            int nw = w + j % 3 - 1;
            nw = (nw < 0) ? -nw : ((nw >= W_) ? 2 * W_ - 2 - nw : nw);
            nhw9[j] = nh * W_ + nw;
        }
        const float* ws = &sc_s[pix * 73];
        const float* y3 = yn + (size_t)(32 + g * 8) * HW_;
        float acc[8];
#pragma unroll
        for (int c = 0; c < 8; c++) acc[c] = 0.0f;
#pragma unroll
        for (int j = 0; j < 9; j++) {
            const int nhw = nhw9[j];
#pragma unroll
            for (int c = 0; c < 8; c++)
                acc[c] = fmaf(ws[j * 8 + c], y3[(size_t)c * HW_ + nhw], acc[c]);
        }
        float* on = out + (size_t)n * 64 * HW_ + (size_t)g * 8 * HW_ + hw;
#pragma unroll
        for (int c = 0; c < 8; c++) on[(size_t)c * HW_] = acc[c];
    }
}

// -------------------------------------------------------------------------
// Launcher.
// -------------------------------------------------------------------------
extern "C" void kernel_launch(void* const* d_in, const int* in_sizes, int n_in,
                              void* d_out, int out_size) {
    const float* x   = (const float*)d_in[0];
    const float* w1  = (const float*)d_in[1];
    const float* w2  = (const float*)d_in[2];
    const float* w3  = (const float*)d_in[3];
    const float* cp  = (const float*)d_in[4];
    const float* cw1 = (const float*)d_in[5];
    const float* cw2 = (const float*)d_in[6];
    const float* g1  = (const float*)d_in[7];
    const float* b1  = (const float*)d_in[8];
    const float* m1  = (const float*)d_in[9];
    const float* v1  = (const float*)d_in[10];
    const float* g2  = (const float*)d_in[11];
    const float* b2  = (const float*)d_in[12];
    const float* m2  = (const float*)d_in[13];
    const float* v2  = (const float*)d_in[14];
    float* out = (float*)d_out;

    dim3 gg((HW_ + 127) / 128, N_);   // 25 x 16
    sam_gemm96_kernel<<<gg, 256>>>(x, w1, w2, w3);

    dim3 ga(HW_ / 32, N_);            // 98 x 16
    sam_attn_kernel<<<ga, 288>>>(cp, cw1, cw2,
                                 g1, b1, m1, v1,
                                 g2, b2, m2, v2, out);
}

// round 5
// speedup vs baseline: 2.0702x; 1.0209x over previous
#include <cuda_runtime.h>
#include <math.h>

#define H_ 56
#define W_ 56
#define HW_ 3136
#define N_ 16
#define C_ 256
#define EPSBN 1e-3f

// Scratch: stacked GEMM output y[n][o][hw], o in [0,96):
//   rows  0..15  = x1, rows 16..31 = x2, rows 32..95 = x3
__device__ float g_y[N_ * 96 * HW_];

// f32x2 packed FMA: d.lo = a.lo*b.lo + c.lo ; d.hi = a.hi*b.hi + c.hi (RN)
__device__ __forceinline__ void ffma2(unsigned long long& acc,
                                      unsigned long long a,
                                      unsigned long long b) {
    asm("fma.rn.f32x2 %0, %1, %2, %0;" : "+l"(acc) : "l"(a), "l"(b));
}

__device__ __forceinline__ unsigned long long dup2(float w) {
    unsigned long long r;
    asm("mov.b64 %0, {%1, %1};" : "=l"(r) : "r"(__float_as_uint(w)));
    return r;
}

__device__ __forceinline__ void cp_async16(void* smem_dst, const void* gsrc) {
    unsigned s = (unsigned)__cvta_generic_to_shared(smem_dst);
    asm volatile("cp.async.cg.shared.global [%0], [%1], 16;" :: "r"(s), "l"(gsrc));
}

// -------------------------------------------------------------------------
// Kernel 1: fused GEMM for the three 1x1 convs, packed f32x2 FMA +
// 3-stage cp.async pipeline, ONE barrier per k-tile.
// y[n, 0:96, hw] = W[96,256] @ x[n, :, hw]
// Block: 256 threads. Tile: 96 rows x 128 px. BK=16, 16 k-tiles.
// -------------------------------------------------------------------------
__global__ __launch_bounds__(256) void sam_gemm96_kernel(
    const float* __restrict__ x,
    const float* __restrict__ w1,
    const float* __restrict__ w2,
    const float* __restrict__ w3) {
    __shared__ alignas(16) float Ws[3][96][20];   // pad 20 (80B rows)
    __shared__ alignas(16) float Xs[3][16][128];

    const int n   = blockIdx.y;
    const int p0  = blockIdx.x * 128;     // 25 tiles, last partial
    const int tid = threadIdx.x;
    const int tx  = tid & 15;
    const int ty  = tid >> 4;             // 0..15

    const float* xn = x + (size_t)n * C_ * HW_;

    // Per-thread prefetch coordinates (constant across tiles)
    const int xk0 = tid >> 5,         xp0 = (tid & 31) * 4;
    const int xk1 = (tid + 256) >> 5, xp1 = ((tid + 256) & 31) * 4;
    int xg0 = p0 + xp0; if (xg0 > HW_ - 4) xg0 = HW_ - 4;
    int xg1 = p0 + xp1; if (xg1 > HW_ - 4) xg1 = HW_ - 4;
    const int wo = tid >> 2, wq = tid & 3;
    const float* wrow = (wo < 16) ? (w1 + wo * C_)
                      : (wo < 32) ? (w2 + (wo - 16) * C_)
                                  : (w3 + (wo - 32) * C_);
    const int wo2 = (tid + 256) >> 2, wq2 = (tid + 256) & 3;
    const float* wrow2 = (tid < 128) ? (w3 + (wo2 - 32) * C_) : (const float*)0;

    unsigned long long acc[6][4];
#pragma unroll
    for (int r = 0; r < 6; r++)
#pragma unroll
        for (int s = 0; s < 4; s++) acc[r][s] = 0ull;

#define PREFETCH(slot, k0)                                                     \
    do {                                                                       \
        cp_async16(&Xs[slot][xk0][xp0], xn + (size_t)((k0) + xk0) * HW_ + xg0);\
        cp_async16(&Xs[slot][xk1][xp1], xn + (size_t)((k0) + xk1) * HW_ + xg1);\
        cp_async16(&Ws[slot][wo][wq * 4], wrow + (k0) + wq * 4);               \
        if (wrow2) cp_async16(&Ws[slot][wo2][wq2 * 4], wrow2 + (k0) + wq2 * 4);\
        asm volatile("cp.async.commit_group;");                                \
    } while (0)

    // Prologue: fill stages 0, 1
    PREFETCH(0, 0);
    PREFETCH(1, 16);

    int slot = 0;
    for (int t = 0; t < 16; t++) {
        asm volatile("cp.async.wait_group 1;");   // tile t landed
        __syncthreads();                          // all warps done with t-1's slot

        if (t + 2 < 16) {
            int ns = slot + 2; if (ns >= 3) ns -= 3;
            PREFETCH(ns, (t + 2) * 16);
        } else {
            asm volatile("cp.async.commit_group;");  // keep group count aligned
        }

        const float (*Wb)[20]  = Ws[slot];
        const float (*Xb)[128] = Xs[slot];
#pragma unroll
        for (int k = 0; k < 16; k++) {
            ulonglong2 xa = *(const ulonglong2*)&Xb[k][4 * tx];
            ulonglong2 xb = *(const ulonglong2*)&Xb[k][64 + 4 * tx];
#pragma unroll
            for (int r = 0; r < 6; r++) {
                unsigned long long wd = dup2(Wb[ty + 16 * r][k]);
                ffma2(acc[r][0], wd, xa.x);
                ffma2(acc[r][1], wd, xa.y);
                ffma2(acc[r][2], wd, xb.x);
                ffma2(acc[r][3], wd, xb.y);
            }
        }
        if (++slot == 3) slot = 0;
    }
#undef PREFETCH

    float* yn = g_y + (size_t)n * 96 * HW_;
    const int pA = p0 + 4 * tx;            // always in-bounds
    const int pB = pA + 64;                // may be OOB on last tile
#pragma unroll
    for (int r = 0; r < 6; r++) {
        int o = ty + 16 * r;
        ulonglong2 va; va.x = acc[r][0]; va.y = acc[r][1];
        *(ulonglong2*)&yn[(size_t)o * HW_ + pA] = va;
        if (pB < HW_) {
            ulonglong2 vb; vb.x = acc[r][2]; vb.y = acc[r][3];
            *(ulonglong2*)&yn[(size_t)o * HW_ + pB] = vb;
        }
    }
}

// -------------------------------------------------------------------------
// Kernel 2: fused attention, 3 phases per 32-pixel block, 288 threads.
// __launch_bounds__(288,4): cap regs ~56 -> 4 blocks/SM (occ 37% -> ~56%).
// -------------------------------------------------------------------------
__global__ __launch_bounds__(288, 4) void sam_attn_kernel(
    const float* __restrict__ convp,   // [2,2]
    const float* __restrict__ w1c,     // [16,18]
    const float* __restrict__ w2c,     // [8,16]
    const float* __restrict__ g1, const float* __restrict__ b1,
    const float* __restrict__ m1, const float* __restrict__ v1,
    const float* __restrict__ g2, const float* __restrict__ b2,
    const float* __restrict__ m2, const float* __restrict__ v2,
    float* __restrict__ out) {
    __shared__ alignas(16) float sw1[16][20];
    __shared__ alignas(16) float sw2[8][16];
    __shared__ float scp[4];
    __shared__ float sc_s[32 * 73];            // [pix][jj*8+q], stride 73

    const int t = threadIdx.x;
    if (t < 288) sw1[t / 18][t % 18] = w1c[t];
    if (t < 128) sw2[t / 16][t % 16] = w2c[t];
    if (t < 4)   scp[t] = convp[t];
    __syncthreads();

    const int n   = blockIdx.y;
    const int hw0 = blockIdx.x * 32;
    const int pix = t & 31;
    const int jj  = t >> 5;                    // 0..8
    const int hw  = hw0 + pix;
    const int h   = hw / W_;
    const int w   = hw % W_;

    const float* yn = g_y + (size_t)n * 96 * HW_;

    const float s1 = g1[hw] * rsqrtf(v1[hw] + EPSBN);
    const float o1 = b1[hw] - m1[hw] * s1;
    const float s2 = g2[hw] * rsqrtf(v2[hw] + EPSBN);
    const float o2 = b2[hw] - m2[hw] * s2;

    // ---- Phase 1: logits for this (pix, jj) ----
    {
        int di = jj / 3 - 1, dj = jj % 3 - 1;
        int nh = h + di;
        nh = (nh < 0) ? -nh : ((nh >= H_) ? 2 * H_ - 2 - nh : nh);
        int nw = w + dj;
        nw = (nw < 0) ? -nw : ((nw >= W_) ? 2 * W_ - 2 - nw : nw);
        const int nhw = nh * W_ + nw;

        float a[18];
#pragma unroll
        for (int c = 0; c < 16; c++) {
            float r = yn[(size_t)c * HW_ + hw] - yn[(size_t)(16 + c) * HW_ + nhw];
            a[c] = fmaxf(fmaf(r, s1, o1), 0.0f);
        }
        const float lw  = -1.0f + 2.0f * (float)w  / 55.0f;
        const float lh  = -1.0f + 2.0f * (float)h  / 55.0f;
        const float nlw = -1.0f + 2.0f * (float)nw / 55.0f;
        const float nlh = -1.0f + 2.0f * (float)nh / 55.0f;
        const float dp0 = scp[0] * (lw - nlw) + scp[1] * (lh - nlh);
        const float dp1 = scp[2] * (lw - nlw) + scp[3] * (lh - nlh);
        a[16] = fmaxf(fmaf(dp0, s1, o1), 0.0f);
        a[17] = fmaxf(fmaf(dp1, s1, o1), 0.0f);

        float hb[16];
#pragma unroll
        for (int o = 0; o < 16; o++) {
            const float4* wr = (const float4*)&sw1[o][0];
            float4 w0 = wr[0], w1v = wr[1], w2v = wr[2], w3v = wr[3];
            float tacc = 0.0f;
            tacc = fmaf(w0.x,  a[0],  tacc); tacc = fmaf(w0.y,  a[1],  tacc);
            tacc = fmaf(w0.z,  a[2],  tacc); tacc = fmaf(w0.w,  a[3],  tacc);
            tacc = fmaf(w1v.x, a[4],  tacc); tacc = fmaf(w1v.y, a[5],  tacc);
            tacc = fmaf(w1v.z, a[6],  tacc); tacc = fmaf(w1v.w, a[7],  tacc);
            tacc = fmaf(w2v.x, a[8],  tacc); tacc = fmaf(w2v.y, a[9],  tacc);
            tacc = fmaf(w2v.z, a[10], tacc); tacc = fmaf(w2v.w, a[11], tacc);
            tacc = fmaf(w3v.x, a[12], tacc); tacc = fmaf(w3v.y, a[13], tacc);
            tacc = fmaf(w3v.z, a[14], tacc); tacc = fmaf(w3v.w, a[15], tacc);
            tacc = fmaf(sw1[o][16], a[16], tacc);
            tacc = fmaf(sw1[o][17], a[17], tacc);
            hb[o] = fmaxf(fmaf(tacc, s2, o2), 0.0f);
        }
        float* dst = &sc_s[pix * 73 + jj * 8];
#pragma unroll
        for (int q = 0; q < 8; q++) {
            const float4* wr = (const float4*)&sw2[q][0];
            float4 w0 = wr[0], w1v = wr[1], w2v = wr[2], w3v = wr[3];
            float tacc = 0.0f;
            tacc = fmaf(w0.x,  hb[0],  tacc); tacc = fmaf(w0.y,  hb[1],  tacc);
            tacc = fmaf(w0.z,  hb[2],  tacc); tacc = fmaf(w0.w,  hb[3],  tacc);
            tacc = fmaf(w1v.x, hb[4],  tacc); tacc = fmaf(w1v.y, hb[5],  tacc);
            tacc = fmaf(w1v.z, hb[6],  tacc); tacc = fmaf(w1v.w, hb[7],  tacc);
            tacc = fmaf(w2v.x, hb[8],  tacc); tacc = fmaf(w2v.y, hb[9],  tacc);
            tacc = fmaf(w2v.z, hb[10], tacc); tacc = fmaf(w2v.w, hb[11], tacc);
            tacc = fmaf(w3v.x, hb[12], tacc); tacc = fmaf(w3v.y, hb[13], tacc);
            tacc = fmaf(w3v.z, hb[14], tacc); tacc = fmaf(w3v.w, hb[15], tacc);
            dst[q] = tacc;
        }
    }
    __syncthreads();

    // ---- Phase 2: softmax over jj, thread = (q, pix) ----
    if (t < 256) {
        const int q = t >> 5;
        float* base = &sc_s[pix * 73 + q];
        float v[9];
#pragma unroll
        for (int j = 0; j < 9; j++) v[j] = base[j * 8];
        float mx = v[0];
#pragma unroll
        for (int j = 1; j < 9; j++) mx = fmaxf(mx, v[j]);
        float sum = 0.0f;
#pragma unroll
        for (int j = 0; j < 9; j++) { v[j] = __expf(v[j] - mx); sum += v[j]; }
        float inv = 1.0f / sum;
#pragma unroll
        for (int j = 0; j < 9; j++) base[j * 8] = v[j] * inv;
    }
    __syncthreads();

    // ---- Phase 3: aggregation, thread = (g, pix) ----
    if (t < 256) {
        const int g = t >> 5;
        int nhw9[9];
#pragma unroll
        for (int j = 0; j < 9; j++) {
            int nh = h + j / 3 - 1;
            nh = (nh < 0) ? -nh : ((nh >= H_) ? 2 * H_ - 2 - nh : nh);
            int nw = w + j % 3 - 1;
            nw = (nw < 0) ? -nw : ((nw >= W_) ? 2 * W_ - 2 - nw : nw);
            nhw9[j] = nh * W_ + nw;
        }
        const float* ws = &sc_s[pix * 73];
        const float* y3 = yn + (size_t)(32 + g * 8) * HW_;
        float acc[8];
#pragma unroll
        for (int c = 0; c < 8; c++) acc[c] = 0.0f;
#pragma unroll
        for (int j = 0; j < 9; j++) {
            const int nhw = nhw9[j];
#pragma unroll
            for (int c = 0; c < 8; c++)
                acc[c] = fmaf(ws[j * 8 + c], y3[(size_t)c * HW_ + nhw], acc[c]);
        }
        float* on = out + (size_t)n * 64 * HW_ + (size_t)g * 8 * HW_ + hw;
#pragma unroll
        for (int c = 0; c < 8; c++) on[(size_t)c * HW_] = acc[c];
    }
}

// -------------------------------------------------------------------------
// Launcher.
// -------------------------------------------------------------------------
extern "C" void kernel_launch(void* const* d_in, const int* in_sizes, int n_in,
                              void* d_out, int out_size) {
    const float* x   = (const float*)d_in[0];
    const float* w1  = (const float*)d_in[1];
    const float* w2  = (const float*)d_in[2];
    const float* w3  = (const float*)d_in[3];
    const float* cp  = (const float*)d_in[4];
    const float* cw1 = (const float*)d_in[5];
    const float* cw2 = (const float*)d_in[6];
    const float* g1  = (const float*)d_in[7];
    const float* b1  = (const float*)d_in[8];
    const float* m1  = (const float*)d_in[9];
    const float* v1  = (const float*)d_in[10];
    const float* g2  = (const float*)d_in[11];
    const float* b2  = (const float*)d_in[12];
    const float* m2  = (const float*)d_in[13];
    const float* v2  = (const float*)d_in[14];
    float* out = (float*)d_out;

    dim3 gg((HW_ + 127) / 128, N_);   // 25 x 16
    sam_gemm96_kernel<<<gg, 256>>>(x, w1, w2, w3);

    dim3 ga(HW_ / 32, N_);            // 98 x 16
    sam_attn_kernel<<<ga, 288>>>(cp, cw1, cw2,
                                 g1, b1, m1, v1,
                                 g2, b2, m2, v2, out);
}

// round 7
// speedup vs baseline: 2.5778x; 1.2452x over previous
#include <cuda_runtime.h>
#include <cuda_bf16.h>
#include <math.h>
#include <stdint.h>

#define H_ 56
#define W_ 56
#define HW_ 3136
#define N_ 16
#define C_ 256
#define CH_ 96
#define EPSBN 1e-3f

// Scratch: stacked GEMM output y[n][o][hw], o in [0,96):
//   rows 0..15 = x1, 16..31 = x2, 32..95 = x3
__device__ float g_y[N_ * CH_ * HW_];
// Split-bf16 weights [96][256]
__device__ __nv_bfloat16 g_wh[CH_ * C_];
__device__ __nv_bfloat16 g_wl[CH_ * C_];

// ---------------- helpers ----------------
__device__ __forceinline__ uint32_t smem_addr_u32(const void* p) {
    uint32_t a;
    asm("{ .reg .u64 t; cvta.to.shared.u64 t, %1; cvt.u32.u64 %0, t; }"
        : "=r"(a) : "l"(p));
    return a;
}

__device__ __forceinline__ void cp_async16(void* smem_dst, const void* gsrc) {
    unsigned s = (unsigned)__cvta_generic_to_shared(smem_dst);
    asm volatile("cp.async.cg.shared.global [%0], [%1], 16;" :: "r"(s), "l"(gsrc));
}

__device__ __forceinline__ void ldsm_x4(uint32_t* r, uint32_t addr) {
    asm volatile("ldmatrix.sync.aligned.m8n8.x4.shared.b16 {%0,%1,%2,%3}, [%4];"
                 : "=r"(r[0]), "=r"(r[1]), "=r"(r[2]), "=r"(r[3]) : "r"(addr));
}

__device__ __forceinline__ void ldsm_x2t(uint32_t* r, uint32_t addr) {
    asm volatile("ldmatrix.sync.aligned.m8n8.x2.trans.shared.b16 {%0,%1}, [%2];"
                 : "=r"(r[0]), "=r"(r[1]) : "r"(addr));
}

__device__ __forceinline__ void mma_bf16(float* d, const uint32_t* a,
                                         const uint32_t* b) {
    asm volatile(
        "mma.sync.aligned.m16n8k16.row.col.f32.bf16.bf16.f32 "
        "{%0,%1,%2,%3}, {%4,%5,%6,%7}, {%8,%9}, {%0,%1,%2,%3};"
        : "+f"(d[0]), "+f"(d[1]), "+f"(d[2]), "+f"(d[3])
        : "r"(a[0]), "r"(a[1]), "r"(a[2]), "r"(a[3]), "r"(b[0]), "r"(b[1]));
}

// SW128 swizzle for 128B rows (16B granular)
#define SWZ(o) ((o) ^ (((o) >> 3) & 0x70))
// X-tile swizzle: rows of 256B (128 px bf16); XOR 16B-chunk index by k&7
#define XSWZ(k, pxb) ((k) * 256 + ((pxb) ^ (((k) & 7) << 4)))

// smem layout (bytes), dynamic
#define BH_OFF 0        // X hi  [64 k][128 px] bf16, 256B rows  = 16384
#define BL_OFF 16384    // X lo
#define WH_OFF 32768    // W hi  [96 ch][64 k]  bf16, SW128      = 12288
#define WL_OFF 45056    // W lo
#define SMEM_MMA 57344

// -------------------------------------------------------------------------
// Kernel 0: split stacked W (96x256) into bf16 hi/lo.
// -------------------------------------------------------------------------
__global__ __launch_bounds__(256) void sam_wsplit_kernel(
    const float* __restrict__ w1, const float* __restrict__ w2,
    const float* __restrict__ w3) {
    int i = blockIdx.x * 256 + threadIdx.x;
    if (i >= CH_ * C_) return;
    int o = i >> 8, k = i & 255;
    float v = (o < 16) ? w1[o * C_ + k]
            : (o < 32) ? w2[(o - 16) * C_ + k]
                       : w3[(o - 32) * C_ + k];
    __nv_bfloat16 h = __float2bfloat16(v);
    g_wh[i] = h;
    g_wl[i] = __float2bfloat16(v - __bfloat162float(h));
}

// -------------------------------------------------------------------------
// Kernel 1: split-bf16 GEMM via mma.sync (HMMA, base ISA -- no 'a' features).
// D[ch=96, px=128] = W[96,256] @ X[256, px]
//   = Wh@Xh + Wh@Xl + Wl@Xh       (Wl@Xl dropped, ~2^-16)
// M=ch (6 m-tiles x16), N=px (warp owns 16 px = 2 n-tiles x8), K=4 chunks x64.
// X loaded fp32 (coalesced LDG.128), converted to bf16 hi/lo in-regs, STS
// into k-swizzled [k][px] tile; B-frags via ldmatrix.x2.trans (no transpose
// pass needed). W pre-split, cp.async into SW128 [ch][k] tiles.
// -------------------------------------------------------------------------
__global__ __launch_bounds__(256) void sam_gemm_mma(const float* __restrict__ x) {
    extern __shared__ __align__(1024) char smem[];
    const int tid  = threadIdx.x;
    const int wid  = tid >> 5;
    const int lane = tid & 31;
    const int n    = blockIdx.y;
    int p0 = blockIdx.x * 128;
    if (p0 > HW_ - 128) p0 = HW_ - 128;   // overlap tile: identical dup writes

    const uint32_t sb = smem_addr_u32(smem);
    const float* xn = x + (size_t)n * C_ * HW_ + p0;

    float d[6][2][4];
#pragma unroll
    for (int m = 0; m < 6; m++)
#pragma unroll
        for (int nt = 0; nt < 2; nt++)
#pragma unroll
            for (int r = 0; r < 4; r++) d[m][nt][r] = 0.0f;

    // W cp.async coordinates (constant across chunks)
    const int wo = tid >> 3, wq = tid & 7;          // jj = tid: o 0..31
    const int xk = tid >> 5, xp4 = (tid & 31) * 4;  // X load coords

    for (int c = 0; c < 4; c++) {
        const int kb = c * 64;
        // ---- stage W hi/lo via swizzle-aware cp.async: 1536 16B chunks ----
#pragma unroll
        for (int i = 0; i < 6; i++) {
            int j = tid + i * 256;
            int tgt = (j >= 768);
            int jj = j - (tgt ? 768 : 0);
            int o = jj >> 3, q = jj & 7;
            const __nv_bfloat16* src = (tgt ? g_wl : g_wh) + o * C_ + kb + q * 8;
            cp_async16(smem + (tgt ? WL_OFF : WH_OFF) + SWZ(o * 128 + q * 16), src);
        }
        asm volatile("cp.async.commit_group;");

        // ---- load X fp32, convert, STS bf16 hi/lo (overlaps cp.async) ----
#pragma unroll
        for (int i = 0; i < 8; i++) {
            int k = xk + i * 8;                    // 0..63
            float4 v = *(const float4*)(xn + (size_t)(kb + k) * HW_ + xp4);
            __nv_bfloat162 h0 = __floats2bfloat162_rn(v.x, v.y);
            __nv_bfloat162 h1 = __floats2bfloat162_rn(v.z, v.w);
            float2 f0 = __bfloat1622float2(h0);
            float2 f1 = __bfloat1622float2(h1);
            __nv_bfloat162 l0 = __floats2bfloat162_rn(v.x - f0.x, v.y - f0.y);
            __nv_bfloat162 l1 = __floats2bfloat162_rn(v.z - f1.x, v.w - f1.y);
            int off = XSWZ(k, xp4 * 2);
            uint2 hw_; hw_.x = *(uint32_t*)&h0; hw_.y = *(uint32_t*)&h1;
            uint2 lw_; lw_.x = *(uint32_t*)&l0; lw_.y = *(uint32_t*)&l1;
            *(uint2*)(smem + BH_OFF + off) = hw_;
            *(uint2*)(smem + BL_OFF + off) = lw_;
        }
        asm volatile("cp.async.wait_group 0;");
        __syncthreads();

        // ---- compute: 4 k16 steps ----
#pragma unroll
        for (int ks = 0; ks < 4; ks++) {
            // B fragments (X): 2 n-tiles, hi/lo
            uint32_t bh[2][2], bl[2][2];
            const int bk = ks * 16 + (lane & 15);  // k row for this lane
#pragma unroll
            for (int nt = 0; nt < 2; nt++) {
                int pxb = wid * 32 + nt * 16;
                uint32_t ba = sb + XSWZ(bk, pxb);
                ldsm_x2t(bh[nt], ba + BH_OFF);
                ldsm_x2t(bl[nt], ba + BL_OFF);
            }
            // A fragments (W) per m-tile
            const int ach  = (lane & 15);
            const int acol = ks * 32 + ((lane >> 4) << 4);
#pragma unroll
            for (int m = 0; m < 6; m++) {
                uint32_t ah[4], al[4];
                uint32_t aoff = SWZ((m * 16 + ach) * 128 + acol);
                ldsm_x4(ah, sb + WH_OFF + aoff);
                ldsm_x4(al, sb + WL_OFF + aoff);
#pragma unroll
                for (int nt = 0; nt < 2; nt++) {
                    mma_bf16(d[m][nt], ah, bh[nt]);
                    mma_bf16(d[m][nt], al, bh[nt]);
                    mma_bf16(d[m][nt], ah, bl[nt]);
                }
            }
        }
        __syncthreads();
    }

    // ---- epilogue: fragment -> g_y[ch][px], float2 stores ----
    const int gid = lane >> 2, tig = lane & 3;
    float* yn = g_y + (size_t)n * CH_ * HW_;
    const int pxb = p0 + wid * 16 + 2 * tig;
#pragma unroll
    for (int m = 0; m < 6; m++) {
#pragma unroll
        for (int nt = 0; nt < 2; nt++) {
            int px = pxb + nt * 8;
            int ch = m * 16 + gid;
            float2 v0; v0.x = d[m][nt][0]; v0.y = d[m][nt][1];
            float2 v1; v1.x = d[m][nt][2]; v1.y = d[m][nt][3];
            *(float2*)&yn[(size_t)ch * HW_ + px] = v0;
            *(float2*)&yn[(size_t)(ch + 8) * HW_ + px] = v1;
        }
    }
}

// -------------------------------------------------------------------------
// Kernel 2: fused attention (unchanged, 32.7us).
// -------------------------------------------------------------------------
__global__ __launch_bounds__(288, 4) void sam_attn_kernel(
    const float* __restrict__ convp,
    const float* __restrict__ w1c,
    const float* __restrict__ w2c,
    const float* __restrict__ g1, const float* __restrict__ b1,
    const float* __restrict__ m1, const float* __restrict__ v1,
    const float* __restrict__ g2, const float* __restrict__ b2,
    const float* __restrict__ m2, const float* __restrict__ v2,
    float* __restrict__ out) {
    __shared__ alignas(16) float sw1[16][20];
    __shared__ alignas(16) float sw2[8][16];
    __shared__ float scp[4];
    __shared__ float sc_s[32 * 73];

    const int t = threadIdx.x;
    if (t < 288) sw1[t / 18][t % 18] = w1c[t];
    if (t < 128) sw2[t / 16][t % 16] = w2c[t];
    if (t < 4)   scp[t] = convp[t];
    __syncthreads();

    const int n   = blockIdx.y;
    const int hw0 = blockIdx.x * 32;
    const int pix = t & 31;
    const int jj  = t >> 5;
    const int hw  = hw0 + pix;
    const int h   = hw / W_;
    const int w   = hw % W_;

    const float* yn = g_y + (size_t)n * CH_ * HW_;

    const float s1 = g1[hw] * rsqrtf(v1[hw] + EPSBN);
    const float o1 = b1[hw] - m1[hw] * s1;
    const float s2 = g2[hw] * rsqrtf(v2[hw] + EPSBN);
    const float o2 = b2[hw] - m2[hw] * s2;

    {
        int di = jj / 3 - 1, dj = jj % 3 - 1;
        int nh = h + di;
        nh = (nh < 0) ? -nh : ((nh >= H_) ? 2 * H_ - 2 - nh : nh);
        int nw = w + dj;
        nw = (nw < 0) ? -nw : ((nw >= W_) ? 2 * W_ - 2 - nw : nw);
        const int nhw = nh * W_ + nw;

        float a[18];
#pragma unroll
        for (int c = 0; c < 16; c++) {
            float r = yn[(size_t)c * HW_ + hw] - yn[(size_t)(16 + c) * HW_ + nhw];
            a[c] = fmaxf(fmaf(r, s1, o1), 0.0f);
        }
        const float lw  = -1.0f + 2.0f * (float)w  / 55.0f;
        const float lh  = -1.0f + 2.0f * (float)h  / 55.0f;
        const float nlw = -1.0f + 2.0f * (float)nw / 55.0f;
        const float nlh = -1.0f + 2.0f * (float)nh / 55.0f;
        const float dp0 = scp[0] * (lw - nlw) + scp[1] * (lh - nlh);
        const float dp1 = scp[2] * (lw - nlw) + scp[3] * (lh - nlh);
        a[16] = fmaxf(fmaf(dp0, s1, o1), 0.0f);
        a[17] = fmaxf(fmaf(dp1, s1, o1), 0.0f);

        float hb[16];
#pragma unroll
        for (int o = 0; o < 16; o++) {
            const float4* wr = (const float4*)&sw1[o][0];
            float4 w0 = wr[0], w1v = wr[1], w2v = wr[2], w3v = wr[3];
            float tacc = 0.0f;
            tacc = fmaf(w0.x,  a[0],  tacc); tacc = fmaf(w0.y,  a[1],  tacc);
            tacc = fmaf(w0.z,  a[2],  tacc); tacc = fmaf(w0.w,  a[3],  tacc);
            tacc = fmaf(w1v.x, a[4],  tacc); tacc = fmaf(w1v.y, a[5],  tacc);
            tacc = fmaf(w1v.z, a[6],  tacc); tacc = fmaf(w1v.w, a[7],  tacc);
            tacc = fmaf(w2v.x, a[8],  tacc); tacc = fmaf(w2v.y, a[9],  tacc);
            tacc = fmaf(w2v.z, a[10], tacc); tacc = fmaf(w2v.w, a[11], tacc);
            tacc = fmaf(w3v.x, a[12], tacc); tacc = fmaf(w3v.y, a[13], tacc);
            tacc = fmaf(w3v.z, a[14], tacc); tacc = fmaf(w3v.w, a[15], tacc);
            tacc = fmaf(sw1[o][16], a[16], tacc);
            tacc = fmaf(sw1[o][17], a[17], tacc);
            hb[o] = fmaxf(fmaf(tacc, s2, o2), 0.0f);
        }
        float* dst = &sc_s[pix * 73 + jj * 8];
#pragma unroll
        for (int q = 0; q < 8; q++) {
            const float4* wr = (const float4*)&sw2[q][0];
            float4 w0 = wr[0], w1v = wr[1], w2v = wr[2], w3v = wr[3];
            float tacc = 0.0f;
            tacc = fmaf(w0.x,  hb[0],  tacc); tacc = fmaf(w0.y,  hb[1],  tacc);
            tacc = fmaf(w0.z,  hb[2],  tacc); tacc = fmaf(w0.w,  hb[3],  tacc);
            tacc = fmaf(w1v.x, hb[4],  tacc); tacc = fmaf(w1v.y, hb[5],  tacc);
            tacc = fmaf(w1v.z, hb[6],  tacc); tacc = fmaf(w1v.w, hb[7],  tacc);
            tacc = fmaf(w2v.x, hb[8],  tacc); tacc = fmaf(w2v.y, hb[9],  tacc);
            tacc = fmaf(w2v.z, hb[10], tacc); tacc = fmaf(w2v.w, hb[11], tacc);
            tacc = fmaf(w3v.x, hb[12], tacc); tacc = fmaf(w3v.y, hb[13], tacc);
            tacc = fmaf(w3v.z, hb[14], tacc); tacc = fmaf(w3v.w, hb[15], tacc);
            dst[q] = tacc;
        }
    }
    __syncthreads();

    if (t < 256) {
        const int q = t >> 5;
        float* base = &sc_s[pix * 73 + q];
        float v[9];
#pragma unroll
        for (int j = 0; j < 9; j++) v[j] = base[j * 8];
        float mx = v[0];
#pragma unroll
        for (int j = 1; j < 9; j++) mx = fmaxf(mx, v[j]);
        float sum = 0.0f;
#pragma unroll
        for (int j = 0; j < 9; j++) { v[j] = __expf(v[j] - mx); sum += v[j]; }
        float inv = 1.0f / sum;
#pragma unroll
        for (int j = 0; j < 9; j++) base[j * 8] = v[j] * inv;
    }
    __syncthreads();

    if (t < 256) {
        const int g = t >> 5;
        int nhw9[9];
#pragma unroll
        for (int j = 0; j < 9; j++) {
            int nh = h + j / 3 - 1;
            nh = (nh < 0) ? -nh : ((nh >= H_) ? 2 * H_ - 2 - nh : nh);
            int nw = w + j % 3 - 1;
            nw = (nw < 0) ? -nw : ((nw >= W_) ? 2 * W_ - 2 - nw : nw);
            nhw9[j] = nh * W_ + nw;
        }
        const float* ws = &sc_s[pix * 73];
        const float* y3 = yn + (size_t)(32 + g * 8) * HW_;
        float acc[8];
#pragma unroll
        for (int c = 0; c < 8; c++) acc[c] = 0.0f;
#pragma unroll
        for (int j = 0; j < 9; j++) {
            const int nhw = nhw9[j];
#pragma unroll
            for (int c = 0; c < 8; c++)
                acc[c] = fmaf(ws[j * 8 + c], y3[(size_t)c * HW_ + nhw], acc[c]);
        }
        float* on = out + (size_t)n * 64 * HW_ + (size_t)g * 8 * HW_ + hw;
#pragma unroll
        for (int c = 0; c < 8; c++) on[(size_t)c * HW_] = acc[c];
    }
}

// -------------------------------------------------------------------------
// Launcher.
// -------------------------------------------------------------------------
extern "C" void kernel_launch(void* const* d_in, const int* in_sizes, int n_in,
                              void* d_out, int out_size) {
    const float* x   = (const float*)d_in[0];
    const float* w1  = (const float*)d_in[1];
    const float* w2  = (const float*)d_in[2];
    const float* w3  = (const float*)d_in[3];
    const float* cp  = (const float*)d_in[4];
    const float* cw1 = (const float*)d_in[5];
    const float* cw2 = (const float*)d_in[6];
    const float* g1  = (const float*)d_in[7];
    const float* b1  = (const float*)d_in[8];
    const float* m1  = (const float*)d_in[9];
    const float* v1  = (const float*)d_in[10];
    const float* g2  = (const float*)d_in[11];
    const float* b2  = (const float*)d_in[12];
    const float* m2  = (const float*)d_in[13];
    const float* v2  = (const float*)d_in[14];
    float* out = (float*)d_out;

    cudaFuncSetAttribute(sam_gemm_mma,
                         cudaFuncAttributeMaxDynamicSharedMemorySize, SMEM_MMA);

    sam_wsplit_kernel<<<(CH_ * C_ + 255) / 256, 256>>>(w1, w2, w3);

    dim3 gg(25, N_);                  // 25 px tiles (last clamped) x 16 n
    sam_gemm_mma<<<gg, 256, SMEM_MMA>>>(x);

    dim3 ga(HW_ / 32, N_);            // 98 x 16
    sam_attn_kernel<<<ga, 288>>>(cp, cw1, cw2,
                                 g1, b1, m1, v1,
                                 g2, b2, m2, v2, out);
}

// round 8
// speedup vs baseline: 2.5884x; 1.0041x over previous
#include <cuda_runtime.h>
#include <cuda_bf16.h>
#include <math.h>
#include <stdint.h>

#define H_ 56
#define W_ 56
#define HW_ 3136
#define N_ 16
#define C_ 256
#define CH_ 96
#define EPSBN 1e-3f

// Scratch: stacked GEMM output y[n][o][hw], o in [0,96):
//   rows 0..15 = x1, 16..31 = x2, 32..95 = x3
__device__ float g_y[N_ * CH_ * HW_];

// ---------------- helpers ----------------
__device__ __forceinline__ uint32_t smem_addr_u32(const void* p) {
    uint32_t a;
    asm("{ .reg .u64 t; cvta.to.shared.u64 t, %1; cvt.u32.u64 %0, t; }"
        : "=r"(a) : "l"(p));
    return a;
}

__device__ __forceinline__ void ldsm_x4(uint32_t* r, uint32_t addr) {
    asm volatile("ldmatrix.sync.aligned.m8n8.x4.shared.b16 {%0,%1,%2,%3}, [%4];"
                 : "=r"(r[0]), "=r"(r[1]), "=r"(r[2]), "=r"(r[3]) : "r"(addr));
}

__device__ __forceinline__ void ldsm_x2t(uint32_t* r, uint32_t addr) {
    asm volatile("ldmatrix.sync.aligned.m8n8.x2.trans.shared.b16 {%0,%1}, [%2];"
                 : "=r"(r[0]), "=r"(r[1]) : "r"(addr));
}

__device__ __forceinline__ void mma_bf16(float* d, const uint32_t* a,
                                         const uint32_t* b) {
    asm volatile(
        "mma.sync.aligned.m16n8k16.row.col.f32.bf16.bf16.f32 "
        "{%0,%1,%2,%3}, {%4,%5,%6,%7}, {%8,%9}, {%0,%1,%2,%3};"
        : "+f"(d[0]), "+f"(d[1]), "+f"(d[2]), "+f"(d[3])
        : "r"(a[0]), "r"(a[1]), "r"(a[2]), "r"(a[3]), "r"(b[0]), "r"(b[1]));
}

// SW128 swizzle for 128B rows (16B granular)
#define SWZ(o) ((o) ^ (((o) >> 3) & 0x70))
// X-tile swizzle: rows of 256B (128 px bf16); XOR 16B-chunk index by k&7
#define XSWZ(k, pxb) ((k) * 256 + ((pxb) ^ (((k) & 7) << 4)))

// smem layout (bytes), dynamic
#define BH_OFF 0        // X hi  [64 k][128 px] bf16, 256B rows  = 16384
#define BL_OFF 16384    // X lo
#define WH_OFF 32768    // W hi  [96 ch][64 k]  bf16, SW128      = 12288
#define WL_OFF 45056    // W lo
#define SMEM_MMA 57344

// -------------------------------------------------------------------------
// Kernel 1: split-bf16 GEMM via mma.sync.
// D[ch=96, px=128] = W[96,256] @ X[256, px]
//   = Wh@Xh + Wh@Xl + Wl@Xh       (Wl@Xl dropped, ~2^-16)
// W converted fp32->bf16 hi/lo IN-KERNEL (98KB, L2-resident; no wsplit pass).
// -------------------------------------------------------------------------
__global__ __launch_bounds__(256) void sam_gemm_mma(
    const float* __restrict__ x,
    const float* __restrict__ w1,
    const float* __restrict__ w2,
    const float* __restrict__ w3) {
    extern __shared__ __align__(1024) char smem[];
    const int tid  = threadIdx.x;
    const int wid  = tid >> 5;
    const int lane = tid & 31;
    const int n    = blockIdx.y;
    int p0 = blockIdx.x * 128;
    if (p0 > HW_ - 128) p0 = HW_ - 128;   // overlap tile: identical dup writes

    const uint32_t sb = smem_addr_u32(smem);
    const float* xn = x + (size_t)n * C_ * HW_ + p0;

    float d[6][2][4];
#pragma unroll
    for (int m = 0; m < 6; m++)
#pragma unroll
        for (int nt = 0; nt < 2; nt++)
#pragma unroll
            for (int r = 0; r < 4; r++) d[m][nt][r] = 0.0f;

    const int xk = tid >> 5, xp4 = (tid & 31) * 4;  // X load coords

    for (int c = 0; c < 4; c++) {
        const int kb = c * 64;

        // ---- stage W: fp32 LDG (L2-hot) -> bf16 hi/lo swizzled STS ----
        // 768 tasks (96 rows x 8 16B-chunks), 3 per thread.
#pragma unroll
        for (int i = 0; i < 3; i++) {
            int j = tid + i * 256;
            int o = j >> 3, q = j & 7;
            const float* wr = (o < 16) ? (w1 + o * C_)
                            : (o < 32) ? (w2 + (o - 16) * C_)
                                       : (w3 + (o - 32) * C_);
            float4 va = *(const float4*)(wr + kb + q * 8);
            float4 vb = *(const float4*)(wr + kb + q * 8 + 4);
            __nv_bfloat162 h0 = __floats2bfloat162_rn(va.x, va.y);
            __nv_bfloat162 h1 = __floats2bfloat162_rn(va.z, va.w);
            __nv_bfloat162 h2 = __floats2bfloat162_rn(vb.x, vb.y);
            __nv_bfloat162 h3 = __floats2bfloat162_rn(vb.z, vb.w);
            float2 f0 = __bfloat1622float2(h0);
            float2 f1 = __bfloat1622float2(h1);
            float2 f2 = __bfloat1622float2(h2);
            float2 f3 = __bfloat1622float2(h3);
            __nv_bfloat162 l0 = __floats2bfloat162_rn(va.x - f0.x, va.y - f0.y);
            __nv_bfloat162 l1 = __floats2bfloat162_rn(va.z - f1.x, va.w - f1.y);
            __nv_bfloat162 l2 = __floats2bfloat162_rn(vb.x - f2.x, vb.y - f2.y);
            __nv_bfloat162 l3 = __floats2bfloat162_rn(vb.z - f3.x, vb.w - f3.y);
            int off = SWZ(o * 128 + q * 16);
            uint4 hv; hv.x = *(uint32_t*)&h0; hv.y = *(uint32_t*)&h1;
                      hv.z = *(uint32_t*)&h2; hv.w = *(uint32_t*)&h3;
            uint4 lv; lv.x = *(uint32_t*)&l0; lv.y = *(uint32_t*)&l1;
                      lv.z = *(uint32_t*)&l2; lv.w = *(uint32_t*)&l3;
            *(uint4*)(smem + WH_OFF + off) = hv;
            *(uint4*)(smem + WL_OFF + off) = lv;
        }

        // ---- load X fp32, convert, STS bf16 hi/lo ----
#pragma unroll
        for (int i = 0; i < 8; i++) {
            int k = xk + i * 8;                    // 0..63
            float4 v = *(const float4*)(xn + (size_t)(kb + k) * HW_ + xp4);
            __nv_bfloat162 h0 = __floats2bfloat162_rn(v.x, v.y);
            __nv_bfloat162 h1 = __floats2bfloat162_rn(v.z, v.w);
            float2 f0 = __bfloat1622float2(h0);
            float2 f1 = __bfloat1622float2(h1);
            __nv_bfloat162 l0 = __floats2bfloat162_rn(v.x - f0.x, v.y - f0.y);
            __nv_bfloat162 l1 = __floats2bfloat162_rn(v.z - f1.x, v.w - f1.y);
            int off = XSWZ(k, xp4 * 2);
            uint2 hw_; hw_.x = *(uint32_t*)&h0; hw_.y = *(uint32_t*)&h1;
            uint2 lw_; lw_.x = *(uint32_t*)&l0; lw_.y = *(uint32_t*)&l1;
            *(uint2*)(smem + BH_OFF + off) = hw_;
            *(uint2*)(smem + BL_OFF + off) = lw_;
        }
        __syncthreads();

        // ---- compute: 4 k16 steps ----
#pragma unroll
        for (int ks = 0; ks < 4; ks++) {
            uint32_t bh[2][2], bl[2][2];
            const int bk = ks * 16 + (lane & 15);
#pragma unroll
            for (int nt = 0; nt < 2; nt++) {
                int pxb = wid * 32 + nt * 16;
                uint32_t ba = sb + XSWZ(bk, pxb);
                ldsm_x2t(bh[nt], ba + BH_OFF);
                ldsm_x2t(bl[nt], ba + BL_OFF);
            }
            const int ach  = (lane & 15);
            const int acol = ks * 32 + ((lane >> 4) << 4);
#pragma unroll
            for (int m = 0; m < 6; m++) {
                uint32_t ah[4], al[4];
                uint32_t aoff = SWZ((m * 16 + ach) * 128 + acol);
                ldsm_x4(ah, sb + WH_OFF + aoff);
                ldsm_x4(al, sb + WL_OFF + aoff);
#pragma unroll
                for (int nt = 0; nt < 2; nt++) {
                    mma_bf16(d[m][nt], ah, bh[nt]);
                    mma_bf16(d[m][nt], al, bh[nt]);
                    mma_bf16(d[m][nt], ah, bl[nt]);
                }
            }
        }
        __syncthreads();
    }

    // ---- epilogue: fragment -> g_y[ch][px], float2 stores ----
    const int gid = lane >> 2, tig = lane & 3;
    float* yn = g_y + (size_t)n * CH_ * HW_;
    const int pxb = p0 + wid * 16 + 2 * tig;
#pragma unroll
    for (int m = 0; m < 6; m++) {
#pragma unroll
        for (int nt = 0; nt < 2; nt++) {
            int px = pxb + nt * 8;
            int ch = m * 16 + gid;
            float2 v0; v0.x = d[m][nt][0]; v0.y = d[m][nt][1];
            float2 v1; v1.x = d[m][nt][2]; v1.y = d[m][nt][3];
            *(float2*)&yn[(size_t)ch * HW_ + px] = v0;
            *(float2*)&yn[(size_t)(ch + 8) * HW_ + px] = v1;
        }
    }
}

// -------------------------------------------------------------------------
// Kernel 2: fused attention.
//   P0: stage per-pixel BN affines in smem
//   P1 (t=(jj,pix)): rel -> bn1 -> relu -> W1 -> bn2 -> relu -> W2 -> smem
//   P2+3 fused (t=(q,pix)): softmax over 9 in regs, then aggregation using
//        the register-resident weights (no smem round-trip, no ws LDS).
// -------------------------------------------------------------------------
__global__ __launch_bounds__(288, 4) void sam_attn_kernel(
    const float* __restrict__ convp,
    const float* __restrict__ w1c,
    const float* __restrict__ w2c,
    const float* __restrict__ g1, const float* __restrict__ b1,
    const float* __restrict__ m1, const float* __restrict__ v1,
    const float* __restrict__ g2, const float* __restrict__ b2,
    const float* __restrict__ m2, const float* __restrict__ v2,
    float* __restrict__ out) {
    __shared__ alignas(16) float sw1[16][20];
    __shared__ alignas(16) float sw2[8][16];
    __shared__ float scp[4];
    __shared__ float sbn[4][32];
    __shared__ float sc_s[32 * 73];

    const int t = threadIdx.x;
    if (t < 288) sw1[t / 18][t % 18] = w1c[t];
    if (t < 128) sw2[t / 16][t % 16] = w2c[t];
    if (t < 4)   scp[t] = convp[t];

    const int n   = blockIdx.y;
    const int hw0 = blockIdx.x * 32;
    const int pix = t & 31;
    const int jj  = t >> 5;
    const int hw  = hw0 + pix;
    const int h   = hw / W_;
    const int w   = hw % W_;

    // ---- Phase 0: BN affines once per pixel ----
    if (t < 32) {
        const int phw = hw0 + t;
        float s1 = g1[phw] * rsqrtf(v1[phw] + EPSBN);
        float s2 = g2[phw] * rsqrtf(v2[phw] + EPSBN);
        sbn[0][t] = s1;
        sbn[1][t] = b1[phw] - m1[phw] * s1;
        sbn[2][t] = s2;
        sbn[3][t] = b2[phw] - m2[phw] * s2;
    }
    __syncthreads();

    const float* yn = g_y + (size_t)n * CH_ * HW_;

    // ---- Phase 1: logits for this (pix, jj) ----
    {
        const float s1 = sbn[0][pix], o1 = sbn[1][pix];
        const float s2 = sbn[2][pix], o2 = sbn[3][pix];

        int di = jj / 3 - 1, dj = jj % 3 - 1;
        int nh = h + di;
        nh = (nh < 0) ? -nh : ((nh >= H_) ? 2 * H_ - 2 - nh : nh);
        int nw = w + dj;
        nw = (nw < 0) ? -nw : ((nw >= W_) ? 2 * W_ - 2 - nw : nw);
        const int nhw = nh * W_ + nw;

        float a[18];
#pragma unroll
        for (int c = 0; c < 16; c++) {
            float r = yn[(size_t)c * HW_ + hw] - yn[(size_t)(16 + c) * HW_ + nhw];
            a[c] = fmaxf(fmaf(r, s1, o1), 0.0f);
        }
        const float lw  = -1.0f + 2.0f * (float)w  / 55.0f;
        const float lh  = -1.0f + 2.0f * (float)h  / 55.0f;
        const float nlw = -1.0f + 2.0f * (float)nw / 55.0f;
        const float nlh = -1.0f + 2.0f * (float)nh / 55.0f;
        const float dp0 = scp[0] * (lw - nlw) + scp[1] * (lh - nlh);
        const float dp1 = scp[2] * (lw - nlw) + scp[3] * (lh - nlh);
        a[16] = fmaxf(fmaf(dp0, s1, o1), 0.0f);
        a[17] = fmaxf(fmaf(dp1, s1, o1), 0.0f);

        float hb[16];
#pragma unroll
        for (int o = 0; o < 16; o++) {
            const float4* wr = (const float4*)&sw1[o][0];
            float4 w0 = wr[0], w1v = wr[1], w2v = wr[2], w3v = wr[3];
            float tacc = 0.0f;
            tacc = fmaf(w0.x,  a[0],  tacc); tacc = fmaf(w0.y,  a[1],  tacc);
            tacc = fmaf(w0.z,  a[2],  tacc); tacc = fmaf(w0.w,  a[3],  tacc);
            tacc = fmaf(w1v.x, a[4],  tacc); tacc = fmaf(w1v.y, a[5],  tacc);
            tacc = fmaf(w1v.z, a[6],  tacc); tacc = fmaf(w1v.w, a[7],  tacc);
            tacc = fmaf(w2v.x, a[8],  tacc); tacc = fmaf(w2v.y, a[9],  tacc);
            tacc = fmaf(w2v.z, a[10], tacc); tacc = fmaf(w2v.w, a[11], tacc);
            tacc = fmaf(w3v.x, a[12], tacc); tacc = fmaf(w3v.y, a[13], tacc);
            tacc = fmaf(w3v.z, a[14], tacc); tacc = fmaf(w3v.w, a[15], tacc);
            tacc = fmaf(sw1[o][16], a[16], tacc);
            tacc = fmaf(sw1[o][17], a[17], tacc);
            hb[o] = fmaxf(fmaf(tacc, s2, o2), 0.0f);
        }
        float* dst = &sc_s[pix * 73 + jj * 8];
#pragma unroll
        for (int q = 0; q < 8; q++) {
            const float4* wr = (const float4*)&sw2[q][0];
            float4 w0 = wr[0], w1v = wr[1], w2v = wr[2], w3v = wr[3];
            float tacc = 0.0f;
            tacc = fmaf(w0.x,  hb[0],  tacc); tacc = fmaf(w0.y,  hb[1],  tacc);
            tacc = fmaf(w0.z,  hb[2],  tacc); tacc = fmaf(w0.w,  hb[3],  tacc);
            tacc = fmaf(w1v.x, hb[4],  tacc); tacc = fmaf(w1v.y, hb[5],  tacc);
            tacc = fmaf(w1v.z, hb[6],  tacc); tacc = fmaf(w1v.w, hb[7],  tacc);
            tacc = fmaf(w2v.x, hb[8],  tacc); tacc = fmaf(w2v.y, hb[9],  tacc);
            tacc = fmaf(w2v.z, hb[10], tacc); tacc = fmaf(w2v.w, hb[11], tacc);
            tacc = fmaf(w3v.x, hb[12], tacc); tacc = fmaf(w3v.y, hb[13], tacc);
            tacc = fmaf(w3v.z, hb[14], tacc); tacc = fmaf(w3v.w, hb[15], tacc);
            dst[q] = tacc;
        }
    }
    __syncthreads();

    // ---- Phase 2+3 fused: softmax (regs) + aggregation, thread=(q,pix) ----
    if (t < 256) {
        const int q = t >> 5;
        const float* base = &sc_s[pix * 73 + q];
        float v[9];
#pragma unroll
        for (int j = 0; j < 9; j++) v[j] = base[j * 8];
        float mx = v[0];
#pragma unroll
        for (int j = 1; j < 9; j++) mx = fmaxf(mx, v[j]);
        float sum = 0.0f;
#pragma unroll
        for (int j = 0; j < 9; j++) { v[j] = __expf(v[j] - mx); sum += v[j]; }
        float inv = 1.0f / sum;
#pragma unroll
        for (int j = 0; j < 9; j++) v[j] *= inv;

        int nhw9[9];
#pragma unroll
        for (int j = 0; j < 9; j++) {
            int nh = h + j / 3 - 1;
            nh = (nh < 0) ? -nh : ((nh >= H_) ? 2 * H_ - 2 - nh : nh);
            int nw = w + j % 3 - 1;
            nw = (nw < 0) ? -nw : ((nw >= W_) ? 2 * W_ - 2 - nw : nw);
            nhw9[j] = nh * W_ + nw;
        }
        // aggregation: out channel = g*8 + q, weight = v[j]
        const float* y3 = yn + (size_t)(32 + q) * HW_;
        float acc[8];
#pragma unroll
        for (int g = 0; g < 8; g++) acc[g] = 0.0f;
#pragma unroll
        for (int j = 0; j < 9; j++) {
            const int nhw = nhw9[j];
            const float wj = v[j];
#pragma unroll
            for (int g = 0; g < 8; g++)
                acc[g] = fmaf(wj, y3[(size_t)(g * 8) * HW_ + nhw], acc[g]);
        }
        float* on = out + (size_t)n * 64 * HW_ + hw;
#pragma unroll
        for (int g = 0; g < 8; g++)
            on[(size_t)(g * 8 + q) * HW_] = acc[g];
    }
}

// -------------------------------------------------------------------------
// Launcher.
// -------------------------------------------------------------------------
extern "C" void kernel_launch(void* const* d_in, const int* in_sizes, int n_in,
                              void* d_out, int out_size) {
    const float* x   = (const float*)d_in[0];
    const float* w1  = (const float*)d_in[1];
    const float* w2  = (const float*)d_in[2];
    const float* w3  = (const float*)d_in[3];
    const float* cp  = (const float*)d_in[4];
    const float* cw1 = (const float*)d_in[5];
    const float* cw2 = (const float*)d_in[6];
    const float* g1  = (const float*)d_in[7];
    const float* b1  = (const float*)d_in[8];
    const float* m1  = (const float*)d_in[9];
    const float* v1  = (const float*)d_in[10];
    const float* g2  = (const float*)d_in[11];
    const float* b2  = (const float*)d_in[12];
    const float* m2  = (const float*)d_in[13];
    const float* v2  = (const float*)d_in[14];
    float* out = (float*)d_out;

    cudaFuncSetAttribute(sam_gemm_mma,
                         cudaFuncAttributeMaxDynamicSharedMemorySize, SMEM_MMA);

    dim3 gg(25, N_);                  // 25 px tiles (last clamped) x 16 n
    sam_gemm_mma<<<gg, 256, SMEM_MMA>>>(x, w1, w2, w3);

    dim3 ga(HW_ / 32, N_);            // 98 x 16
    sam_attn_kernel<<<ga, 288>>>(cp, cw1, cw2,
                                 g1, b1, m1, v1,
                                 g2, b2, m2, v2, out);
}

// round 9
// speedup vs baseline: 2.8317x; 1.0940x over previous
#include <cuda_runtime.h>
#include <cuda_bf16.h>
#include <math.h>
#include <stdint.h>

#define H_ 56
#define W_ 56
#define HW_ 3136
#define N_ 16
#define C_ 256
#define CH_ 96
#define EPSBN 1e-3f

// Scratch: stacked GEMM output y[n][o][hw], o in [0,96):
//   rows 0..15 = x1, 16..31 = x2, 32..95 = x3
__device__ float g_y[N_ * CH_ * HW_];

// ---------------- helpers ----------------
__device__ __forceinline__ uint32_t smem_addr_u32(const void* p) {
    uint32_t a;
    asm("{ .reg .u64 t; cvta.to.shared.u64 t, %1; cvt.u32.u64 %0, t; }"
        : "=r"(a) : "l"(p));
    return a;
}

__device__ __forceinline__ void ldsm_x4(uint32_t* r, uint32_t addr) {
    asm volatile("ldmatrix.sync.aligned.m8n8.x4.shared.b16 {%0,%1,%2,%3}, [%4];"
                 : "=r"(r[0]), "=r"(r[1]), "=r"(r[2]), "=r"(r[3]) : "r"(addr));
}

__device__ __forceinline__ void ldsm_x2t(uint32_t* r, uint32_t addr) {
    asm volatile("ldmatrix.sync.aligned.m8n8.x2.trans.shared.b16 {%0,%1}, [%2];"
                 : "=r"(r[0]), "=r"(r[1]) : "r"(addr));
}

__device__ __forceinline__ void mma_bf16(float* d, const uint32_t* a,
                                         const uint32_t* b) {
    asm volatile(
        "mma.sync.aligned.m16n8k16.row.col.f32.bf16.bf16.f32 "
        "{%0,%1,%2,%3}, {%4,%5,%6,%7}, {%8,%9}, {%0,%1,%2,%3};"
        : "+f"(d[0]), "+f"(d[1]), "+f"(d[2]), "+f"(d[3])
        : "r"(a[0]), "r"(a[1]), "r"(a[2]), "r"(a[3]), "r"(b[0]), "r"(b[1]));
}

// SW128 swizzle for 128B rows (16B granular)
#define SWZ(o) ((o) ^ (((o) >> 3) & 0x70))
// X-tile swizzle: rows of 256B (128 px bf16); XOR 16B-chunk index by k&7
#define XSWZ(k, pxb) ((k) * 256 + ((pxb) ^ (((k) & 7) << 4)))

// smem layout (bytes), dynamic
#define BH_OFF 0        // X hi  [64 k][128 px] bf16, 256B rows  = 16384
#define BL_OFF 16384    // X lo
#define WH_OFF 32768    // W hi  [96 ch][64 k]  bf16, SW128      = 12288
#define WL_OFF 45056    // W lo
#define SMEM_MMA 57344

// -------------------------------------------------------------------------
// Kernel 1: split-bf16 GEMM via mma.sync, register-prefetch pipelined.
// D[ch=96, px=128] = W[96,256] @ X[256, px]
//   = Wh@Xh + Wh@Xl + Wl@Xh       (Wl@Xl dropped, ~2^-16)
// Per chunk: STS-convert (from regs) -> sync -> LDG prefetch chunk c+1 ->
// MMA loop (covers LDG latency) -> sync.
// -------------------------------------------------------------------------
__global__ __launch_bounds__(256) void sam_gemm_mma(
    const float* __restrict__ x,
    const float* __restrict__ w1,
    const float* __restrict__ w2,
    const float* __restrict__ w3) {
    extern __shared__ __align__(1024) char smem[];
    const int tid  = threadIdx.x;
    const int wid  = tid >> 5;
    const int lane = tid & 31;
    const int n    = blockIdx.y;
    int p0 = blockIdx.x * 128;
    if (p0 > HW_ - 128) p0 = HW_ - 128;   // overlap tile: identical dup writes

    const uint32_t sb = smem_addr_u32(smem);
    const float* xn = x + (size_t)n * C_ * HW_ + p0;

    float d[6][2][4];
#pragma unroll
    for (int m = 0; m < 6; m++)
#pragma unroll
        for (int nt = 0; nt < 2; nt++)
#pragma unroll
            for (int r = 0; r < 4; r++) d[m][nt][r] = 0.0f;

    const int xk = tid >> 5, xp4 = (tid & 31) * 4;  // X load coords
    // W task coords: 3 tasks j = tid + i*256; o = j>>3, q = j&7
    const float* wrow_[3];
    int wq_[3];
#pragma unroll
    for (int i = 0; i < 3; i++) {
        int j = tid + i * 256;
        int o = j >> 3;
        wq_[i] = j & 7;
        wrow_[i] = (o < 16) ? (w1 + o * C_)
                 : (o < 32) ? (w2 + (o - 16) * C_)
                            : (w3 + (o - 32) * C_);
    }

    float4 Xr[8];        // X prefetch regs
    float4 Wr[3][2];     // W prefetch regs

#define LOADX(kb)                                                              \
    _Pragma("unroll")                                                          \
    for (int i = 0; i < 8; i++)                                                \
        Xr[i] = *(const float4*)(xn + (size_t)((kb) + xk + i * 8) * HW_ + xp4)

#define LOADW(kb)                                                              \
    _Pragma("unroll")                                                          \
    for (int i = 0; i < 3; i++) {                                              \
        Wr[i][0] = *(const float4*)(wrow_[i] + (kb) + wq_[i] * 8);             \
        Wr[i][1] = *(const float4*)(wrow_[i] + (kb) + wq_[i] * 8 + 4);         \
    }

    LOADX(0);
    LOADW(0);

    for (int c = 0; c < 4; c++) {
        // ---- STS: convert regs -> bf16 hi/lo swizzled tiles ----
#pragma unroll
        for (int i = 0; i < 3; i++) {
            int j = tid + i * 256;
            int o = j >> 3, q = j & 7;
            float4 va = Wr[i][0], vb = Wr[i][1];
            __nv_bfloat162 h0 = __floats2bfloat162_rn(va.x, va.y);
            __nv_bfloat162 h1 = __floats2bfloat162_rn(va.z, va.w);
            __nv_bfloat162 h2 = __floats2bfloat162_rn(vb.x, vb.y);
            __nv_bfloat162 h3 = __floats2bfloat162_rn(vb.z, vb.w);
            float2 f0 = __bfloat1622float2(h0);
            float2 f1 = __bfloat1622float2(h1);
            float2 f2 = __bfloat1622float2(h2);
            float2 f3 = __bfloat1622float2(h3);
            __nv_bfloat162 l0 = __floats2bfloat162_rn(va.x - f0.x, va.y - f0.y);
            __nv_bfloat162 l1 = __floats2bfloat162_rn(va.z - f1.x, va.w - f1.y);
            __nv_bfloat162 l2 = __floats2bfloat162_rn(vb.x - f2.x, vb.y - f2.y);
            __nv_bfloat162 l3 = __floats2bfloat162_rn(vb.z - f3.x, vb.w - f3.y);
            int off = SWZ(o * 128 + q * 16);
            uint4 hv; hv.x = *(uint32_t*)&h0; hv.y = *(uint32_t*)&h1;
                      hv.z = *(uint32_t*)&h2; hv.w = *(uint32_t*)&h3;
            uint4 lv; lv.x = *(uint32_t*)&l0; lv.y = *(uint32_t*)&l1;
                      lv.z = *(uint32_t*)&l2; lv.w = *(uint32_t*)&l3;
            *(uint4*)(smem + WH_OFF + off) = hv;
            *(uint4*)(smem + WL_OFF + off) = lv;
        }
#pragma unroll
        for (int i = 0; i < 8; i++) {
            int k = xk + i * 8;
            float4 v = Xr[i];
            __nv_bfloat162 h0 = __floats2bfloat162_rn(v.x, v.y);
            __nv_bfloat162 h1 = __floats2bfloat162_rn(v.z, v.w);
            float2 f0 = __bfloat1622float2(h0);
            float2 f1 = __bfloat1622float2(h1);
            __nv_bfloat162 l0 = __floats2bfloat162_rn(v.x - f0.x, v.y - f0.y);
            __nv_bfloat162 l1 = __floats2bfloat162_rn(v.z - f1.x, v.w - f1.y);
            int off = XSWZ(k, xp4 * 2);
            uint2 hw_; hw_.x = *(uint32_t*)&h0; hw_.y = *(uint32_t*)&h1;
            uint2 lw_; lw_.x = *(uint32_t*)&l0; lw_.y = *(uint32_t*)&l1;
            *(uint2*)(smem + BH_OFF + off) = hw_;
            *(uint2*)(smem + BL_OFF + off) = lw_;
        }
        __syncthreads();

        // ---- prefetch next chunk (LDG drains under MMA loop) ----
        if (c < 3) {
            const int kn = (c + 1) * 64;
            LOADX(kn);
            LOADW(kn);
        }

        // ---- compute: 4 k16 steps ----
#pragma unroll
        for (int ks = 0; ks < 4; ks++) {
            uint32_t bh[2][2], bl[2][2];
            const int bk = ks * 16 + (lane & 15);
#pragma unroll
            for (int nt = 0; nt < 2; nt++) {
                int pxb = wid * 32 + nt * 16;
                uint32_t ba = sb + XSWZ(bk, pxb);
                ldsm_x2t(bh[nt], ba + BH_OFF);
                ldsm_x2t(bl[nt], ba + BL_OFF);
            }
            const int ach  = (lane & 15);
            const int acol = ks * 32 + ((lane >> 4) << 4);
#pragma unroll
            for (int m = 0; m < 6; m++) {
                uint32_t ah[4], al[4];
                uint32_t aoff = SWZ((m * 16 + ach) * 128 + acol);
                ldsm_x4(ah, sb + WH_OFF + aoff);
                ldsm_x4(al, sb + WL_OFF + aoff);
#pragma unroll
                for (int nt = 0; nt < 2; nt++) {
                    mma_bf16(d[m][nt], ah, bh[nt]);
                    mma_bf16(d[m][nt], al, bh[nt]);
                    mma_bf16(d[m][nt], ah, bl[nt]);
                }
            }
        }
        __syncthreads();
    }
#undef LOADX
#undef LOADW

    // ---- epilogue: fragment -> g_y[ch][px], float2 stores ----
    const int gid = lane >> 2, tig = lane & 3;
    float* yn = g_y + (size_t)n * CH_ * HW_;
    const int pxb = p0 + wid * 16 + 2 * tig;
#pragma unroll
    for (int m = 0; m < 6; m++) {
#pragma unroll
        for (int nt = 0; nt < 2; nt++) {
            int px = pxb + nt * 8;
            int ch = m * 16 + gid;
            float2 v0; v0.x = d[m][nt][0]; v0.y = d[m][nt][1];
            float2 v1; v1.x = d[m][nt][2]; v1.y = d[m][nt][3];
            *(float2*)&yn[(size_t)ch * HW_ + px] = v0;
            *(float2*)&yn[(size_t)(ch + 8) * HW_ + px] = v1;
        }
    }
}

// -------------------------------------------------------------------------
// Kernel 2: fused attention.
//   P0: stage per-pixel BN affines + center x1[16] in smem
//   P1 (t=(jj,pix)): rel -> bn1 -> relu -> W1 -> bn2 -> relu -> W2 -> smem
//   P2+3 fused (t=(q,pix)): softmax in regs + aggregation
// -------------------------------------------------------------------------
__global__ __launch_bounds__(288, 4) void sam_attn_kernel(
    const float* __restrict__ convp,
    const float* __restrict__ w1c,
    const float* __restrict__ w2c,
    const float* __restrict__ g1, const float* __restrict__ b1,
    const float* __restrict__ m1, const float* __restrict__ v1,
    const float* __restrict__ g2, const float* __restrict__ b2,
    const float* __restrict__ m2, const float* __restrict__ v2,
    float* __restrict__ out) {
    __shared__ alignas(16) float sw1[16][20];
    __shared__ alignas(16) float sw2[8][16];
    __shared__ float scp[4];
    __shared__ float sbn[4][32];
    __shared__ float sx1[16][33];
    __shared__ float sc_s[32 * 73];

    const int t = threadIdx.x;
    if (t < 288) sw1[t / 18][t % 18] = w1c[t];
    if (t < 128) sw2[t / 16][t % 16] = w2c[t];
    if (t < 4)   scp[t] = convp[t];

    const int n   = blockIdx.y;
    const int hw0 = blockIdx.x * 32;
    const int pix = t & 31;
    const int jj  = t >> 5;
    const int hw  = hw0 + pix;
    const int h   = hw / W_;
    const int w   = hw % W_;

    const float* yn = g_y + (size_t)n * CH_ * HW_;

    // ---- Phase 0: BN affines + center x1 staging ----
    if (t < 32) {
        const int phw = hw0 + t;
        float s1 = g1[phw] * rsqrtf(v1[phw] + EPSBN);
        float s2 = g2[phw] * rsqrtf(v2[phw] + EPSBN);
        sbn[0][t] = s1;
        sbn[1][t] = b1[phw] - m1[phw] * s1;
        sbn[2][t] = s2;
        sbn[3][t] = b2[phw] - m2[phw] * s2;
    }
    if (t < 256) {
#pragma unroll
        for (int i = 0; i < 2; i++) {
            int idx = t + i * 256;
            int c = idx >> 5, p = idx & 31;
            sx1[c][p] = yn[(size_t)c * HW_ + hw0 + p];
        }
    }
    __syncthreads();

    // ---- Phase 1: logits for this (pix, jj) ----
    {
        const float s1 = sbn[0][pix], o1 = sbn[1][pix];
        const float s2 = sbn[2][pix], o2 = sbn[3][pix];

        int di = jj / 3 - 1, dj = jj % 3 - 1;
        int nh = h + di;
        nh = (nh < 0) ? -nh : ((nh >= H_) ? 2 * H_ - 2 - nh : nh);
        int nw = w + dj;
        nw = (nw < 0) ? -nw : ((nw >= W_) ? 2 * W_ - 2 - nw : nw);
        const int nhw = nh * W_ + nw;

        float a[18];
#pragma unroll
        for (int c = 0; c < 16; c++) {
            float r = sx1[c][pix] - yn[(size_t)(16 + c) * HW_ + nhw];
            a[c] = fmaxf(fmaf(r, s1, o1), 0.0f);
        }
        const float lw  = -1.0f + 2.0f * (float)w  / 55.0f;
        const float lh  = -1.0f + 2.0f * (float)h  / 55.0f;
        const float nlw = -1.0f + 2.0f * (float)nw / 55.0f;
        const float nlh = -1.0f + 2.0f * (float)nh / 55.0f;
        const float dp0 = scp[0] * (lw - nlw) + scp[1] * (lh - nlh);
        const float dp1 = scp[2] * (lw - nlw) + scp[3] * (lh - nlh);
        a[16] = fmaxf(fmaf(dp0, s1, o1), 0.0f);
        a[17] = fmaxf(fmaf(dp1, s1, o1), 0.0f);

        float hb[16];
#pragma unroll
        for (int o = 0; o < 16; o++) {
            const float4* wr = (const float4*)&sw1[o][0];
            float4 w0 = wr[0], w1v = wr[1], w2v = wr[2], w3v = wr[3];
            float tacc = 0.0f;
            tacc = fmaf(w0.x,  a[0],  tacc); tacc = fmaf(w0.y,  a[1],  tacc);
            tacc = fmaf(w0.z,  a[2],  tacc); tacc = fmaf(w0.w,  a[3],  tacc);
            tacc = fmaf(w1v.x, a[4],  tacc); tacc = fmaf(w1v.y, a[5],  tacc);
            tacc = fmaf(w1v.z, a[6],  tacc); tacc = fmaf(w1v.w, a[7],  tacc);
            tacc = fmaf(w2v.x, a[8],  tacc); tacc = fmaf(w2v.y, a[9],  tacc);
            tacc = fmaf(w2v.z, a[10], tacc); tacc = fmaf(w2v.w, a[11], tacc);
            tacc = fmaf(w3v.x, a[12], tacc); tacc = fmaf(w3v.y, a[13], tacc);
            tacc = fmaf(w3v.z, a[14], tacc); tacc = fmaf(w3v.w, a[15], tacc);
            tacc = fmaf(sw1[o][16], a[16], tacc);
            tacc = fmaf(sw1[o][17], a[17], tacc);
            hb[o] = fmaxf(fmaf(tacc, s2, o2), 0.0f);
        }
        float* dst = &sc_s[pix * 73 + jj * 8];
#pragma unroll
        for (int q = 0; q < 8; q++) {
            const float4* wr = (const float4*)&sw2[q][0];
            float4 w0 = wr[0], w1v = wr[1], w2v = wr[2], w3v = wr[3];
            float tacc = 0.0f;
            tacc = fmaf(w0.x,  hb[0],  tacc); tacc = fmaf(w0.y,  hb[1],  tacc);
            tacc = fmaf(w0.z,  hb[2],  tacc); tacc = fmaf(w0.w,  hb[3],  tacc);
            tacc = fmaf(w1v.x, hb[4],  tacc); tacc = fmaf(w1v.y, hb[5],  tacc);
            tacc = fmaf(w1v.z, hb[6],  tacc); tacc = fmaf(w1v.w, hb[7],  tacc);
            tacc = fmaf(w2v.x, hb[8],  tacc); tacc = fmaf(w2v.y, hb[9],  tacc);
            tacc = fmaf(w2v.z, hb[10], tacc); tacc = fmaf(w2v.w, hb[11], tacc);
            tacc = fmaf(w3v.x, hb[12], tacc); tacc = fmaf(w3v.y, hb[13], tacc);
            tacc = fmaf(w3v.z, hb[14], tacc); tacc = fmaf(w3v.w, hb[15], tacc);
            dst[q] = tacc;
        }
    }
    __syncthreads();

    // ---- Phase 2+3 fused: softmax (regs) + aggregation, thread=(q,pix) ----
    if (t < 256) {
        const int q = t >> 5;
        const float* base = &sc_s[pix * 73 + q];
        float v[9];
#pragma unroll
        for (int j = 0; j < 9; j++) v[j] = base[j * 8];
        float mx = v[0];
#pragma unroll
        for (int j = 1; j < 9; j++) mx = fmaxf(mx, v[j]);
        float sum = 0.0f;
#pragma unroll
        for (int j = 0; j < 9; j++) { v[j] = __expf(v[j] - mx); sum += v[j]; }
        float inv = 1.0f / sum;
#pragma unroll
        for (int j = 0; j < 9; j++) v[j] *= inv;

        int nhw9[9];
#pragma unroll
        for (int j = 0; j < 9; j++) {
            int nh = h + j / 3 - 1;
            nh = (nh < 0) ? -nh : ((nh >= H_) ? 2 * H_ - 2 - nh : nh);
            int nw = w + j % 3 - 1;
            nw = (nw < 0) ? -nw : ((nw >= W_) ? 2 * W_ - 2 - nw : nw);
            nhw9[j] = nh * W_ + nw;
        }
        const float* y3 = yn + (size_t)(32 + q) * HW_;
        float acc[8];
#pragma unroll
        for (int g = 0; g < 8; g++) acc[g] = 0.0f;
#pragma unroll
        for (int j = 0; j < 9; j++) {
            const int nhw = nhw9[j];
            const float wj = v[j];
#pragma unroll
            for (int g = 0; g < 8; g++)
                acc[g] = fmaf(wj, y3[(size_t)(g * 8) * HW_ + nhw], acc[g]);
        }
        float* on = out + (size_t)n * 64 * HW_ + hw;
#pragma unroll
        for (int g = 0; g < 8; g++)
            on[(size_t)(g * 8 + q) * HW_] = acc[g];
    }
}

// -------------------------------------------------------------------------
// Launcher.
// -------------------------------------------------------------------------
extern "C" void kernel_launch(void* const* d_in, const int* in_sizes, int n_in,
                              void* d_out, int out_size) {
    const float* x   = (const float*)d_in[0];
    const float* w1  = (const float*)d_in[1];
    const float* w2  = (const float*)d_in[2];
    const float* w3  = (const float*)d_in[3];
    const float* cp  = (const float*)d_in[4];
    const float* cw1 = (const float*)d_in[5];
    const float* cw2 = (const float*)d_in[6];
    const float* g1  = (const float*)d_in[7];
    const float* b1  = (const float*)d_in[8];
    const float* m1  = (const float*)d_in[9];
    const float* v1  = (const float*)d_in[10];
    const float* g2  = (const float*)d_in[11];
    const float* b2  = (const float*)d_in[12];
    const float* m2  = (const float*)d_in[13];
    const float* v2  = (const float*)d_in[14];
    float* out = (float*)d_out;

    cudaFuncSetAttribute(sam_gemm_mma,
                         cudaFuncAttributeMaxDynamicSharedMemorySize, SMEM_MMA);

    dim3 gg(25, N_);                  // 25 px tiles (last clamped) x 16 n
    sam_gemm_mma<<<gg, 256, SMEM_MMA>>>(x, w1, w2, w3);

    dim3 ga(HW_ / 32, N_);            // 98 x 16
    sam_attn_kernel<<<ga, 288>>>(cp, cw1, cw2,
                                 g1, b1, m1, v1,
                                 g2, b2, m2, v2, out);
}

// round 10
// speedup vs baseline: 3.0101x; 1.0630x over previous
#include <cuda_runtime.h>
#include <cuda_bf16.h>
#include <math.h>
#include <stdint.h>

#define H_ 56
#define W_ 56
#define HW_ 3136
#define N_ 16
#define C_ 256
#define CH_ 96
#define EPSBN 1e-3f

// Scratch: stacked GEMM output y[n][o][hw], o in [0,96):
//   rows 0..15 = x1, 16..31 = x2, 32..95 = x3
__device__ float g_y[N_ * CH_ * HW_];

// ---------------- helpers ----------------
__device__ __forceinline__ uint32_t smem_addr_u32(const void* p) {
    uint32_t a;
    asm("{ .reg .u64 t; cvta.to.shared.u64 t, %1; cvt.u32.u64 %0, t; }"
        : "=r"(a) : "l"(p));
    return a;
}

__device__ __forceinline__ void ldsm_x4(uint32_t* r, uint32_t addr) {
    asm volatile("ldmatrix.sync.aligned.m8n8.x4.shared.b16 {%0,%1,%2,%3}, [%4];"
                 : "=r"(r[0]), "=r"(r[1]), "=r"(r[2]), "=r"(r[3]) : "r"(addr));
}

__device__ __forceinline__ void ldsm_x2t(uint32_t* r, uint32_t addr) {
    asm volatile("ldmatrix.sync.aligned.m8n8.x2.trans.shared.b16 {%0,%1}, [%2];"
                 : "=r"(r[0]), "=r"(r[1]) : "r"(addr));
}

__device__ __forceinline__ void mma_bf16(float* d, const uint32_t* a,
                                         const uint32_t* b) {
    asm volatile(
        "mma.sync.aligned.m16n8k16.row.col.f32.bf16.bf16.f32 "
        "{%0,%1,%2,%3}, {%4,%5,%6,%7}, {%8,%9}, {%0,%1,%2,%3};"
        : "+f"(d[0]), "+f"(d[1]), "+f"(d[2]), "+f"(d[3])
        : "r"(a[0]), "r"(a[1]), "r"(a[2]), "r"(a[3]), "r"(b[0]), "r"(b[1]));
}

// SW128 swizzle for 128B rows (16B granular)
#define SWZ(o) ((o) ^ (((o) >> 3) & 0x70))
// X-tile swizzle: rows of 256B (128 px bf16); XOR 16B-chunk index by k&7
#define XSWZ(k, pxb) ((k) * 256 + ((pxb) ^ (((k) & 7) << 4)))

// smem layout (bytes), dynamic
#define BH_OFF 0        // X hi  [64 k][128 px] bf16, 256B rows  = 16384
#define BL_OFF 16384    // X lo
#define WH_OFF 32768    // W hi  [96 ch][64 k]  bf16, SW128      = 12288
#define WL_OFF 45056    // W lo
#define SMEM_MMA 57344

// -------------------------------------------------------------------------
// Kernel 1: split-bf16 GEMM via mma.sync.
// D[ch=96, px=128] = W[96,256] @ X[256, px]
//   = Wh@Xh + Wh@Xl + Wl@Xh       (Wl@Xl dropped, ~2^-16)
// __launch_bounds__(256,2): reg cap 128 -> 2 blocks/SM; co-resident block's
// MMA loop hides this block's convert/STS/LDG phase. X prefetched in regs
// (DRAM latency); W loaded synchronously at chunk head (L2-hot, 98KB).
// -------------------------------------------------------------------------
__global__ __launch_bounds__(256, 2) void sam_gemm_mma(
    const float* __restrict__ x,
    const float* __restrict__ w1,
    const float* __restrict__ w2,
    const float* __restrict__ w3) {
    extern __shared__ __align__(1024) char smem[];
    const int tid  = threadIdx.x;
    const int wid  = tid >> 5;
    const int lane = tid & 31;
    const int n    = blockIdx.y;
    int p0 = blockIdx.x * 128;
    if (p0 > HW_ - 128) p0 = HW_ - 128;   // overlap tile: identical dup writes

    const uint32_t sb = smem_addr_u32(smem);
    const float* xn = x + (size_t)n * C_ * HW_ + p0;

    float d[6][2][4];
#pragma unroll
    for (int m = 0; m < 6; m++)
#pragma unroll
        for (int nt = 0; nt < 2; nt++)
#pragma unroll
            for (int r = 0; r < 4; r++) d[m][nt][r] = 0.0f;

    const int xk = tid >> 5, xp4 = (tid & 31) * 4;  // X load coords
    // W task coords: 3 tasks j = tid + i*256; o = j>>3, q = j&7
    const float* wrow_[3];
    int wq_[3];
#pragma unroll
    for (int i = 0; i < 3; i++) {
        int j = tid + i * 256;
        int o = j >> 3;
        wq_[i] = j & 7;
        wrow_[i] = (o < 16) ? (w1 + o * C_)
                 : (o < 32) ? (w2 + (o - 16) * C_)
                            : (w3 + (o - 32) * C_);
    }

    float4 Xr[8];        // X prefetch regs

#define LOADX(kb)                                                              \
    _Pragma("unroll")                                                          \
    for (int i = 0; i < 8; i++)                                                \
        Xr[i] = *(const float4*)(xn + (size_t)((kb) + xk + i * 8) * HW_ + xp4)

    LOADX(0);

    for (int c = 0; c < 4; c++) {
        const int kb = c * 64;

        // ---- W: synchronous LDG (L2-hot) -> bf16 hi/lo swizzled STS ----
#pragma unroll
        for (int i = 0; i < 3; i++) {
            int j = tid + i * 256;
            int o = j >> 3, q = j & 7;
            float4 va = *(const float4*)(wrow_[i] + kb + wq_[i] * 8);
            float4 vb = *(const float4*)(wrow_[i] + kb + wq_[i] * 8 + 4);
            __nv_bfloat162 h0 = __floats2bfloat162_rn(va.x, va.y);
            __nv_bfloat162 h1 = __floats2bfloat162_rn(va.z, va.w);
            __nv_bfloat162 h2 = __floats2bfloat162_rn(vb.x, vb.y);
            __nv_bfloat162 h3 = __floats2bfloat162_rn(vb.z, vb.w);
            float2 f0 = __bfloat1622float2(h0);
            float2 f1 = __bfloat1622float2(h1);
            float2 f2 = __bfloat1622float2(h2);
            float2 f3 = __bfloat1622float2(h3);
            __nv_bfloat162 l0 = __floats2bfloat162_rn(va.x - f0.x, va.y - f0.y);
            __nv_bfloat162 l1 = __floats2bfloat162_rn(va.z - f1.x, va.w - f1.y);
            __nv_bfloat162 l2 = __floats2bfloat162_rn(vb.x - f2.x, vb.y - f2.y);
            __nv_bfloat162 l3 = __floats2bfloat162_rn(vb.z - f3.x, vb.w - f3.y);
            int off = SWZ(o * 128 + q * 16);
            uint4 hv; hv.x = *(uint32_t*)&h0; hv.y = *(uint32_t*)&h1;
                      hv.z = *(uint32_t*)&h2; hv.w = *(uint32_t*)&h3;
            uint4 lv; lv.x = *(uint32_t*)&l0; lv.y = *(uint32_t*)&l1;
                      lv.z = *(uint32_t*)&l2; lv.w = *(uint32_t*)&l3;
            *(uint4*)(smem + WH_OFF + off) = hv;
            *(uint4*)(smem + WL_OFF + off) = lv;
        }

        // ---- X: convert prefetched regs -> bf16 hi/lo swizzled STS ----
#pragma unroll
        for (int i = 0; i < 8; i++) {
            int k = xk + i * 8;
            float4 v = Xr[i];
            __nv_bfloat162 h0 = __floats2bfloat162_rn(v.x, v.y);
            __nv_bfloat162 h1 = __floats2bfloat162_rn(v.z, v.w);
            float2 f0 = __bfloat1622float2(h0);
            float2 f1 = __bfloat1622float2(h1);
            __nv_bfloat162 l0 = __floats2bfloat162_rn(v.x - f0.x, v.y - f0.y);
            __nv_bfloat162 l1 = __floats2bfloat162_rn(v.z - f1.x, v.w - f1.y);
            int off = XSWZ(k, xp4 * 2);
            uint2 hw_; hw_.x = *(uint32_t*)&h0; hw_.y = *(uint32_t*)&h1;
            uint2 lw_; lw_.x = *(uint32_t*)&l0; lw_.y = *(uint32_t*)&l1;
            *(uint2*)(smem + BH_OFF + off) = hw_;
            *(uint2*)(smem + BL_OFF + off) = lw_;
        }
        __syncthreads();

        // ---- prefetch next X chunk (LDG drains under MMA loop) ----
        if (c < 3) LOADX(kb + 64);

        // ---- compute: 4 k16 steps ----
#pragma unroll
        for (int ks = 0; ks < 4; ks++) {
            uint32_t bh[2][2], bl[2][2];
            const int bk = ks * 16 + (lane & 15);
#pragma unroll
            for (int nt = 0; nt < 2; nt++) {
                int pxb = wid * 32 + nt * 16;
                uint32_t ba = sb + XSWZ(bk, pxb);
                ldsm_x2t(bh[nt], ba + BH_OFF);
                ldsm_x2t(bl[nt], ba + BL_OFF);
            }
            const int ach  = (lane & 15);
            const int acol = ks * 32 + ((lane >> 4) << 4);
#pragma unroll
            for (int m = 0; m < 6; m++) {
                uint32_t ah[4], al[4];
                uint32_t aoff = SWZ((m * 16 + ach) * 128 + acol);
                ldsm_x4(ah, sb + WH_OFF + aoff);
                ldsm_x4(al, sb + WL_OFF + aoff);
#pragma unroll
                for (int nt = 0; nt < 2; nt++) {
                    mma_bf16(d[m][nt], ah, bh[nt]);
                    mma_bf16(d[m][nt], al, bh[nt]);
                    mma_bf16(d[m][nt], ah, bl[nt]);
                }
            }
        }
        __syncthreads();
    }
#undef LOADX

    // ---- epilogue: fragment -> g_y[ch][px], float2 stores ----
    const int gid = lane >> 2, tig = lane & 3;
    float* yn = g_y + (size_t)n * CH_ * HW_;
    const int pxb = p0 + wid * 16 + 2 * tig;
#pragma unroll
    for (int m = 0; m < 6; m++) {
#pragma unroll
        for (int nt = 0; nt < 2; nt++) {
            int px = pxb + nt * 8;
            int ch = m * 16 + gid;
            float2 v0; v0.x = d[m][nt][0]; v0.y = d[m][nt][1];
            float2 v1; v1.x = d[m][nt][2]; v1.y = d[m][nt][3];
            *(float2*)&yn[(size_t)ch * HW_ + px] = v0;
            *(float2*)&yn[(size_t)(ch + 8) * HW_ + px] = v1;
        }
    }
}

// -------------------------------------------------------------------------
// Kernel 2: fused attention (unchanged from round 9, 28.2us).
// -------------------------------------------------------------------------
__global__ __launch_bounds__(288, 4) void sam_attn_kernel(
    const float* __restrict__ convp,
    const float* __restrict__ w1c,
    const float* __restrict__ w2c,
    const float* __restrict__ g1, const float* __restrict__ b1,
    const float* __restrict__ m1, const float* __restrict__ v1,
    const float* __restrict__ g2, const float* __restrict__ b2,
    const float* __restrict__ m2, const float* __restrict__ v2,
    float* __restrict__ out) {
    __shared__ alignas(16) float sw1[16][20];
    __shared__ alignas(16) float sw2[8][16];
    __shared__ float scp[4];
    __shared__ float sbn[4][32];
    __shared__ float sx1[16][33];
    __shared__ float sc_s[32 * 73];

    const int t = threadIdx.x;
    if (t < 288) sw1[t / 18][t % 18] = w1c[t];
    if (t < 128) sw2[t / 16][t % 16] = w2c[t];
    if (t < 4)   scp[t] = convp[t];

    const int n   = blockIdx.y;
    const int hw0 = blockIdx.x * 32;
    const int pix = t & 31;
    const int jj  = t >> 5;
    const int hw  = hw0 + pix;
    const int h   = hw / W_;
    const int w   = hw % W_;

    const float* yn = g_y + (size_t)n * CH_ * HW_;

    // ---- Phase 0: BN affines + center x1 staging ----
    if (t < 32) {
        const int phw = hw0 + t;
        float s1 = g1[phw] * rsqrtf(v1[phw] + EPSBN);
        float s2 = g2[phw] * rsqrtf(v2[phw] + EPSBN);
        sbn[0][t] = s1;
        sbn[1][t] = b1[phw] - m1[phw] * s1;
        sbn[2][t] = s2;
        sbn[3][t] = b2[phw] - m2[phw] * s2;
    }
    if (t < 256) {
#pragma unroll
        for (int i = 0; i < 2; i++) {
            int idx = t + i * 256;
            int c = idx >> 5, p = idx & 31;
            sx1[c][p] = yn[(size_t)c * HW_ + hw0 + p];
        }
    }
    __syncthreads();

    // ---- Phase 1: logits for this (pix, jj) ----
    {
        const float s1 = sbn[0][pix], o1 = sbn[1][pix];
        const float s2 = sbn[2][pix], o2 = sbn[3][pix];

        int di = jj / 3 - 1, dj = jj % 3 - 1;
        int nh = h + di;
        nh = (nh < 0) ? -nh : ((nh >= H_) ? 2 * H_ - 2 - nh : nh);
        int nw = w + dj;
        nw = (nw < 0) ? -nw : ((nw >= W_) ? 2 * W_ - 2 - nw : nw);
        const int nhw = nh * W_ + nw;

        float a[18];
#pragma unroll
        for (int c = 0; c < 16; c++) {
            float r = sx1[c][pix] - yn[(size_t)(16 + c) * HW_ + nhw];
            a[c] = fmaxf(fmaf(r, s1, o1), 0.0f);
        }
        const float lw  = -1.0f + 2.0f * (float)w  / 55.0f;
        const float lh  = -1.0f + 2.0f * (float)h  / 55.0f;
        const float nlw = -1.0f + 2.0f * (float)nw / 55.0f;
        const float nlh = -1.0f + 2.0f * (float)nh / 55.0f;
        const float dp0 = scp[0] * (lw - nlw) + scp[1] * (lh - nlh);
        const float dp1 = scp[2] * (lw - nlw) + scp[3] * (lh - nlh);
        a[16] = fmaxf(fmaf(dp0, s1, o1), 0.0f);
        a[17] = fmaxf(fmaf(dp1, s1, o1), 0.0f);

        float hb[16];
#pragma unroll
        for (int o = 0; o < 16; o++) {
            const float4* wr = (const float4*)&sw1[o][0];
            float4 w0 = wr[0], w1v = wr[1], w2v = wr[2], w3v = wr[3];
            float tacc = 0.0f;
            tacc = fmaf(w0.x,  a[0],  tacc); tacc = fmaf(w0.y,  a[1],  tacc);
            tacc = fmaf(w0.z,  a[2],  tacc); tacc = fmaf(w0.w,  a[3],  tacc);
            tacc = fmaf(w1v.x, a[4],  tacc); tacc = fmaf(w1v.y, a[5],  tacc);
            tacc = fmaf(w1v.z, a[6],  tacc); tacc = fmaf(w1v.w, a[7],  tacc);
            tacc = fmaf(w2v.x, a[8],  tacc); tacc = fmaf(w2v.y, a[9],  tacc);
            tacc = fmaf(w2v.z, a[10], tacc); tacc = fmaf(w2v.w, a[11], tacc);
            tacc = fmaf(w3v.x, a[12], tacc); tacc = fmaf(w3v.y, a[13], tacc);
            tacc = fmaf(w3v.z, a[14], tacc); tacc = fmaf(w3v.w, a[15], tacc);
            tacc = fmaf(sw1[o][16], a[16], tacc);
            tacc = fmaf(sw1[o][17], a[17], tacc);
            hb[o] = fmaxf(fmaf(tacc, s2, o2), 0.0f);
        }
        float* dst = &sc_s[pix * 73 + jj * 8];
#pragma unroll
        for (int q = 0; q < 8; q++) {
            const float4* wr = (const float4*)&sw2[q][0];
            float4 w0 = wr[0], w1v = wr[1], w2v = wr[2], w3v = wr[3];
            float tacc = 0.0f;
            tacc = fmaf(w0.x,  hb[0],  tacc); tacc = fmaf(w0.y,  hb[1],  tacc);
            tacc = fmaf(w0.z,  hb[2],  tacc); tacc = fmaf(w0.w,  hb[3],  tacc);
            tacc = fmaf(w1v.x, hb[4],  tacc); tacc = fmaf(w1v.y, hb[5],  tacc);
            tacc = fmaf(w1v.z, hb[6],  tacc); tacc = fmaf(w1v.w, hb[7],  tacc);
            tacc = fmaf(w2v.x, hb[8],  tacc); tacc = fmaf(w2v.y, hb[9],  tacc);
            tacc = fmaf(w2v.z, hb[10], tacc); tacc = fmaf(w2v.w, hb[11], tacc);
            tacc = fmaf(w3v.x, hb[12], tacc); tacc = fmaf(w3v.y, hb[13], tacc);
            tacc = fmaf(w3v.z, hb[14], tacc); tacc = fmaf(w3v.w, hb[15], tacc);
            dst[q] = tacc;
        }
    }
    __syncthreads();

    // ---- Phase 2+3 fused: softmax (regs) + aggregation, thread=(q,pix) ----
    if (t < 256) {
        const int q = t >> 5;
        const float* base = &sc_s[pix * 73 + q];
        float v[9];
#pragma unroll
        for (int j = 0; j < 9; j++) v[j] = base[j * 8];
        float mx = v[0];
#pragma unroll
        for (int j = 1; j < 9; j++) mx = fmaxf(mx, v[j]);
        float sum = 0.0f;
#pragma unroll
        for (int j = 0; j < 9; j++) { v[j] = __expf(v[j] - mx); sum += v[j]; }
        float inv = 1.0f / sum;
#pragma unroll
        for (int j = 0; j < 9; j++) v[j] *= inv;

        int nhw9[9];
#pragma unroll
        for (int j = 0; j < 9; j++) {
            int nh = h + j / 3 - 1;
            nh = (nh < 0) ? -nh : ((nh >= H_) ? 2 * H_ - 2 - nh : nh);
            int nw = w + j % 3 - 1;
            nw = (nw < 0) ? -nw : ((nw >= W_) ? 2 * W_ - 2 - nw : nw);
            nhw9[j] = nh * W_ + nw;
        }
        const float* y3 = yn + (size_t)(32 + q) * HW_;
        float acc[8];
#pragma unroll
        for (int g = 0; g < 8; g++) acc[g] = 0.0f;
#pragma unroll
        for (int j = 0; j < 9; j++) {
            const int nhw = nhw9[j];
            const float wj = v[j];
#pragma unroll
            for (int g = 0; g < 8; g++)
                acc[g] = fmaf(wj, y3[(size_t)(g * 8) * HW_ + nhw], acc[g]);
        }
        float* on = out + (size_t)n * 64 * HW_ + hw;
#pragma unroll
        for (int g = 0; g < 8; g++)
            on[(size_t)(g * 8 + q) * HW_] = acc[g];
    }
}

// -------------------------------------------------------------------------
// Launcher.
// -------------------------------------------------------------------------
extern "C" void kernel_launch(void* const* d_in, const int* in_sizes, int n_in,
                              void* d_out, int out_size) {
    const float* x   = (const float*)d_in[0];
    const float* w1  = (const float*)d_in[1];
    const float* w2  = (const float*)d_in[2];
    const float* w3  = (const float*)d_in[3];
    const float* cp  = (const float*)d_in[4];
    const float* cw1 = (const float*)d_in[5];
    const float* cw2 = (const float*)d_in[6];
    const float* g1  = (const float*)d_in[7];
    const float* b1  = (const float*)d_in[8];
    const float* m1  = (const float*)d_in[9];
    const float* v1  = (const float*)d_in[10];
    const float* g2  = (const float*)d_in[11];
    const float* b2  = (const float*)d_in[12];
    const float* m2  = (const float*)d_in[13];
    const float* v2  = (const float*)d_in[14];
    float* out = (float*)d_out;

    cudaFuncSetAttribute(sam_gemm_mma,
                         cudaFuncAttributeMaxDynamicSharedMemorySize, SMEM_MMA);

    dim3 gg(25, N_);                  // 25 px tiles (last clamped) x 16 n
    sam_gemm_mma<<<gg, 256, SMEM_MMA>>>(x, w1, w2, w3);

    dim3 ga(HW_ / 32, N_);            // 98 x 16
    sam_attn_kernel<<<ga, 288>>>(cp, cw1, cw2,
                                 g1, b1, m1, v1,
                                 g2, b2, m2, v2, out);
}

// round 11
// speedup vs baseline: 3.3522x; 1.1136x over previous
#include <cuda_runtime.h>
#include <cuda_fp16.h>
#include <math.h>
#include <stdint.h>

#define H_ 56
#define W_ 56
#define HW_ 3136
#define N_ 16
#define C_ 256
#define CH_ 96
#define EPSBN 1e-3f

// Scratch: stacked GEMM output y[n][o][hw], o in [0,96):
//   rows 0..15 = x1, 16..31 = x2, 32..95 = x3
__device__ float g_y[N_ * CH_ * HW_];

// ---------------- helpers ----------------
__device__ __forceinline__ uint32_t smem_addr_u32(const void* p) {
    uint32_t a;
    asm("{ .reg .u64 t; cvta.to.shared.u64 t, %1; cvt.u32.u64 %0, t; }"
        : "=r"(a) : "l"(p));
    return a;
}

__device__ __forceinline__ void ldsm_x4(uint32_t* r, uint32_t addr) {
    asm volatile("ldmatrix.sync.aligned.m8n8.x4.shared.b16 {%0,%1,%2,%3}, [%4];"
                 : "=r"(r[0]), "=r"(r[1]), "=r"(r[2]), "=r"(r[3]) : "r"(addr));
}

__device__ __forceinline__ void ldsm_x2t(uint32_t* r, uint32_t addr) {
    asm volatile("ldmatrix.sync.aligned.m8n8.x2.trans.shared.b16 {%0,%1}, [%2];"
                 : "=r"(r[0]), "=r"(r[1]) : "r"(addr));
}

__device__ __forceinline__ void mma_fp16(float* d, const uint32_t* a,
                                         const uint32_t* b) {
    asm volatile(
        "mma.sync.aligned.m16n8k16.row.col.f32.f16.f16.f32 "
        "{%0,%1,%2,%3}, {%4,%5,%6,%7}, {%8,%9}, {%0,%1,%2,%3};"
        : "+f"(d[0]), "+f"(d[1]), "+f"(d[2]), "+f"(d[3])
        : "r"(a[0]), "r"(a[1]), "r"(a[2]), "r"(a[3]), "r"(b[0]), "r"(b[1]));
}

// packed f32x2 FMA and pack/dup/unpack helpers
__device__ __forceinline__ void fma2(unsigned long long& acc,
                                     unsigned long long a,
                                     unsigned long long b) {
    asm("fma.rn.f32x2 %0, %1, %2, %0;" : "+l"(acc) : "l"(a), "l"(b));
}
__device__ __forceinline__ unsigned long long dup2(float w) {
    unsigned long long r;
    asm("mov.b64 %0, {%1, %1};" : "=l"(r) : "f"(w));
    return r;
}
__device__ __forceinline__ unsigned long long pack2(float lo, float hi) {
    unsigned long long r;
    asm("mov.b64 %0, {%1, %2};" : "=l"(r) : "f"(lo), "f"(hi));
    return r;
}
__device__ __forceinline__ void unpack2(unsigned long long v, float& lo, float& hi) {
    asm("mov.b64 {%0, %1}, %2;" : "=f"(lo), "=f"(hi) : "l"(v));
}

// SW128 swizzle for 128B rows (16B granular)
#define SWZ(o) ((o) ^ (((o) >> 3) & 0x70))
// X-tile swizzle: rows of 256B (128 px fp16); XOR 16B-chunk index by k&7
#define XSWZ(k, pxb) ((k) * 256 + ((pxb) ^ (((k) & 7) << 4)))

// smem layout (bytes), dynamic
#define XH_OFF 0        // X hi  [64 k][128 px] fp16, 256B rows = 16384
#define XL_OFF 16384    // X lo
#define WF_OFF 32768    // W     [96 ch][64 k]  fp16, SW128     = 12288
#define SMEM_MMA 45056

// -------------------------------------------------------------------------
// Kernel 1: 2-term fp16 GEMM via mma.sync.
// D[ch=96, px=128] = W[96,256] @ X[256, px]  =  Wf16 @ Xh + Wf16 @ Xl
// (X split to fp16 hi/lo -> X exact to ~2^-22; error = W fp16 rounding
//  ~2^-12/sqrt(3) ~ 1.4e-4 norm-relative, well under 1e-3.)
// __launch_bounds__(256,2): 2 blocks/SM for cross-block latency hiding.
// -------------------------------------------------------------------------
__global__ __launch_bounds__(256, 2) void sam_gemm_mma(
    const float* __restrict__ x,
    const float* __restrict__ w1,
    const float* __restrict__ w2,
    const float* __restrict__ w3) {
    extern __shared__ __align__(1024) char smem[];
    const int tid  = threadIdx.x;
    const int wid  = tid >> 5;
    const int lane = tid & 31;
    const int n    = blockIdx.y;
    int p0 = blockIdx.x * 128;
    if (p0 > HW_ - 128) p0 = HW_ - 128;   // overlap tile: identical dup writes

    const uint32_t sb = smem_addr_u32(smem);
    const float* xn = x + (size_t)n * C_ * HW_ + p0;

    float d[6][2][4];
#pragma unroll
    for (int m = 0; m < 6; m++)
#pragma unroll
        for (int nt = 0; nt < 2; nt++)
#pragma unroll
            for (int r = 0; r < 4; r++) d[m][nt][r] = 0.0f;

    const int xk = tid >> 5, xp4 = (tid & 31) * 4;  // X load coords
    const float* wrow_[3];
    int wq_[3];
#pragma unroll
    for (int i = 0; i < 3; i++) {
        int j = tid + i * 256;
        int o = j >> 3;
        wq_[i] = j & 7;
        wrow_[i] = (o < 16) ? (w1 + o * C_)
                 : (o < 32) ? (w2 + (o - 16) * C_)
                            : (w3 + (o - 32) * C_);
    }

    float4 Xr[8];        // X prefetch regs

#define LOADX(kb)                                                              \
    _Pragma("unroll")                                                          \
    for (int i = 0; i < 8; i++)                                                \
        Xr[i] = *(const float4*)(xn + (size_t)((kb) + xk + i * 8) * HW_ + xp4)

    LOADX(0);

    for (int c = 0; c < 4; c++) {
        const int kb = c * 64;

        // ---- W: synchronous LDG (L2-hot) -> fp16 swizzled STS ----
#pragma unroll
        for (int i = 0; i < 3; i++) {
            int j = tid + i * 256;
            int o = j >> 3, q = j & 7;
            float4 va = *(const float4*)(wrow_[i] + kb + wq_[i] * 8);
            float4 vb = *(const float4*)(wrow_[i] + kb + wq_[i] * 8 + 4);
            __half2 h0 = __floats2half2_rn(va.x, va.y);
            __half2 h1 = __floats2half2_rn(va.z, va.w);
            __half2 h2 = __floats2half2_rn(vb.x, vb.y);
            __half2 h3 = __floats2half2_rn(vb.z, vb.w);
            int off = SWZ(o * 128 + q * 16);
            uint4 hv; hv.x = *(uint32_t*)&h0; hv.y = *(uint32_t*)&h1;
                      hv.z = *(uint32_t*)&h2; hv.w = *(uint32_t*)&h3;
            *(uint4*)(smem + WF_OFF + off) = hv;
        }

        // ---- X: convert prefetched regs -> fp16 hi/lo swizzled STS ----
#pragma unroll
        for (int i = 0; i < 8; i++) {
            int k = xk + i * 8;
            float4 v = Xr[i];
            __half2 h0 = __floats2half2_rn(v.x, v.y);
            __half2 h1 = __floats2half2_rn(v.z, v.w);
            float2 f0 = __half22float2(h0);
            float2 f1 = __half22float2(h1);
            __half2 l0 = __floats2half2_rn(v.x - f0.x, v.y - f0.y);
            __half2 l1 = __floats2half2_rn(v.z - f1.x, v.w - f1.y);
            int off = XSWZ(k, xp4 * 2);
            uint2 hw_; hw_.x = *(uint32_t*)&h0; hw_.y = *(uint32_t*)&h1;
            uint2 lw_; lw_.x = *(uint32_t*)&l0; lw_.y = *(uint32_t*)&l1;
            *(uint2*)(smem + XH_OFF + off) = hw_;
            *(uint2*)(smem + XL_OFF + off) = lw_;
        }
        __syncthreads();

        // ---- prefetch next X chunk (LDG drains under MMA loop) ----
        if (c < 3) LOADX(kb + 64);

        // ---- compute: 4 k16 steps ----
#pragma unroll
        for (int ks = 0; ks < 4; ks++) {
            uint32_t bh[2][2], bl[2][2];
            const int bk = ks * 16 + (lane & 15);
#pragma unroll
            for (int nt = 0; nt < 2; nt++) {
                int pxb = wid * 32 + nt * 16;
                uint32_t ba = sb + XSWZ(bk, pxb);
                ldsm_x2t(bh[nt], ba + XH_OFF);
                ldsm_x2t(bl[nt], ba + XL_OFF);
            }
            const int ach  = (lane & 15);
            const int acol = ks * 32 + ((lane >> 4) << 4);
#pragma unroll
            for (int m = 0; m < 6; m++) {
                uint32_t wf[4];
                ldsm_x4(wf, sb + WF_OFF + SWZ((m * 16 + ach) * 128 + acol));
#pragma unroll
                for (int nt = 0; nt < 2; nt++) {
                    mma_fp16(d[m][nt], wf, bh[nt]);
                    mma_fp16(d[m][nt], wf, bl[nt]);
                }
            }
        }
        __syncthreads();
    }
#undef LOADX

    // ---- epilogue: fragment -> g_y[ch][px], float2 stores ----
    const int gid = lane >> 2, tig = lane & 3;
    float* yn = g_y + (size_t)n * CH_ * HW_;
    const int pxb = p0 + wid * 16 + 2 * tig;
#pragma unroll
    for (int m = 0; m < 6; m++) {
#pragma unroll
        for (int nt = 0; nt < 2; nt++) {
            int px = pxb + nt * 8;
            int ch = m * 16 + gid;
            float2 v0; v0.x = d[m][nt][0]; v0.y = d[m][nt][1];
            float2 v1; v1.x = d[m][nt][2]; v1.y = d[m][nt][3];
            *(float2*)&yn[(size_t)ch * HW_ + px] = v0;
            *(float2*)&yn[(size_t)(ch + 8) * HW_ + px] = v1;
        }
    }
}

// -------------------------------------------------------------------------
// Kernel 2: fused attention with f32x2-packed matvecs.
//   P0: stage BN affines + center x1 + packed weight pairs
//   P1 (t=(jj,pix)): rel -> bn1/relu -> W1 (packed) -> bn2/relu -> W2 (packed)
//   P2+3 fused (t=(q,pix)): softmax in regs + aggregation
// -------------------------------------------------------------------------
__global__ __launch_bounds__(288, 4) void sam_attn_kernel(
    const float* __restrict__ convp,
    const float* __restrict__ w1c,
    const float* __restrict__ w2c,
    const float* __restrict__ g1, const float* __restrict__ b1,
    const float* __restrict__ m1, const float* __restrict__ v1,
    const float* __restrict__ g2, const float* __restrict__ b2,
    const float* __restrict__ m2, const float* __restrict__ v2,
    float* __restrict__ out) {
    __shared__ alignas(16) unsigned long long sw1p[18][8];  // [c][o-pair]
    __shared__ alignas(16) unsigned long long sw2p[16][4];  // [o][q-pair]
    __shared__ float scp[4];
    __shared__ float sbn[4][32];
    __shared__ float sx1[16][33];
    __shared__ float sc_s[32 * 74];   // [pix][q + 8*jj], stride 74 (8B-aligned)

    const int t = threadIdx.x;
    if (t < 144) {
        int o2 = t & 7, c = t >> 3;
        sw1p[c][o2] = pack2(w1c[(2 * o2) * 18 + c], w1c[(2 * o2 + 1) * 18 + c]);
    }
    if (t < 64) {
        int o = t >> 2, q2 = t & 3;
        sw2p[o][q2] = pack2(w2c[(2 * q2) * 16 + o], w2c[(2 * q2 + 1) * 16 + o]);
    }
    if (t < 4) scp[t] = convp[t];

    const int n   = blockIdx.y;
    const int hw0 = blockIdx.x * 32;
    const int pix = t & 31;
    const int jj  = t >> 5;
    const int hw  = hw0 + pix;
    const int h   = hw / W_;
    const int w   = hw % W_;

    const float* yn = g_y + (size_t)n * CH_ * HW_;

    // ---- Phase 0: BN affines + center x1 staging ----
    if (t < 32) {
        const int phw = hw0 + t;
        float s1 = g1[phw] * rsqrtf(v1[phw] + EPSBN);
        float s2 = g2[phw] * rsqrtf(v2[phw] + EPSBN);
        sbn[0][t] = s1;
        sbn[1][t] = b1[phw] - m1[phw] * s1;
        sbn[2][t] = s2;
        sbn[3][t] = b2[phw] - m2[phw] * s2;
    }
    if (t < 256) {
#pragma unroll
        for (int i = 0; i < 2; i++) {
            int idx = t + i * 256;
            int c = idx >> 5, p = idx & 31;
            sx1[c][p] = yn[(size_t)c * HW_ + hw0 + p];
        }
    }
    __syncthreads();

    // ---- Phase 1: logits for this (pix, jj) ----
    {
        const float s1 = sbn[0][pix], o1 = sbn[1][pix];
        const float s2 = sbn[2][pix], o2b = sbn[3][pix];

        int di = jj / 3 - 1, dj = jj % 3 - 1;
        int nh = h + di;
        nh = (nh < 0) ? -nh : ((nh >= H_) ? 2 * H_ - 2 - nh : nh);
        int nw = w + dj;
        nw = (nw < 0) ? -nw : ((nw >= W_) ? 2 * W_ - 2 - nw : nw);
        const int nhw = nh * W_ + nw;

        float a[18];
#pragma unroll
        for (int c = 0; c < 16; c++) {
            float r = sx1[c][pix] - yn[(size_t)(16 + c) * HW_ + nhw];
            a[c] = fmaxf(fmaf(r, s1, o1), 0.0f);
        }
        const float lw  = -1.0f + 2.0f * (float)w  / 55.0f;
        const float lh  = -1.0f + 2.0f * (float)h  / 55.0f;
        const float nlw = -1.0f + 2.0f * (float)nw / 55.0f;
        const float nlh = -1.0f + 2.0f * (float)nh / 55.0f;
        const float dp0 = scp[0] * (lw - nlw) + scp[1] * (lh - nlh);
        const float dp1 = scp[2] * (lw - nlw) + scp[3] * (lh - nlh);
        a[16] = fmaxf(fmaf(dp0, s1, o1), 0.0f);
        a[17] = fmaxf(fmaf(dp1, s1, o1), 0.0f);

        // matvec1 packed: hb2[o2] = (hb[2o2], hb[2o2+1])
        unsigned long long hb2[8];
#pragma unroll
        for (int o2 = 0; o2 < 8; o2++) hb2[o2] = 0ull;
#pragma unroll
        for (int c = 0; c < 18; c++) {
            unsigned long long ad = dup2(a[c]);
            ulonglong2 p0 = *(const ulonglong2*)&sw1p[c][0];
            ulonglong2 p1 = *(const ulonglong2*)&sw1p[c][2];
            ulonglong2 p2 = *(const ulonglong2*)&sw1p[c][4];
            ulonglong2 p3 = *(const ulonglong2*)&sw1p[c][6];
            fma2(hb2[0], p0.x, ad); fma2(hb2[1], p0.y, ad);
            fma2(hb2[2], p1.x, ad); fma2(hb2[3], p1.y, ad);
            fma2(hb2[4], p2.x, ad); fma2(hb2[5], p2.y, ad);
            fma2(hb2[6], p3.x, ad); fma2(hb2[7], p3.y, ad);
        }
        float hb[16];
#pragma unroll
        for (int o2 = 0; o2 < 8; o2++) {
            float lo, hi;
            unpack2(hb2[o2], lo, hi);
            hb[2 * o2]     = fmaxf(fmaf(lo, s2, o2b), 0.0f);
            hb[2 * o2 + 1] = fmaxf(fmaf(hi, s2, o2b), 0.0f);
        }

        // matvec2 packed: sc2[q2] = (sc[2q2], sc[2q2+1])
        unsigned long long sc2[4];
#pragma unroll
        for (int q2 = 0; q2 < 4; q2++) sc2[q2] = 0ull;
#pragma unroll
        for (int o = 0; o < 16; o++) {
            unsigned long long ad = dup2(hb[o]);
            ulonglong2 q0 = *(const ulonglong2*)&sw2p[o][0];
            ulonglong2 q1 = *(const ulonglong2*)&sw2p[o][2];
            fma2(sc2[0], q0.x, ad); fma2(sc2[1], q0.y, ad);
            fma2(sc2[2], q1.x, ad); fma2(sc2[3], q1.y, ad);
        }
        float* dst = &sc_s[pix * 74 + jj * 8];
        *(unsigned long long*)&dst[0] = sc2[0];
        *(unsigned long long*)&dst[2] = sc2[1];
        *(unsigned long long*)&dst[4] = sc2[2];
        *(unsigned long long*)&dst[6] = sc2[3];
    }
    __syncthreads();

    // ---- Phase 2+3 fused: softmax (regs) + aggregation, thread=(q,pix) ----
    if (t < 256) {
        const int q = t >> 5;
        const float* base = &sc_s[pix * 74 + q];
        float v[9];
#pragma unroll
        for (int j = 0; j < 9; j++) v[j] = base[j * 8];
        float mx = v[0];
#pragma unroll
        for (int j = 1; j < 9; j++) mx = fmaxf(mx, v[j]);
        float sum = 0.0f;
#pragma unroll
        for (int j = 0; j < 9; j++) { v[j] = __expf(v[j] - mx); sum += v[j]; }
        float inv = 1.0f / sum;
#pragma unroll
        for (int j = 0; j < 9; j++) v[j] *= inv;

        int nhw9[9];
#pragma unroll
        for (int j = 0; j < 9; j++) {
            int nh = h + j / 3 - 1;
            nh = (nh < 0) ? -nh : ((nh >= H_) ? 2 * H_ - 2 - nh : nh);
            int nw = w + j % 3 - 1;
            nw = (nw < 0) ? -nw : ((nw >= W_) ? 2 * W_ - 2 - nw : nw);
            nhw9[j] = nh * W_ + nw;
        }
        const float* y3 = yn + (size_t)(32 + q) * HW_;
        float acc[8];
#pragma unroll
        for (int g = 0; g < 8; g++) acc[g] = 0.0f;
#pragma unroll
        for (int j = 0; j < 9; j++) {
            const int nhw = nhw9[j];
            const float wj = v[j];
#pragma unroll
            for (int g = 0; g < 8; g++)
                acc[g] = fmaf(wj, y3[(size_t)(g * 8) * HW_ + nhw], acc[g]);
        }
        float* on = out + (size_t)n * 64 * HW_ + hw;
#pragma unroll
        for (int g = 0; g < 8; g++)
            on[(size_t)(g * 8 + q) * HW_] = acc[g];
    }
}

// -------------------------------------------------------------------------
// Launcher.
// -------------------------------------------------------------------------
extern "C" void kernel_launch(void* const* d_in, const int* in_sizes, int n_in,
                              void* d_out, int out_size) {
    const float* x   = (const float*)d_in[0];
    const float* w1  = (const float*)d_in[1];
    const float* w2  = (const float*)d_in[2];
    const float* w3  = (const float*)d_in[3];
    const float* cp  = (const float*)d_in[4];
    const float* cw1 = (const float*)d_in[5];
    const float* cw2 = (const float*)d_in[6];
    const float* g1  = (const float*)d_in[7];
    const float* b1  = (const float*)d_in[8];
    const float* m1  = (const float*)d_in[9];
    const float* v1  = (const float*)d_in[10];
    const float* g2  = (const float*)d_in[11];
    const float* b2  = (const float*)d_in[12];
    const float* m2  = (const float*)d_in[13];
    const float* v2  = (const float*)d_in[14];
    float* out = (float*)d_out;

    cudaFuncSetAttribute(sam_gemm_mma,
                         cudaFuncAttributeMaxDynamicSharedMemorySize, SMEM_MMA);

    dim3 gg(25, N_);                  // 25 px tiles (last clamped) x 16 n
    sam_gemm_mma<<<gg, 256, SMEM_MMA>>>(x, w1, w2, w3);

    dim3 ga(HW_ / 32, N_);            // 98 x 16
    sam_attn_kernel<<<ga, 288>>>(cp, cw1, cw2,
                                 g1, b1, m1, v1,
                                 g2, b2, m2, v2, out);
}

// round 12
// speedup vs baseline: 3.4892x; 1.0409x over previous
#include <cuda_runtime.h>
#include <cuda_fp16.h>
#include <math.h>
#include <stdint.h>

#define H_ 56
#define W_ 56
#define HW_ 3136
#define N_ 16
#define C_ 256
#define CH_ 96
#define EPSBN 1e-3f

// Scratch: GEMM outputs.
// g_y  (channel-major): rows 0..15 = x1, 32..95 = x3  (row 16..31 unused)
// g_y2 (pixel-major):   x2 as [n][hw][16]
__device__ float g_y[N_ * CH_ * HW_];
__device__ float g_y2[N_ * HW_ * 16];

// ---------------- helpers ----------------
__device__ __forceinline__ uint32_t smem_addr_u32(const void* p) {
    uint32_t a;
    asm("{ .reg .u64 t; cvta.to.shared.u64 t, %1; cvt.u32.u64 %0, t; }"
        : "=r"(a) : "l"(p));
    return a;
}

__device__ __forceinline__ void ldsm_x4(uint32_t* r, uint32_t addr) {
    asm volatile("ldmatrix.sync.aligned.m8n8.x4.shared.b16 {%0,%1,%2,%3}, [%4];"
                 : "=r"(r[0]), "=r"(r[1]), "=r"(r[2]), "=r"(r[3]) : "r"(addr));
}

__device__ __forceinline__ void ldsm_x2t(uint32_t* r, uint32_t addr) {
    asm volatile("ldmatrix.sync.aligned.m8n8.x2.trans.shared.b16 {%0,%1}, [%2];"
                 : "=r"(r[0]), "=r"(r[1]) : "r"(addr));
}

__device__ __forceinline__ void mma_fp16(float* d, const uint32_t* a,
                                         const uint32_t* b) {
    asm volatile(
        "mma.sync.aligned.m16n8k16.row.col.f32.f16.f16.f32 "
        "{%0,%1,%2,%3}, {%4,%5,%6,%7}, {%8,%9}, {%0,%1,%2,%3};"
        : "+f"(d[0]), "+f"(d[1]), "+f"(d[2]), "+f"(d[3])
        : "r"(a[0]), "r"(a[1]), "r"(a[2]), "r"(a[3]), "r"(b[0]), "r"(b[1]));
}

// packed f32x2 FMA and pack/dup/unpack helpers
__device__ __forceinline__ void fma2(unsigned long long& acc,
                                     unsigned long long a,
                                     unsigned long long b) {
    asm("fma.rn.f32x2 %0, %1, %2, %0;" : "+l"(acc) : "l"(a), "l"(b));
}
__device__ __forceinline__ unsigned long long dup2(float w) {
    unsigned long long r;
    asm("mov.b64 %0, {%1, %1};" : "=l"(r) : "f"(w));
    return r;
}
__device__ __forceinline__ unsigned long long pack2(float lo, float hi) {
    unsigned long long r;
    asm("mov.b64 %0, {%1, %2};" : "=l"(r) : "f"(lo), "f"(hi));
    return r;
}
__device__ __forceinline__ void unpack2(unsigned long long v, float& lo, float& hi) {
    asm("mov.b64 {%0, %1}, %2;" : "=f"(lo), "=f"(hi) : "l"(v));
}

// SW128 swizzle for 128B rows (16B granular)
#define SWZ(o) ((o) ^ (((o) >> 3) & 0x70))
// X-tile swizzle: rows of 256B (128 px fp16); XOR 16B-chunk index by k&7
#define XSWZ(k, pxb) ((k) * 256 + ((pxb) ^ (((k) & 7) << 4)))

// smem layout (bytes), dynamic
#define XF_OFF 0        // X  [64 k][128 px] fp16, 256B rows = 16384
#define WF_OFF 16384    // W  [96 ch][64 k]  fp16, SW128     = 12288
#define SMEM_MMA 28672

// -------------------------------------------------------------------------
// Kernel 1: single-term fp16 GEMM via mma.sync.
// D[ch=96, px=128] = Wf16[96,256] @ Xf16[256, px]
// (both fp16 RN; combined rounding ~3e-4 norm-relative, < 1e-3 budget)
// x2 channels written PIXEL-MAJOR to g_y2 for the attention gather.
// -------------------------------------------------------------------------
__global__ __launch_bounds__(256, 2) void sam_gemm_mma(
    const float* __restrict__ x,
    const float* __restrict__ w1,
    const float* __restrict__ w2,
    const float* __restrict__ w3) {
    extern __shared__ __align__(1024) char smem[];
    const int tid  = threadIdx.x;
    const int wid  = tid >> 5;
    const int lane = tid & 31;
    const int n    = blockIdx.y;
    int p0 = blockIdx.x * 128;
    if (p0 > HW_ - 128) p0 = HW_ - 128;   // overlap tile: identical dup writes

    const uint32_t sb = smem_addr_u32(smem);
    const float* xn = x + (size_t)n * C_ * HW_ + p0;

    float d[6][2][4];
#pragma unroll
    for (int m = 0; m < 6; m++)
#pragma unroll
        for (int nt = 0; nt < 2; nt++)
#pragma unroll
            for (int r = 0; r < 4; r++) d[m][nt][r] = 0.0f;

    const int xk = tid >> 5, xp4 = (tid & 31) * 4;  // X load coords
    const float* wrow_[3];
    int wq_[3];
#pragma unroll
    for (int i = 0; i < 3; i++) {
        int j = tid + i * 256;
        int o = j >> 3;
        wq_[i] = j & 7;
        wrow_[i] = (o < 16) ? (w1 + o * C_)
                 : (o < 32) ? (w2 + (o - 16) * C_)
                            : (w3 + (o - 32) * C_);
    }

    float4 Xr[8];        // X prefetch regs

#define LOADX(kb)                                                              \
    _Pragma("unroll")                                                          \
    for (int i = 0; i < 8; i++)                                                \
        Xr[i] = *(const float4*)(xn + (size_t)((kb) + xk + i * 8) * HW_ + xp4)

    LOADX(0);

    for (int c = 0; c < 4; c++) {
        const int kb = c * 64;

        // ---- W: synchronous LDG (L2-hot) -> fp16 swizzled STS ----
#pragma unroll
        for (int i = 0; i < 3; i++) {
            int j = tid + i * 256;
            int o = j >> 3, q = j & 7;
            float4 va = *(const float4*)(wrow_[i] + kb + wq_[i] * 8);
            float4 vb = *(const float4*)(wrow_[i] + kb + wq_[i] * 8 + 4);
            __half2 h0 = __floats2half2_rn(va.x, va.y);
            __half2 h1 = __floats2half2_rn(va.z, va.w);
            __half2 h2 = __floats2half2_rn(vb.x, vb.y);
            __half2 h3 = __floats2half2_rn(vb.z, vb.w);
            int off = SWZ(o * 128 + q * 16);
            uint4 hv; hv.x = *(uint32_t*)&h0; hv.y = *(uint32_t*)&h1;
                      hv.z = *(uint32_t*)&h2; hv.w = *(uint32_t*)&h3;
            *(uint4*)(smem + WF_OFF + off) = hv;
        }

        // ---- X: convert prefetched regs -> fp16 swizzled STS ----
#pragma unroll
        for (int i = 0; i < 8; i++) {
            int k = xk + i * 8;
            float4 v = Xr[i];
            __half2 h0 = __floats2half2_rn(v.x, v.y);
            __half2 h1 = __floats2half2_rn(v.z, v.w);
            int off = XSWZ(k, xp4 * 2);
            uint2 hw_; hw_.x = *(uint32_t*)&h0; hw_.y = *(uint32_t*)&h1;
            *(uint2*)(smem + XF_OFF + off) = hw_;
        }
        __syncthreads();

        // ---- prefetch next X chunk (LDG drains under MMA loop) ----
        if (c < 3) LOADX(kb + 64);

        // ---- compute: 4 k16 steps ----
#pragma unroll
        for (int ks = 0; ks < 4; ks++) {
            uint32_t bx[2][2];
            const int bk = ks * 16 + (lane & 15);
#pragma unroll
            for (int nt = 0; nt < 2; nt++) {
                int pxb = wid * 32 + nt * 16;
                ldsm_x2t(bx[nt], sb + XF_OFF + XSWZ(bk, pxb));
            }
            const int ach  = (lane & 15);
            const int acol = ks * 32 + ((lane >> 4) << 4);
#pragma unroll
            for (int m = 0; m < 6; m++) {
                uint32_t wf[4];
                ldsm_x4(wf, sb + WF_OFF + SWZ((m * 16 + ach) * 128 + acol));
#pragma unroll
                for (int nt = 0; nt < 2; nt++)
                    mma_fp16(d[m][nt], wf, bx[nt]);
            }
        }
        __syncthreads();
    }
#undef LOADX

    // ---- epilogue ----
    const int gid = lane >> 2, tig = lane & 3;
    float* yn = g_y + (size_t)n * CH_ * HW_;
    float* y2 = g_y2 + (size_t)n * HW_ * 16;
    const int pxb = p0 + wid * 16 + 2 * tig;
#pragma unroll
    for (int m = 0; m < 6; m++) {
#pragma unroll
        for (int nt = 0; nt < 2; nt++) {
            int px = pxb + nt * 8;
            if (m == 1) {
                // x2: pixel-major scatter [px][ch]
                y2[(size_t)px * 16 + gid]           = d[m][nt][0];
                y2[(size_t)(px + 1) * 16 + gid]     = d[m][nt][1];
                y2[(size_t)px * 16 + gid + 8]       = d[m][nt][2];
                y2[(size_t)(px + 1) * 16 + gid + 8] = d[m][nt][3];
            } else {
                int ch = m * 16 + gid;
                float2 v0; v0.x = d[m][nt][0]; v0.y = d[m][nt][1];
                float2 v1; v1.x = d[m][nt][2]; v1.y = d[m][nt][3];
                *(float2*)&yn[(size_t)ch * HW_ + px] = v0;
                *(float2*)&yn[(size_t)(ch + 8) * HW_ + px] = v1;
            }
        }
    }
}

// -------------------------------------------------------------------------
// Kernel 2: fused attention with f32x2-packed matvecs; x2 gathered as
// 4x LDG.128 from the pixel-major g_y2 layout.
// -------------------------------------------------------------------------
__global__ __launch_bounds__(288, 4) void sam_attn_kernel(
    const float* __restrict__ convp,
    const float* __restrict__ w1c,
    const float* __restrict__ w2c,
    const float* __restrict__ g1, const float* __restrict__ b1,
    const float* __restrict__ m1, const float* __restrict__ v1,
    const float* __restrict__ g2, const float* __restrict__ b2,
    const float* __restrict__ m2, const float* __restrict__ v2,
    float* __restrict__ out) {
    __shared__ alignas(16) unsigned long long sw1p[18][8];  // [c][o-pair]
    __shared__ alignas(16) unsigned long long sw2p[16][4];  // [o][q-pair]
    __shared__ float scp[4];
    __shared__ float sbn[4][32];
    __shared__ float sx1[16][33];
    __shared__ float sc_s[32 * 74];   // [pix][q + 8*jj], stride 74 (8B-aligned)

    const int t = threadIdx.x;
    if (t < 144) {
        int o2 = t & 7, c = t >> 3;
        sw1p[c][o2] = pack2(w1c[(2 * o2) * 18 + c], w1c[(2 * o2 + 1) * 18 + c]);
    }
    if (t < 64) {
        int o = t >> 2, q2 = t & 3;
        sw2p[o][q2] = pack2(w2c[(2 * q2) * 16 + o], w2c[(2 * q2 + 1) * 16 + o]);
    }
    if (t < 4) scp[t] = convp[t];

    const int n   = blockIdx.y;
    const int hw0 = blockIdx.x * 32;
    const int pix = t & 31;
    const int jj  = t >> 5;
    const int hw  = hw0 + pix;
    const int h   = hw / W_;
    const int w   = hw % W_;

    const float* yn = g_y + (size_t)n * CH_ * HW_;
    const float* y2 = g_y2 + (size_t)n * HW_ * 16;

    // ---- Phase 0: BN affines + center x1 staging ----
    if (t < 32) {
        const int phw = hw0 + t;
        float s1 = g1[phw] * rsqrtf(v1[phw] + EPSBN);
        float s2 = g2[phw] * rsqrtf(v2[phw] + EPSBN);
        sbn[0][t] = s1;
        sbn[1][t] = b1[phw] - m1[phw] * s1;
        sbn[2][t] = s2;
        sbn[3][t] = b2[phw] - m2[phw] * s2;
    }
    if (t < 256) {
#pragma unroll
        for (int i = 0; i < 2; i++) {
            int idx = t + i * 256;
            int c = idx >> 5, p = idx & 31;
            sx1[c][p] = yn[(size_t)c * HW_ + hw0 + p];
        }
    }
    __syncthreads();

    // ---- Phase 1: logits for this (pix, jj) ----
    {
        const float s1 = sbn[0][pix], o1 = sbn[1][pix];
        const float s2 = sbn[2][pix], o2b = sbn[3][pix];

        int di = jj / 3 - 1, dj = jj % 3 - 1;
        int nh = h + di;
        nh = (nh < 0) ? -nh : ((nh >= H_) ? 2 * H_ - 2 - nh : nh);
        int nw = w + dj;
        nw = (nw < 0) ? -nw : ((nw >= W_) ? 2 * W_ - 2 - nw : nw);
        const int nhw = nh * W_ + nw;

        // x2 neighbor: 4 contiguous LDG.128 from px-major layout
        const float4* x2v = (const float4*)(y2 + (size_t)nhw * 16);
        float4 f0 = x2v[0], f1 = x2v[1], f2 = x2v[2], f3 = x2v[3];
        float xv[16] = {f0.x, f0.y, f0.z, f0.w, f1.x, f1.y, f1.z, f1.w,
                        f2.x, f2.y, f2.z, f2.w, f3.x, f3.y, f3.z, f3.w};

        float a[18];
#pragma unroll
        for (int c = 0; c < 16; c++) {
            float r = sx1[c][pix] - xv[c];
            a[c] = fmaxf(fmaf(r, s1, o1), 0.0f);
        }
        const float lw  = -1.0f + 2.0f * (float)w  / 55.0f;
        const float lh  = -1.0f + 2.0f * (float)h  / 55.0f;
        const float nlw = -1.0f + 2.0f * (float)nw / 55.0f;
        const float nlh = -1.0f + 2.0f * (float)nh / 55.0f;
        const float dp0 = scp[0] * (lw - nlw) + scp[1] * (lh - nlh);
        const float dp1 = scp[2] * (lw - nlw) + scp[3] * (lh - nlh);
        a[16] = fmaxf(fmaf(dp0, s1, o1), 0.0f);
        a[17] = fmaxf(fmaf(dp1, s1, o1), 0.0f);

        // matvec1 packed: hb2[o2] = (hb[2o2], hb[2o2+1])
        unsigned long long hb2[8];
#pragma unroll
        for (int o2 = 0; o2 < 8; o2++) hb2[o2] = 0ull;
#pragma unroll
        for (int c = 0; c < 18; c++) {
            unsigned long long ad = dup2(a[c]);
            ulonglong2 p0 = *(const ulonglong2*)&sw1p[c][0];
            ulonglong2 p1 = *(const ulonglong2*)&sw1p[c][2];
            ulonglong2 p2 = *(const ulonglong2*)&sw1p[c][4];
            ulonglong2 p3 = *(const ulonglong2*)&sw1p[c][6];
            fma2(hb2[0], p0.x, ad); fma2(hb2[1], p0.y, ad);
            fma2(hb2[2], p1.x, ad); fma2(hb2[3], p1.y, ad);
            fma2(hb2[4], p2.x, ad); fma2(hb2[5], p2.y, ad);
            fma2(hb2[6], p3.x, ad); fma2(hb2[7], p3.y, ad);
        }
        float hb[16];
#pragma unroll
        for (int o2 = 0; o2 < 8; o2++) {
            float lo, hi;
            unpack2(hb2[o2], lo, hi);
            hb[2 * o2]     = fmaxf(fmaf(lo, s2, o2b), 0.0f);
            hb[2 * o2 + 1] = fmaxf(fmaf(hi, s2, o2b), 0.0f);
        }

        // matvec2 packed
        unsigned long long sc2[4];
#pragma unroll
        for (int q2 = 0; q2 < 4; q2++) sc2[q2] = 0ull;
#pragma unroll
        for (int o = 0; o < 16; o++) {
            unsigned long long ad = dup2(hb[o]);
            ulonglong2 q0 = *(const ulonglong2*)&sw2p[o][0];
            ulonglong2 q1 = *(const ulonglong2*)&sw2p[o][2];
            fma2(sc2[0], q0.x, ad); fma2(sc2[1], q0.y, ad);
            fma2(sc2[2], q1.x, ad); fma2(sc2[3], q1.y, ad);
        }
        float* dst = &sc_s[pix * 74 + jj * 8];
        *(unsigned long long*)&dst[0] = sc2[0];
        *(unsigned long long*)&dst[2] = sc2[1];
        *(unsigned long long*)&dst[4] = sc2[2];
        *(unsigned long long*)&dst[6] = sc2[3];
    }
    __syncthreads();

    // ---- Phase 2+3 fused: softmax (regs) + aggregation, thread=(q,pix) ----
    if (t < 256) {
        const int q = t >> 5;
        const float* base = &sc_s[pix * 74 + q];
        float v[9];
#pragma unroll
        for (int j = 0; j < 9; j++) v[j] = base[j * 8];
        float mx = v[0];
#pragma unroll
        for (int j = 1; j < 9; j++) mx = fmaxf(mx, v[j]);
        float sum = 0.0f;
#pragma unroll
        for (int j = 0; j < 9; j++) { v[j] = __expf(v[j] - mx); sum += v[j]; }
        float inv = 1.0f / sum;
#pragma unroll
        for (int j = 0; j < 9; j++) v[j] *= inv;

        int nhw9[9];
#pragma unroll
        for (int j = 0; j < 9; j++) {
            int nh = h + j / 3 - 1;
            nh = (nh < 0) ? -nh : ((nh >= H_) ? 2 * H_ - 2 - nh : nh);
            int nw = w + j % 3 - 1;
            nw = (nw < 0) ? -nw : ((nw >= W_) ? 2 * W_ - 2 - nw : nw);
            nhw9[j] = nh * W_ + nw;
        }
        const float* y3 = yn + (size_t)(32 + q) * HW_;
        float acc[8];
#pragma unroll
        for (int g = 0; g < 8; g++) acc[g] = 0.0f;
#pragma unroll
        for (int j = 0; j < 9; j++) {
            const int nhw = nhw9[j];
            const float wj = v[j];
#pragma unroll
            for (int g = 0; g < 8; g++)
                acc[g] = fmaf(wj, y3[(size_t)(g * 8) * HW_ + nhw], acc[g]);
        }
        float* on = out + (size_t)n * 64 * HW_ + hw;
#pragma unroll
        for (int g = 0; g < 8; g++)
            on[(size_t)(g * 8 + q) * HW_] = acc[g];
    }
}

// -------------------------------------------------------------------------
// Launcher.
// -------------------------------------------------------------------------
extern "C" void kernel_launch(void* const* d_in, const int* in_sizes, int n_in,
                              void* d_out, int out_size) {
    const float* x   = (const float*)d_in[0];
    const float* w1  = (const float*)d_in[1];
    const float* w2  = (const float*)d_in[2];
    const float* w3  = (const float*)d_in[3];
    const float* cp  = (const float*)d_in[4];
    const float* cw1 = (const float*)d_in[5];
    const float* cw2 = (const float*)d_in[6];
    const float* g1  = (const float*)d_in[7];
    const float* b1  = (const float*)d_in[8];
    const float* m1  = (const float*)d_in[9];
    const float* v1  = (const float*)d_in[10];
    const float* g2  = (const float*)d_in[11];
    const float* b2  = (const float*)d_in[12];
    const float* m2  = (const float*)d_in[13];
    const float* v2  = (const float*)d_in[14];
    float* out = (float*)d_out;

    cudaFuncSetAttribute(sam_gemm_mma,
                         cudaFuncAttributeMaxDynamicSharedMemorySize, SMEM_MMA);

    dim3 gg(25, N_);                  // 25 px tiles (last clamped) x 16 n
    sam_gemm_mma<<<gg, 256, SMEM_MMA>>>(x, w1, w2, w3);

    dim3 ga(HW_ / 32, N_);            // 98 x 16
    sam_attn_kernel<<<ga, 288>>>(cp, cw1, cw2,
                                 g1, b1, m1, v1,
                                 g2, b2, m2, v2, out);
}

// round 13
// speedup vs baseline: 3.7692x; 1.0803x over previous
#include <cuda_runtime.h>
#include <cuda_fp16.h>
#include <math.h>
#include <stdint.h>

#define H_ 56
#define W_ 56
#define HW_ 3136
#define N_ 16
#define C_ 256
#define CH_ 96
#define EPSBN 1e-3f

// Scratch: stacked GEMM output y[n][o][hw], o in [0,96):
//   rows 0..15 = x1, 16..31 = x2, 32..95 = x3
__device__ float g_y[N_ * CH_ * HW_];

// ---------------- helpers ----------------
__device__ __forceinline__ uint32_t smem_addr_u32(const void* p) {
    uint32_t a;
    asm("{ .reg .u64 t; cvta.to.shared.u64 t, %1; cvt.u32.u64 %0, t; }"
        : "=r"(a) : "l"(p));
    return a;
}

__device__ __forceinline__ void ldsm_x4(uint32_t* r, uint32_t addr) {
    asm volatile("ldmatrix.sync.aligned.m8n8.x4.shared.b16 {%0,%1,%2,%3}, [%4];"
                 : "=r"(r[0]), "=r"(r[1]), "=r"(r[2]), "=r"(r[3]) : "r"(addr));
}

__device__ __forceinline__ void ldsm_x2t(uint32_t* r, uint32_t addr) {
    asm volatile("ldmatrix.sync.aligned.m8n8.x2.trans.shared.b16 {%0,%1}, [%2];"
                 : "=r"(r[0]), "=r"(r[1]) : "r"(addr));
}

__device__ __forceinline__ void mma_fp16(float* d, const uint32_t* a,
                                         const uint32_t* b) {
    asm volatile(
        "mma.sync.aligned.m16n8k16.row.col.f32.f16.f16.f32 "
        "{%0,%1,%2,%3}, {%4,%5,%6,%7}, {%8,%9}, {%0,%1,%2,%3};"
        : "+f"(d[0]), "+f"(d[1]), "+f"(d[2]), "+f"(d[3])
        : "r"(a[0]), "r"(a[1]), "r"(a[2]), "r"(a[3]), "r"(b[0]), "r"(b[1]));
}

// packed f32x2 FMA and pack/dup/unpack helpers
__device__ __forceinline__ void fma2(unsigned long long& acc,
                                     unsigned long long a,
                                     unsigned long long b) {
    asm("fma.rn.f32x2 %0, %1, %2, %0;" : "+l"(acc) : "l"(a), "l"(b));
}
__device__ __forceinline__ unsigned long long dup2(float w) {
    unsigned long long r;
    asm("mov.b64 %0, {%1, %1};" : "=l"(r) : "f"(w));
    return r;
}
__device__ __forceinline__ unsigned long long pack2(float lo, float hi) {
    unsigned long long r;
    asm("mov.b64 %0, {%1, %2};" : "=l"(r) : "f"(lo), "f"(hi));
    return r;
}
__device__ __forceinline__ void unpack2(unsigned long long v, float& lo, float& hi) {
    asm("mov.b64 {%0, %1}, %2;" : "=f"(lo), "=f"(hi) : "l"(v));
}

// SW128 swizzle for 128B rows (16B granular)
#define SWZ(o) ((o) ^ (((o) >> 3) & 0x70))
// X-tile swizzle: rows of 256B (128 px fp16); XOR 16B-chunk index by k&7
#define XSWZ(k, pxb) ((k) * 256 + ((pxb) ^ (((k) & 7) << 4)))

// smem: double-buffered (X 16384 + W 12288) = 28672 per buffer
#define BUFSZ  28672
#define XF_OFF 0
#define WF_OFF 16384
#define SMEM_MMA (2 * BUFSZ)   // 57344

// -------------------------------------------------------------------------
// Kernel 1: single-term fp16 GEMM via mma.sync, double-buffered smem.
// D[ch=96, px=128] = Wf16[96,256] @ Xf16[256, px]
// One __syncthreads per k-chunk: warps finishing compute(c) stage chunk c+1
// into the other buffer while slow warps still compute -> intra-block overlap.
// -------------------------------------------------------------------------
__global__ __launch_bounds__(256, 2) void sam_gemm_mma(
    const float* __restrict__ x,
    const float* __restrict__ w1,
    const float* __restrict__ w2,
    const float* __restrict__ w3) {
    extern __shared__ __align__(1024) char smem[];
    const int tid  = threadIdx.x;
    const int wid  = tid >> 5;
    const int lane = tid & 31;
    const int n    = blockIdx.y;
    int p0 = blockIdx.x * 128;
    if (p0 > HW_ - 128) p0 = HW_ - 128;   // overlap tile: identical dup writes

    const uint32_t sb = smem_addr_u32(smem);
    const float* xn = x + (size_t)n * C_ * HW_ + p0;

    float d[6][2][4];
#pragma unroll
    for (int m = 0; m < 6; m++)
#pragma unroll
        for (int nt = 0; nt < 2; nt++)
#pragma unroll
            for (int r = 0; r < 4; r++) d[m][nt][r] = 0.0f;

    const int xk = tid >> 5, xp4 = (tid & 31) * 4;  // X load coords
    const float* wrow_[3];
    int wq_[3];
#pragma unroll
    for (int i = 0; i < 3; i++) {
        int j = tid + i * 256;
        int o = j >> 3;
        wq_[i] = j & 7;
        wrow_[i] = (o < 16) ? (w1 + o * C_)
                 : (o < 32) ? (w2 + (o - 16) * C_)
                            : (w3 + (o - 32) * C_);
    }

    float4 Xr[8];        // X prefetch regs

#define LOADX(kb)                                                              \
    _Pragma("unroll")                                                          \
    for (int i = 0; i < 8; i++)                                                \
        Xr[i] = *(const float4*)(xn + (size_t)((kb) + xk + i * 8) * HW_ + xp4)

    // Stage W chunk kb into buffer base bb (LDG L2-hot + convert + STS)
#define STAGEW(bb, kb)                                                         \
    _Pragma("unroll")                                                          \
    for (int i = 0; i < 3; i++) {                                              \
        int j = tid + i * 256;                                                 \
        int o = j >> 3, q = j & 7;                                             \
        float4 va = *(const float4*)(wrow_[i] + (kb) + wq_[i] * 8);            \
        float4 vb = *(const float4*)(wrow_[i] + (kb) + wq_[i] * 8 + 4);        \
        __half2 h0 = __floats2half2_rn(va.x, va.y);                            \
        __half2 h1 = __floats2half2_rn(va.z, va.w);                            \
        __half2 h2 = __floats2half2_rn(vb.x, vb.y);                            \
        __half2 h3 = __floats2half2_rn(vb.z, vb.w);                            \
        int off = SWZ(o * 128 + q * 16);                                       \
        uint4 hv; hv.x = *(uint32_t*)&h0; hv.y = *(uint32_t*)&h1;              \
                  hv.z = *(uint32_t*)&h2; hv.w = *(uint32_t*)&h3;              \
        *(uint4*)(smem + (bb) + WF_OFF + off) = hv;                            \
    }

    // Stage X (from Xr regs) into buffer base bb
#define STAGEX(bb)                                                             \
    _Pragma("unroll")                                                          \
    for (int i = 0; i < 8; i++) {                                              \
        int k = xk + i * 8;                                                    \
        float4 v = Xr[i];                                                      \
        __half2 h0 = __floats2half2_rn(v.x, v.y);                              \
        __half2 h1 = __floats2half2_rn(v.z, v.w);                              \
        int off = XSWZ(k, xp4 * 2);                                            \
        uint2 hw_; hw_.x = *(uint32_t*)&h0; hw_.y = *(uint32_t*)&h1;           \
        *(uint2*)(smem + (bb) + XF_OFF + off) = hw_;                           \
    }

    // ---- prologue: stage chunk 0, prefetch chunk 1 ----
    LOADX(0);
    STAGEW(0, 0);
    STAGEX(0);
    LOADX(64);
    __syncthreads();

    for (int c = 0; c < 4; c++) {
        const int bb = (c & 1) * BUFSZ;

        // ---- compute chunk c from buffer bb: 4 k16 steps ----
#pragma unroll
        for (int ks = 0; ks < 4; ks++) {
            uint32_t bx[2][2];
            const int bk = ks * 16 + (lane & 15);
#pragma unroll
            for (int nt = 0; nt < 2; nt++) {
                int pxb = wid * 32 + nt * 16;
                ldsm_x2t(bx[nt], sb + bb + XF_OFF + XSWZ(bk, pxb));
            }
            const int ach  = (lane & 15);
            const int acol = ks * 32 + ((lane >> 4) << 4);
#pragma unroll
            for (int m = 0; m < 6; m++) {
                uint32_t wf[4];
                ldsm_x4(wf, sb + bb + WF_OFF + SWZ((m * 16 + ach) * 128 + acol));
#pragma unroll
                for (int nt = 0; nt < 2; nt++)
                    mma_fp16(d[m][nt], wf, bx[nt]);
            }
        }

        // ---- stage chunk c+1 into the other buffer (no barrier before) ----
        if (c < 3) {
            const int nb = ((c + 1) & 1) * BUFSZ;
            STAGEW(nb, (c + 1) * 64);
            STAGEX(nb);
            if (c < 2) LOADX((c + 2) * 64);
            __syncthreads();   // staging visible before next compute
        }
    }
#undef LOADX
#undef STAGEW
#undef STAGEX

    // ---- epilogue: fragment -> g_y[ch][px], float2 stores ----
    const int gid = lane >> 2, tig = lane & 3;
    float* yn = g_y + (size_t)n * CH_ * HW_;
    const int pxb = p0 + wid * 16 + 2 * tig;
#pragma unroll
    for (int m = 0; m < 6; m++) {
#pragma unroll
        for (int nt = 0; nt < 2; nt++) {
            int px = pxb + nt * 8;
            int ch = m * 16 + gid;
            float2 v0; v0.x = d[m][nt][0]; v0.y = d[m][nt][1];
            float2 v1; v1.x = d[m][nt][2]; v1.y = d[m][nt][3];
            *(float2*)&yn[(size_t)ch * HW_ + px] = v0;
            *(float2*)&yn[(size_t)(ch + 8) * HW_ + px] = v1;
        }
    }
}

// -------------------------------------------------------------------------
// Kernel 2: fused attention (R11 version: ch-major x2 gathers, packed
// f32x2 matvecs, fused softmax+aggregation). Measured 27.36us.
// -------------------------------------------------------------------------
__global__ __launch_bounds__(288, 4) void sam_attn_kernel(
    const float* __restrict__ convp,
    const float* __restrict__ w1c,
    const float* __restrict__ w2c,
    const float* __restrict__ g1, const float* __restrict__ b1,
    const float* __restrict__ m1, const float* __restrict__ v1,
    const float* __restrict__ g2, const float* __restrict__ b2,
    const float* __restrict__ m2, const float* __restrict__ v2,
    float* __restrict__ out) {
    __shared__ alignas(16) unsigned long long sw1p[18][8];  // [c][o-pair]
    __shared__ alignas(16) unsigned long long sw2p[16][4];  // [o][q-pair]
    __shared__ float scp[4];
    __shared__ float sbn[4][32];
    __shared__ float sx1[16][33];
    __shared__ float sc_s[32 * 74];   // [pix][q + 8*jj], stride 74 (8B-aligned)

    const int t = threadIdx.x;
    if (t < 144) {
        int o2 = t & 7, c = t >> 3;
        sw1p[c][o2] = pack2(w1c[(2 * o2) * 18 + c], w1c[(2 * o2 + 1) * 18 + c]);
    }
    if (t < 64) {
        int o = t >> 2, q2 = t & 3;
        sw2p[o][q2] = pack2(w2c[(2 * q2) * 16 + o], w2c[(2 * q2 + 1) * 16 + o]);
    }
    if (t < 4) scp[t] = convp[t];

    const int n   = blockIdx.y;
    const int hw0 = blockIdx.x * 32;
    const int pix = t & 31;
    const int jj  = t >> 5;
    const int hw  = hw0 + pix;
    const int h   = hw / W_;
    const int w   = hw % W_;

    const float* yn = g_y + (size_t)n * CH_ * HW_;

    // ---- Phase 0: BN affines + center x1 staging ----
    if (t < 32) {
        const int phw = hw0 + t;
        float s1 = g1[phw] * rsqrtf(v1[phw] + EPSBN);
        float s2 = g2[phw] * rsqrtf(v2[phw] + EPSBN);
        sbn[0][t] = s1;
        sbn[1][t] = b1[phw] - m1[phw] * s1;
        sbn[2][t] = s2;
        sbn[3][t] = b2[phw] - m2[phw] * s2;
    }
    if (t < 256) {
#pragma unroll
        for (int i = 0; i < 2; i++) {
            int idx = t + i * 256;
            int c = idx >> 5, p = idx & 31;
            sx1[c][p] = yn[(size_t)c * HW_ + hw0 + p];
        }
    }
    __syncthreads();

    // ---- Phase 1: logits for this (pix, jj) ----
    {
        const float s1 = sbn[0][pix], o1 = sbn[1][pix];
        const float s2 = sbn[2][pix], o2b = sbn[3][pix];

        int di = jj / 3 - 1, dj = jj % 3 - 1;
        int nh = h + di;
        nh = (nh < 0) ? -nh : ((nh >= H_) ? 2 * H_ - 2 - nh : nh);
        int nw = w + dj;
        nw = (nw < 0) ? -nw : ((nw >= W_) ? 2 * W_ - 2 - nw : nw);
        const int nhw = nh * W_ + nw;

        float a[18];
#pragma unroll
        for (int c = 0; c < 16; c++) {
            float r = sx1[c][pix] - yn[(size_t)(16 + c) * HW_ + nhw];
            a[c] = fmaxf(fmaf(r, s1, o1), 0.0f);
        }
        const float lw  = -1.0f + 2.0f * (float)w  / 55.0f;
        const float lh  = -1.0f + 2.0f * (float)h  / 55.0f;
        const float nlw = -1.0f + 2.0f * (float)nw / 55.0f;
        const float nlh = -1.0f + 2.0f * (float)nh / 55.0f;
        const float dp0 = scp[0] * (lw - nlw) + scp[1] * (lh - nlh);
        const float dp1 = scp[2] * (lw - nlw) + scp[3] * (lh - nlh);
        a[16] = fmaxf(fmaf(dp0, s1, o1), 0.0f);
        a[17] = fmaxf(fmaf(dp1, s1, o1), 0.0f);

        // matvec1 packed: hb2[o2] = (hb[2o2], hb[2o2+1])
        unsigned long long hb2[8];
#pragma unroll
        for (int o2 = 0; o2 < 8; o2++) hb2[o2] = 0ull;
#pragma unroll
        for (int c = 0; c < 18; c++) {
            unsigned long long ad = dup2(a[c]);
            ulonglong2 p0 = *(const ulonglong2*)&sw1p[c][0];
            ulonglong2 p1 = *(const ulonglong2*)&sw1p[c][2];
            ulonglong2 p2 = *(const ulonglong2*)&sw1p[c][4];
            ulonglong2 p3 = *(const ulonglong2*)&sw1p[c][6];
            fma2(hb2[0], p0.x, ad); fma2(hb2[1], p0.y, ad);
            fma2(hb2[2], p1.x, ad); fma2(hb2[3], p1.y, ad);
            fma2(hb2[4], p2.x, ad); fma2(hb2[5], p2.y, ad);
            fma2(hb2[6], p3.x, ad); fma2(hb2[7], p3.y, ad);
        }
        float hb[16];
#pragma unroll
        for (int o2 = 0; o2 < 8; o2++) {
            float lo, hi;
            unpack2(hb2[o2], lo, hi);
            hb[2 * o2]     = fmaxf(fmaf(lo, s2, o2b), 0.0f);
            hb[2 * o2 + 1] = fmaxf(fmaf(hi, s2, o2b), 0.0f);
        }

        // matvec2 packed
        unsigned long long sc2[4];
#pragma unroll
        for (int q2 = 0; q2 < 4; q2++) sc2[q2] = 0ull;
#pragma unroll
        for (int o = 0; o < 16; o++) {
            unsigned long long ad = dup2(hb[o]);
            ulonglong2 q0 = *(const ulonglong2*)&sw2p[o][0];
            ulonglong2 q1 = *(const ulonglong2*)&sw2p[o][2];
            fma2(sc2[0], q0.x, ad); fma2(sc2[1], q0.y, ad);
            fma2(sc2[2], q1.x, ad); fma2(sc2[3], q1.y, ad);
        }
        float* dst = &sc_s[pix * 74 + jj * 8];
        *(unsigned long long*)&dst[0] = sc2[0];
        *(unsigned long long*)&dst[2] = sc2[1];
        *(unsigned long long*)&dst[4] = sc2[2];
        *(unsigned long long*)&dst[6] = sc2[3];
    }
    __syncthreads();

    // ---- Phase 2+3 fused: softmax (regs) + aggregation, thread=(q,pix) ----
    if (t < 256) {
        const int q = t >> 5;
        const float* base = &sc_s[pix * 74 + q];
        float v[9];
#pragma unroll
        for (int j = 0; j < 9; j++) v[j] = base[j * 8];
        float mx = v[0];
#pragma unroll
        for (int j = 1; j < 9; j++) mx = fmaxf(mx, v[j]);
        float sum = 0.0f;
#pragma unroll
        for (int j = 0; j < 9; j++) { v[j] = __expf(v[j] - mx); sum += v[j]; }
        float inv = 1.0f / sum;
#pragma unroll
        for (int j = 0; j < 9; j++) v[j] *= inv;

        int nhw9[9];
#pragma unroll
        for (int j = 0; j < 9; j++) {
            int nh = h + j / 3 - 1;
            nh = (nh < 0) ? -nh : ((nh >= H_) ? 2 * H_ - 2 - nh : nh);
            int nw = w + j % 3 - 1;
            nw = (nw < 0) ? -nw : ((nw >= W_) ? 2 * W_ - 2 - nw : nw);
            nhw9[j] = nh * W_ + nw;
        }
        const float* y3 = yn + (size_t)(32 + q) * HW_;
        float acc[8];
#pragma unroll
        for (int g = 0; g < 8; g++) acc[g] = 0.0f;
#pragma unroll
        for (int j = 0; j < 9; j++) {
            const int nhw = nhw9[j];
            const float wj = v[j];
#pragma unroll
            for (int g = 0; g < 8; g++)
                acc[g] = fmaf(wj, y3[(size_t)(g * 8) * HW_ + nhw], acc[g]);
        }
        float* on = out + (size_t)n * 64 * HW_ + hw;
#pragma unroll
        for (int g = 0; g < 8; g++)
            on[(size_t)(g * 8 + q) * HW_] = acc[g];
    }
}

// -------------------------------------------------------------------------
// Launcher.
// -------------------------------------------------------------------------
extern "C" void kernel_launch(void* const* d_in, const int* in_sizes, int n_in,
                              void* d_out, int out_size) {
    const float* x   = (const float*)d_in[0];
    const float* w1  = (const float*)d_in[1];
    const float* w2  = (const float*)d_in[2];
    const float* w3  = (const float*)d_in[3];
    const float* cp  = (const float*)d_in[4];
    const float* cw1 = (const float*)d_in[5];
    const float* cw2 = (const float*)d_in[6];
    const float* g1  = (const float*)d_in[7];
    const float* b1  = (const float*)d_in[8];
    const float* m1  = (const float*)d_in[9];
    const float* v1  = (const float*)d_in[10];
    const float* g2  = (const float*)d_in[11];
    const float* b2  = (const float*)d_in[12];
    const float* m2  = (const float*)d_in[13];
    const float* v2  = (const float*)d_in[14];
    float* out = (float*)d_out;

    cudaFuncSetAttribute(sam_gemm_mma,
                         cudaFuncAttributeMaxDynamicSharedMemorySize, SMEM_MMA);

    dim3 gg(25, N_);                  // 25 px tiles (last clamped) x 16 n
    sam_gemm_mma<<<gg, 256, SMEM_MMA>>>(x, w1, w2, w3);

    dim3 ga(HW_ / 32, N_);            // 98 x 16
    sam_attn_kernel<<<ga, 288>>>(cp, cw1, cw2,
                                 g1, b1, m1, v1,
                                 g2, b2, m2, v2, out);
}

// round 14
// speedup vs baseline: 3.7718x; 1.0007x over previous
#include <cuda_runtime.h>
#include <cuda_fp16.h>
#include <math.h>
#include <stdint.h>

#define H_ 56
#define W_ 56
#define HW_ 3136
#define N_ 16
#define C_ 256
#define CH_ 96
#define EPSBN 1e-3f

// Scratch: stacked GEMM output y[n][o][hw], o in [0,96):
//   rows 0..15 = x1, 16..31 = x2, 32..95 = x3
__device__ float g_y[N_ * CH_ * HW_];

// ---------------- helpers ----------------
__device__ __forceinline__ uint32_t smem_addr_u32(const void* p) {
    uint32_t a;
    asm("{ .reg .u64 t; cvta.to.shared.u64 t, %1; cvt.u32.u64 %0, t; }"
        : "=r"(a) : "l"(p));
    return a;
}

__device__ __forceinline__ void ldsm_x4(uint32_t* r, uint32_t addr) {
    asm volatile("ldmatrix.sync.aligned.m8n8.x4.shared.b16 {%0,%1,%2,%3}, [%4];"
                 : "=r"(r[0]), "=r"(r[1]), "=r"(r[2]), "=r"(r[3]) : "r"(addr));
}

__device__ __forceinline__ void ldsm_x2t(uint32_t* r, uint32_t addr) {
    asm volatile("ldmatrix.sync.aligned.m8n8.x2.trans.shared.b16 {%0,%1}, [%2];"
                 : "=r"(r[0]), "=r"(r[1]) : "r"(addr));
}

__device__ __forceinline__ void mma_fp16(float* d, const uint32_t* a,
                                         const uint32_t* b) {
    asm volatile(
        "mma.sync.aligned.m16n8k16.row.col.f32.f16.f16.f32 "
        "{%0,%1,%2,%3}, {%4,%5,%6,%7}, {%8,%9}, {%0,%1,%2,%3};"
        : "+f"(d[0]), "+f"(d[1]), "+f"(d[2]), "+f"(d[3])
        : "r"(a[0]), "r"(a[1]), "r"(a[2]), "r"(a[3]), "r"(b[0]), "r"(b[1]));
}

// packed f32x2 FMA and pack/dup/unpack helpers
__device__ __forceinline__ void fma2(unsigned long long& acc,
                                     unsigned long long a,
                                     unsigned long long b) {
    asm("fma.rn.f32x2 %0, %1, %2, %0;" : "+l"(acc) : "l"(a), "l"(b));
}
__device__ __forceinline__ unsigned long long dup2(float w) {
    unsigned long long r;
    asm("mov.b64 %0, {%1, %1};" : "=l"(r) : "f"(w));
    return r;
}
__device__ __forceinline__ unsigned long long pack2(float lo, float hi) {
    unsigned long long r;
    asm("mov.b64 %0, {%1, %2};" : "=l"(r) : "f"(lo), "f"(hi));
    return r;
}
__device__ __forceinline__ void unpack2(unsigned long long v, float& lo, float& hi) {
    asm("mov.b64 {%0, %1}, %2;" : "=f"(lo), "=f"(hi) : "l"(v));
}

// SW128 swizzle for 128B rows (16B granular)
#define SWZ(o) ((o) ^ (((o) >> 3) & 0x70))
// X-tile swizzle: rows of 256B (128 px fp16); XOR 16B-chunk index by k&7
#define XSWZ(k, pxb) ((k) * 256 + ((pxb) ^ (((k) & 7) << 4)))

// smem: X double buffer (2 x 16384) + W all 4 chunks (4 x 12288)
#define XBUF(i)  ((i) * 16384)
#define WALL_OFF 32768
#define WCHK(c)  (WALL_OFF + (c) * 12288)
#define SMEM_MMA 81920

// -------------------------------------------------------------------------
// Kernel 1: single-term fp16 GEMM via mma.sync.
// D[ch=96, px=128] = Wf16[96,256] @ Xf16[256, px]
// ALL of W (4 chunk tiles, 49KB) staged once in the prologue; the steady
// loop stages only X (double-buffered, reg-prefetched). One barrier/chunk.
// -------------------------------------------------------------------------
__global__ __launch_bounds__(256, 2) void sam_gemm_mma(
    const float* __restrict__ x,
    const float* __restrict__ w1,
    const float* __restrict__ w2,
    const float* __restrict__ w3) {
    extern __shared__ __align__(1024) char smem[];
    const int tid  = threadIdx.x;
    const int wid  = tid >> 5;
    const int lane = tid & 31;
    const int n    = blockIdx.y;
    int p0 = blockIdx.x * 128;
    if (p0 > HW_ - 128) p0 = HW_ - 128;   // overlap tile: identical dup writes

    const uint32_t sb = smem_addr_u32(smem);
    const float* xn = x + (size_t)n * C_ * HW_ + p0;

    float d[6][2][4];
#pragma unroll
    for (int m = 0; m < 6; m++)
#pragma unroll
        for (int nt = 0; nt < 2; nt++)
#pragma unroll
            for (int r = 0; r < 4; r++) d[m][nt][r] = 0.0f;

    const int xk = tid >> 5, xp4 = (tid & 31) * 4;  // X load coords
    const float* wrow_[3];
    int wq_[3];
#pragma unroll
    for (int i = 0; i < 3; i++) {
        int j = tid + i * 256;
        int o = j >> 3;
        wq_[i] = j & 7;
        wrow_[i] = (o < 16) ? (w1 + o * C_)
                 : (o < 32) ? (w2 + (o - 16) * C_)
                            : (w3 + (o - 32) * C_);
    }

    float4 Xr[8];        // X prefetch regs

#define LOADX(kb)                                                              \
    _Pragma("unroll")                                                          \
    for (int i = 0; i < 8; i++)                                                \
        Xr[i] = *(const float4*)(xn + (size_t)((kb) + xk + i * 8) * HW_ + xp4)

    // Stage X (from Xr regs) into X buffer bi
#define STAGEX(bi)                                                             \
    _Pragma("unroll")                                                          \
    for (int i = 0; i < 8; i++) {                                              \
        int k = xk + i * 8;                                                    \
        float4 v = Xr[i];                                                      \
        __half2 h0 = __floats2half2_rn(v.x, v.y);                              \
        __half2 h1 = __floats2half2_rn(v.z, v.w);                              \
        int off = XSWZ(k, xp4 * 2);                                            \
        uint2 hw_; hw_.x = *(uint32_t*)&h0; hw_.y = *(uint32_t*)&h1;           \
        *(uint2*)(smem + XBUF(bi) + off) = hw_;                                \
    }

    // ---- prologue: X chunk0 staged, chunk1 prefetched, ALL W staged ----
    LOADX(0);
    STAGEX(0);
    LOADX(64);
#pragma unroll
    for (int c = 0; c < 4; c++) {
        const int kb = c * 64;
#pragma unroll
        for (int i = 0; i < 3; i++) {
            int j = tid + i * 256;
            int o = j >> 3, q = j & 7;
            float4 va = *(const float4*)(wrow_[i] + kb + wq_[i] * 8);
            float4 vb = *(const float4*)(wrow_[i] + kb + wq_[i] * 8 + 4);
            __half2 h0 = __floats2half2_rn(va.x, va.y);
            __half2 h1 = __floats2half2_rn(va.z, va.w);
            __half2 h2 = __floats2half2_rn(vb.x, vb.y);
            __half2 h3 = __floats2half2_rn(vb.z, vb.w);
            int off = SWZ(o * 128 + q * 16);
            uint4 hv; hv.x = *(uint32_t*)&h0; hv.y = *(uint32_t*)&h1;
                      hv.z = *(uint32_t*)&h2; hv.w = *(uint32_t*)&h3;
            *(uint4*)(smem + WCHK(c) + off) = hv;
        }
    }
    __syncthreads();

    for (int c = 0; c < 4; c++) {
        const int xb = XBUF(c & 1);
        const int wb = WCHK(c);

        // ---- compute chunk c: 4 k16 steps ----
#pragma unroll
        for (int ks = 0; ks < 4; ks++) {
            uint32_t bx[2][2];
            const int bk = ks * 16 + (lane & 15);
#pragma unroll
            for (int nt = 0; nt < 2; nt++) {
                int pxb = wid * 32 + nt * 16;
                ldsm_x2t(bx[nt], sb + xb + XSWZ(bk, pxb));
            }
            const int ach  = (lane & 15);
            const int acol = ks * 32 + ((lane >> 4) << 4);
#pragma unroll
            for (int m = 0; m < 6; m++) {
                uint32_t wf[4];
                ldsm_x4(wf, sb + wb + SWZ((m * 16 + ach) * 128 + acol));
#pragma unroll
                for (int nt = 0; nt < 2; nt++)
                    mma_fp16(d[m][nt], wf, bx[nt]);
            }
        }

        // ---- stage X chunk c+1 into the other buffer ----
        if (c < 3) {
            STAGEX((c + 1) & 1);
            if (c < 2) LOADX((c + 2) * 64);
            __syncthreads();
        }
    }
#undef LOADX
#undef STAGEX

    // ---- epilogue: fragment -> g_y[ch][px], float2 stores ----
    const int gid = lane >> 2, tig = lane & 3;
    float* yn = g_y + (size_t)n * CH_ * HW_;
    const int pxb = p0 + wid * 16 + 2 * tig;
#pragma unroll
    for (int m = 0; m < 6; m++) {
#pragma unroll
        for (int nt = 0; nt < 2; nt++) {
            int px = pxb + nt * 8;
            int ch = m * 16 + gid;
            float2 v0; v0.x = d[m][nt][0]; v0.y = d[m][nt][1];
            float2 v1; v1.x = d[m][nt][2]; v1.y = d[m][nt][3];
            *(float2*)&yn[(size_t)ch * HW_ + px] = v0;
            *(float2*)&yn[(size_t)(ch + 8) * HW_ + px] = v1;
        }
    }
}

// -------------------------------------------------------------------------
// Kernel 2: fused attention. snhw[9][32] staged from phase 1 so phase 2+3
// loads reflect-neighbor indices (9 LDS) instead of recomputing them 8x.
// -------------------------------------------------------------------------
__global__ __launch_bounds__(288, 4) void sam_attn_kernel(
    const float* __restrict__ convp,
    const float* __restrict__ w1c,
    const float* __restrict__ w2c,
    const float* __restrict__ g1, const float* __restrict__ b1,
    const float* __restrict__ m1, const float* __restrict__ v1,
    const float* __restrict__ g2, const float* __restrict__ b2,
    const float* __restrict__ m2, const float* __restrict__ v2,
    float* __restrict__ out) {
    __shared__ alignas(16) unsigned long long sw1p[18][8];  // [c][o-pair]
    __shared__ alignas(16) unsigned long long sw2p[16][4];  // [o][q-pair]
    __shared__ float scp[4];
    __shared__ float sbn[4][32];
    __shared__ float sx1[16][33];
    __shared__ int   snhw[9][32];
    __shared__ float sc_s[32 * 74];   // [pix][q + 8*jj], stride 74 (8B-aligned)

    const int t = threadIdx.x;
    if (t < 144) {
        int o2 = t & 7, c = t >> 3;
        sw1p[c][o2] = pack2(w1c[(2 * o2) * 18 + c], w1c[(2 * o2 + 1) * 18 + c]);
    }
    if (t < 64) {
        int o = t >> 2, q2 = t & 3;
        sw2p[o][q2] = pack2(w2c[(2 * q2) * 16 + o], w2c[(2 * q2 + 1) * 16 + o]);
    }
    if (t < 4) scp[t] = convp[t];

    const int n   = blockIdx.y;
    const int hw0 = blockIdx.x * 32;
    const int pix = t & 31;
    const int jj  = t >> 5;
    const int hw  = hw0 + pix;
    const int h   = hw / W_;
    const int w   = hw % W_;

    const float* yn = g_y + (size_t)n * CH_ * HW_;

    // ---- Phase 0: BN affines + center x1 staging ----
    if (t < 32) {
        const int phw = hw0 + t;
        float s1 = g1[phw] * rsqrtf(v1[phw] + EPSBN);
        float s2 = g2[phw] * rsqrtf(v2[phw] + EPSBN);
        sbn[0][t] = s1;
        sbn[1][t] = b1[phw] - m1[phw] * s1;
        sbn[2][t] = s2;
        sbn[3][t] = b2[phw] - m2[phw] * s2;
    }
    if (t < 256) {
#pragma unroll
        for (int i = 0; i < 2; i++) {
            int idx = t + i * 256;
            int c = idx >> 5, p = idx & 31;
            sx1[c][p] = yn[(size_t)c * HW_ + hw0 + p];
        }
    }
    __syncthreads();

    // ---- Phase 1: logits for this (pix, jj) ----
    {
        const float s1 = sbn[0][pix], o1 = sbn[1][pix];
        const float s2 = sbn[2][pix], o2b = sbn[3][pix];

        int di = jj / 3 - 1, dj = jj % 3 - 1;
        int nh = h + di;
        nh = (nh < 0) ? -nh : ((nh >= H_) ? 2 * H_ - 2 - nh : nh);
        int nw = w + dj;
        nw = (nw < 0) ? -nw : ((nw >= W_) ? 2 * W_ - 2 - nw : nw);
        const int nhw = nh * W_ + nw;
        snhw[jj][pix] = nhw;            // stage for phase 2+3

        float a[18];
#pragma unroll
        for (int c = 0; c < 16; c++) {
            float r = sx1[c][pix] - yn[(size_t)(16 + c) * HW_ + nhw];
            a[c] = fmaxf(fmaf(r, s1, o1), 0.0f);
        }
        const float lw  = -1.0f + 2.0f * (float)w  / 55.0f;
        const float lh  = -1.0f + 2.0f * (float)h  / 55.0f;
        const float nlw = -1.0f + 2.0f * (float)nw / 55.0f;
        const float nlh = -1.0f + 2.0f * (float)nh / 55.0f;
        const float dp0 = scp[0] * (lw - nlw) + scp[1] * (lh - nlh);
        const float dp1 = scp[2] * (lw - nlw) + scp[3] * (lh - nlh);
        a[16] = fmaxf(fmaf(dp0, s1, o1), 0.0f);
        a[17] = fmaxf(fmaf(dp1, s1, o1), 0.0f);

        // matvec1 packed: hb2[o2] = (hb[2o2], hb[2o2+1])
        unsigned long long hb2[8];
#pragma unroll
        for (int o2 = 0; o2 < 8; o2++) hb2[o2] = 0ull;
#pragma unroll
        for (int c = 0; c < 18; c++) {
            unsigned long long ad = dup2(a[c]);
            ulonglong2 p0 = *(const ulonglong2*)&sw1p[c][0];
            ulonglong2 p1 = *(const ulonglong2*)&sw1p[c][2];
            ulonglong2 p2 = *(const ulonglong2*)&sw1p[c][4];
            ulonglong2 p3 = *(const ulonglong2*)&sw1p[c][6];
            fma2(hb2[0], p0.x, ad); fma2(hb2[1], p0.y, ad);
            fma2(hb2[2], p1.x, ad); fma2(hb2[3], p1.y, ad);
            fma2(hb2[4], p2.x, ad); fma2(hb2[5], p2.y, ad);
            fma2(hb2[6], p3.x, ad); fma2(hb2[7], p3.y, ad);
        }
        float hb[16];
#pragma unroll
        for (int o2 = 0; o2 < 8; o2++) {
            float lo, hi;
            unpack2(hb2[o2], lo, hi);
            hb[2 * o2]     = fmaxf(fmaf(lo, s2, o2b), 0.0f);
            hb[2 * o2 + 1] = fmaxf(fmaf(hi, s2, o2b), 0.0f);
        }

        // matvec2 packed
        unsigned long long sc2[4];
#pragma unroll
        for (int q2 = 0; q2 < 4; q2++) sc2[q2] = 0ull;
#pragma unroll
        for (int o = 0; o < 16; o++) {
            unsigned long long ad = dup2(hb[o]);
            ulonglong2 q0 = *(const ulonglong2*)&sw2p[o][0];
            ulonglong2 q1 = *(const ulonglong2*)&sw2p[o][2];
            fma2(sc2[0], q0.x, ad); fma2(sc2[1], q0.y, ad);
            fma2(sc2[2], q1.x, ad); fma2(sc2[3], q1.y, ad);
        }
        float* dst = &sc_s[pix * 74 + jj * 8];
        *(unsigned long long*)&dst[0] = sc2[0];
        *(unsigned long long*)&dst[2] = sc2[1];
        *(unsigned long long*)&dst[4] = sc2[2];
        *(unsigned long long*)&dst[6] = sc2[3];
    }
    __syncthreads();

    // ---- Phase 2+3 fused: softmax (regs) + aggregation, thread=(q,pix) ----
    if (t < 256) {
        const int q = t >> 5;
        const float* base = &sc_s[pix * 74 + q];
        float v[9];
#pragma unroll
        for (int j = 0; j < 9; j++) v[j] = base[j * 8];
        float mx = v[0];
#pragma unroll
        for (int j = 1; j < 9; j++) mx = fmaxf(mx, v[j]);
        float sum = 0.0f;
#pragma unroll
        for (int j = 0; j < 9; j++) { v[j] = __expf(v[j] - mx); sum += v[j]; }
        float inv = 1.0f / sum;
#pragma unroll
        for (int j = 0; j < 9; j++) v[j] *= inv;

        int nhw9[9];
#pragma unroll
        for (int j = 0; j < 9; j++) nhw9[j] = snhw[j][pix];

        const float* y3 = yn + (size_t)(32 + q) * HW_;
        float acc[8];
#pragma unroll
        for (int g = 0; g < 8; g++) acc[g] = 0.0f;
#pragma unroll
        for (int j = 0; j < 9; j++) {
            const int nhw = nhw9[j];
            const float wj = v[j];
#pragma unroll
            for (int g = 0; g < 8; g++)
                acc[g] = fmaf(wj, y3[(size_t)(g * 8) * HW_ + nhw], acc[g]);
        }
        float* on = out + (size_t)n * 64 * HW_ + hw;
#pragma unroll
        for (int g = 0; g < 8; g++)
            on[(size_t)(g * 8 + q) * HW_] = acc[g];
    }
}

// -------------------------------------------------------------------------
// Launcher.
// -------------------------------------------------------------------------
extern "C" void kernel_launch(void* const* d_in, const int* in_sizes, int n_in,
                              void* d_out, int out_size) {
    const float* x   = (const float*)d_in[0];
    const float* w1  = (const float*)d_in[1];
    const float* w2  = (const float*)d_in[2];
    const float* w3  = (const float*)d_in[3];
    const float* cp  = (const float*)d_in[4];
    const float* cw1 = (const float*)d_in[5];
    const float* cw2 = (const float*)d_in[6];
    const float* g1  = (const float*)d_in[7];
    const float* b1  = (const float*)d_in[8];
    const float* m1  = (const float*)d_in[9];
    const float* v1  = (const float*)d_in[10];
    const float* g2  = (const float*)d_in[11];
    const float* b2  = (const float*)d_in[12];
    const float* m2  = (const float*)d_in[13];
    const float* v2  = (const float*)d_in[14];
    float* out = (float*)d_out;

    cudaFuncSetAttribute(sam_gemm_mma,
                         cudaFuncAttributeMaxDynamicSharedMemorySize, SMEM_MMA);

    dim3 gg(25, N_);                  // 25 px tiles (last clamped) x 16 n
    sam_gemm_mma<<<gg, 256, SMEM_MMA>>>(x, w1, w2, w3);

    dim3 ga(HW_ / 32, N_);            // 98 x 16
    sam_attn_kernel<<<ga, 288>>>(cp, cw1, cw2,
                                 g1, b1, m1, v1,
                                 g2, b2, m2, v2, out);
}

// round 15
// speedup vs baseline: 3.9351x; 1.0433x over previous
#include <cuda_runtime.h>
#include <cuda_fp16.h>
#include <math.h>
#include <stdint.h>

#define H_ 56
#define W_ 56
#define HW_ 3136
#define N_ 16
#define C_ 256
#define CH_ 96
#define EPSBN 1e-3f

// Scratch: stacked GEMM output y[n][o][hw], o in [0,96):
//   rows 0..15 = x1, 16..31 = x2, 32..95 = x3
__device__ float g_y[N_ * CH_ * HW_];

// ---------------- helpers ----------------
__device__ __forceinline__ uint32_t smem_addr_u32(const void* p) {
    uint32_t a;
    asm("{ .reg .u64 t; cvta.to.shared.u64 t, %1; cvt.u32.u64 %0, t; }"
        : "=r"(a) : "l"(p));
    return a;
}

__device__ __forceinline__ void ldsm_x4(uint32_t* r, uint32_t addr) {
    asm volatile("ldmatrix.sync.aligned.m8n8.x4.shared.b16 {%0,%1,%2,%3}, [%4];"
                 : "=r"(r[0]), "=r"(r[1]), "=r"(r[2]), "=r"(r[3]) : "r"(addr));
}

__device__ __forceinline__ void ldsm_x2t(uint32_t* r, uint32_t addr) {
    asm volatile("ldmatrix.sync.aligned.m8n8.x2.trans.shared.b16 {%0,%1}, [%2];"
                 : "=r"(r[0]), "=r"(r[1]) : "r"(addr));
}

__device__ __forceinline__ void mma_fp16(float* d, const uint32_t* a,
                                         const uint32_t* b) {
    asm volatile(
        "mma.sync.aligned.m16n8k16.row.col.f32.f16.f16.f32 "
        "{%0,%1,%2,%3}, {%4,%5,%6,%7}, {%8,%9}, {%0,%1,%2,%3};"
        : "+f"(d[0]), "+f"(d[1]), "+f"(d[2]), "+f"(d[3])
        : "r"(a[0]), "r"(a[1]), "r"(a[2]), "r"(a[3]), "r"(b[0]), "r"(b[1]));
}

// packed f32x2 FMA and pack/dup/unpack helpers
__device__ __forceinline__ void fma2(unsigned long long& acc,
                                     unsigned long long a,
                                     unsigned long long b) {
    asm("fma.rn.f32x2 %0, %1, %2, %0;" : "+l"(acc) : "l"(a), "l"(b));
}
__device__ __forceinline__ unsigned long long dup2(float w) {
    unsigned long long r;
    asm("mov.b64 %0, {%1, %1};" : "=l"(r) : "f"(w));
    return r;
}
__device__ __forceinline__ unsigned long long pack2(float lo, float hi) {
    unsigned long long r;
    asm("mov.b64 %0, {%1, %2};" : "=l"(r) : "f"(lo), "f"(hi));
    return r;
}
__device__ __forceinline__ void unpack2(unsigned long long v, float& lo, float& hi) {
    asm("mov.b64 {%0, %1}, %2;" : "=f"(lo), "=f"(hi) : "l"(v));
}

// SW128 swizzle for 128B rows (16B granular)
#define SWZ(o) ((o) ^ (((o) >> 3) & 0x70))
// X-tile swizzle: rows of 256B (128 px fp16); XOR 16B-chunk index by k&7
#define XSWZ(k, pxb) ((k) * 256 + ((pxb) ^ (((k) & 7) << 4)))

// smem: X double buffer (2 x 16384) + W all 4 chunks (4 x 12288)
#define XBUF(i)  ((i) * 16384)
#define WALL_OFF 32768
#define WCHK(c)  (WALL_OFF + (c) * 12288)
#define SMEM_MMA 81920

// -------------------------------------------------------------------------
// Kernel 1: single-term fp16 GEMM via mma.sync (unchanged from R14, 18.4us).
// -------------------------------------------------------------------------
__global__ __launch_bounds__(256, 2) void sam_gemm_mma(
    const float* __restrict__ x,
    const float* __restrict__ w1,
    const float* __restrict__ w2,
    const float* __restrict__ w3) {
    extern __shared__ __align__(1024) char smem[];
    const int tid  = threadIdx.x;
    const int wid  = tid >> 5;
    const int lane = tid & 31;
    const int n    = blockIdx.y;
    int p0 = blockIdx.x * 128;
    if (p0 > HW_ - 128) p0 = HW_ - 128;   // overlap tile: identical dup writes

    const uint32_t sb = smem_addr_u32(smem);
    const float* xn = x + (size_t)n * C_ * HW_ + p0;

    float d[6][2][4];
#pragma unroll
    for (int m = 0; m < 6; m++)
#pragma unroll
        for (int nt = 0; nt < 2; nt++)
#pragma unroll
            for (int r = 0; r < 4; r++) d[m][nt][r] = 0.0f;

    const int xk = tid >> 5, xp4 = (tid & 31) * 4;  // X load coords
    const float* wrow_[3];
    int wq_[3];
#pragma unroll
    for (int i = 0; i < 3; i++) {
        int j = tid + i * 256;
        int o = j >> 3;
        wq_[i] = j & 7;
        wrow_[i] = (o < 16) ? (w1 + o * C_)
                 : (o < 32) ? (w2 + (o - 16) * C_)
                            : (w3 + (o - 32) * C_);
    }

    float4 Xr[8];        // X prefetch regs

#define LOADX(kb)                                                              \
    _Pragma("unroll")                                                          \
    for (int i = 0; i < 8; i++)                                                \
        Xr[i] = *(const float4*)(xn + (size_t)((kb) + xk + i * 8) * HW_ + xp4)

#define STAGEX(bi)                                                             \
    _Pragma("unroll")                                                          \
    for (int i = 0; i < 8; i++) {                                              \
        int k = xk + i * 8;                                                    \
        float4 v = Xr[i];                                                      \
        __half2 h0 = __floats2half2_rn(v.x, v.y);                              \
        __half2 h1 = __floats2half2_rn(v.z, v.w);                              \
        int off = XSWZ(k, xp4 * 2);                                            \
        uint2 hw_; hw_.x = *(uint32_t*)&h0; hw_.y = *(uint32_t*)&h1;           \
        *(uint2*)(smem + XBUF(bi) + off) = hw_;                                \
    }

    // ---- prologue: X chunk0 staged, chunk1 prefetched, ALL W staged ----
    LOADX(0);
    STAGEX(0);
    LOADX(64);
#pragma unroll
    for (int c = 0; c < 4; c++) {
        const int kb = c * 64;
#pragma unroll
        for (int i = 0; i < 3; i++) {
            int j = tid + i * 256;
            int o = j >> 3, q = j & 7;
            float4 va = *(const float4*)(wrow_[i] + kb + wq_[i] * 8);
            float4 vb = *(const float4*)(wrow_[i] + kb + wq_[i] * 8 + 4);
            __half2 h0 = __floats2half2_rn(va.x, va.y);
            __half2 h1 = __floats2half2_rn(va.z, va.w);
            __half2 h2 = __floats2half2_rn(vb.x, vb.y);
            __half2 h3 = __floats2half2_rn(vb.z, vb.w);
            int off = SWZ(o * 128 + q * 16);
            uint4 hv; hv.x = *(uint32_t*)&h0; hv.y = *(uint32_t*)&h1;
                      hv.z = *(uint32_t*)&h2; hv.w = *(uint32_t*)&h3;
            *(uint4*)(smem + WCHK(c) + off) = hv;
        }
    }
    __syncthreads();

    for (int c = 0; c < 4; c++) {
        const int xb = XBUF(c & 1);
        const int wb = WCHK(c);

#pragma unroll
        for (int ks = 0; ks < 4; ks++) {
            uint32_t bx[2][2];
            const int bk = ks * 16 + (lane & 15);
#pragma unroll
            for (int nt = 0; nt < 2; nt++) {
                int pxb = wid * 32 + nt * 16;
                ldsm_x2t(bx[nt], sb + xb + XSWZ(bk, pxb));
            }
            const int ach  = (lane & 15);
            const int acol = ks * 32 + ((lane >> 4) << 4);
#pragma unroll
            for (int m = 0; m < 6; m++) {
                uint32_t wf[4];
                ldsm_x4(wf, sb + wb + SWZ((m * 16 + ach) * 128 + acol));
#pragma unroll
                for (int nt = 0; nt < 2; nt++)
                    mma_fp16(d[m][nt], wf, bx[nt]);
            }
        }

        if (c < 3) {
            STAGEX((c + 1) & 1);
            if (c < 2) LOADX((c + 2) * 64);
            __syncthreads();
        }
    }
#undef LOADX
#undef STAGEX

    const int gid = lane >> 2, tig = lane & 3;
    float* yn = g_y + (size_t)n * CH_ * HW_;
    const int pxb = p0 + wid * 16 + 2 * tig;
#pragma unroll
    for (int m = 0; m < 6; m++) {
#pragma unroll
        for (int nt = 0; nt < 2; nt++) {
            int px = pxb + nt * 8;
            int ch = m * 16 + gid;
            float2 v0; v0.x = d[m][nt][0]; v0.y = d[m][nt][1];
            float2 v1; v1.x = d[m][nt][2]; v1.y = d[m][nt][3];
            *(float2*)&yn[(size_t)ch * HW_ + px] = v0;
            *(float2*)&yn[(size_t)(ch + 8) * HW_ + px] = v1;
        }
    }
}

// -------------------------------------------------------------------------
// Kernel 2: fused attention, 64 px/block, TWO pixels per thread (px, px+32).
// Doubles ILP on all LDG/FFMA chains and reuses every weight-LDS for 2
// pixels; snhw staging reverted (recompute is cheaper).
// -------------------------------------------------------------------------
__global__ __launch_bounds__(288, 2) void sam_attn_kernel(
    const float* __restrict__ convp,
    const float* __restrict__ w1c,
    const float* __restrict__ w2c,
    const float* __restrict__ g1, const float* __restrict__ b1,
    const float* __restrict__ m1, const float* __restrict__ v1,
    const float* __restrict__ g2, const float* __restrict__ b2,
    const float* __restrict__ m2, const float* __restrict__ v2,
    float* __restrict__ out) {
    __shared__ alignas(16) unsigned long long sw1p[18][8];  // [c][o-pair]
    __shared__ alignas(16) unsigned long long sw2p[16][4];  // [o][q-pair]
    __shared__ float scp[4];
    __shared__ float sbn[4][64];
    __shared__ float sx1[16][65];
    __shared__ float sc_s[64 * 74];   // [pix][q + 8*jj]

    const int t = threadIdx.x;
    if (t < 144) {
        int o2 = t & 7, c = t >> 3;
        sw1p[c][o2] = pack2(w1c[(2 * o2) * 18 + c], w1c[(2 * o2 + 1) * 18 + c]);
    }
    if (t < 64) {
        int o = t >> 2, q2 = t & 3;
        sw2p[o][q2] = pack2(w2c[(2 * q2) * 16 + o], w2c[(2 * q2 + 1) * 16 + o]);
    }
    if (t < 4) scp[t] = convp[t];

    const int n   = blockIdx.y;
    const int hw0 = blockIdx.x * 64;          // 3136/64 = 49 exact
    const int pix = t & 31;
    const int jj  = t >> 5;                   // 0..8

    const float* yn = g_y + (size_t)n * CH_ * HW_;

    // ---- Phase 0: BN affines (64 px) + center x1 staging ----
    if (t < 64) {
        const int phw = hw0 + t;
        float s1 = g1[phw] * rsqrtf(v1[phw] + EPSBN);
        float s2 = g2[phw] * rsqrtf(v2[phw] + EPSBN);
        sbn[0][t] = s1;
        sbn[1][t] = b1[phw] - m1[phw] * s1;
        sbn[2][t] = s2;
        sbn[3][t] = b2[phw] - m2[phw] * s2;
    }
#pragma unroll
    for (int i = 0; i < 4; i++) {
        int idx = t + i * 288;
        if (idx < 1024) {
            int c = idx >> 6, p = idx & 63;
            sx1[c][p] = yn[(size_t)c * HW_ + hw0 + p];
        }
    }
    __syncthreads();

    // ---- Phase 1: logits for (pixA, jj) and (pixB, jj) ----
    {
        const int pA = pix, pB = pix + 32;
        const int hwA = hw0 + pA, hwB = hw0 + pB;
        const int hA = hwA / W_, wA = hwA % W_;
        const int hB = hwB / W_, wB = hwB % W_;
        const float s1A = sbn[0][pA], o1A = sbn[1][pA];
        const float s2A = sbn[2][pA], o2A = sbn[3][pA];
        const float s1B = sbn[0][pB], o1B = sbn[1][pB];
        const float s2B = sbn[2][pB], o2B = sbn[3][pB];

        const int di = jj / 3 - 1, dj = jj % 3 - 1;
        int nhA = hA + di; nhA = (nhA < 0) ? -nhA : ((nhA >= H_) ? 2 * H_ - 2 - nhA : nhA);
        int nwA = wA + dj; nwA = (nwA < 0) ? -nwA : ((nwA >= W_) ? 2 * W_ - 2 - nwA : nwA);
        int nhB = hB + di; nhB = (nhB < 0) ? -nhB : ((nhB >= H_) ? 2 * H_ - 2 - nhB : nhB);
        int nwB = wB + dj; nwB = (nwB < 0) ? -nwB : ((nwB >= W_) ? 2 * W_ - 2 - nwB : nwB);
        const int nhwA = nhA * W_ + nwA;
        const int nhwB = nhB * W_ + nwB;

        float aA[18], aB[18];
#pragma unroll
        for (int c = 0; c < 16; c++) {
            float rA = sx1[c][pA] - yn[(size_t)(16 + c) * HW_ + nhwA];
            float rB = sx1[c][pB] - yn[(size_t)(16 + c) * HW_ + nhwB];
            aA[c] = fmaxf(fmaf(rA, s1A, o1A), 0.0f);
            aB[c] = fmaxf(fmaf(rB, s1B, o1B), 0.0f);
        }
        {
            const float lwA = -1.0f + 2.0f * (float)wA / 55.0f;
            const float lhA = -1.0f + 2.0f * (float)hA / 55.0f;
            const float nlwA = -1.0f + 2.0f * (float)nwA / 55.0f;
            const float nlhA = -1.0f + 2.0f * (float)nhA / 55.0f;
            aA[16] = fmaxf(fmaf(scp[0] * (lwA - nlwA) + scp[1] * (lhA - nlhA), s1A, o1A), 0.0f);
            aA[17] = fmaxf(fmaf(scp[2] * (lwA - nlwA) + scp[3] * (lhA - nlhA), s1A, o1A), 0.0f);
            const float lwB = -1.0f + 2.0f * (float)wB / 55.0f;
            const float lhB = -1.0f + 2.0f * (float)hB / 55.0f;
            const float nlwB = -1.0f + 2.0f * (float)nwB / 55.0f;
            const float nlhB = -1.0f + 2.0f * (float)nhB / 55.0f;
            aB[16] = fmaxf(fmaf(scp[0] * (lwB - nlwB) + scp[1] * (lhB - nlhB), s1B, o1B), 0.0f);
            aB[17] = fmaxf(fmaf(scp[2] * (lwB - nlwB) + scp[3] * (lhB - nlhB), s1B, o1B), 0.0f);
        }

        // matvec1 packed: weights loaded once, used for A and B
        unsigned long long hA2[8], hB2[8];
#pragma unroll
        for (int o2 = 0; o2 < 8; o2++) { hA2[o2] = 0ull; hB2[o2] = 0ull; }
#pragma unroll
        for (int c = 0; c < 18; c++) {
            unsigned long long adA = dup2(aA[c]);
            unsigned long long adB = dup2(aB[c]);
            ulonglong2 p0 = *(const ulonglong2*)&sw1p[c][0];
            ulonglong2 p1 = *(const ulonglong2*)&sw1p[c][2];
            ulonglong2 p2 = *(const ulonglong2*)&sw1p[c][4];
            ulonglong2 p3 = *(const ulonglong2*)&sw1p[c][6];
            fma2(hA2[0], p0.x, adA); fma2(hB2[0], p0.x, adB);
            fma2(hA2[1], p0.y, adA); fma2(hB2[1], p0.y, adB);
            fma2(hA2[2], p1.x, adA); fma2(hB2[2], p1.x, adB);
            fma2(hA2[3], p1.y, adA); fma2(hB2[3], p1.y, adB);
            fma2(hA2[4], p2.x, adA); fma2(hB2[4], p2.x, adB);
            fma2(hA2[5], p2.y, adA); fma2(hB2[5], p2.y, adB);
            fma2(hA2[6], p3.x, adA); fma2(hB2[6], p3.x, adB);
            fma2(hA2[7], p3.y, adA); fma2(hB2[7], p3.y, adB);
        }
        float hbA[16], hbB[16];
#pragma unroll
        for (int o2 = 0; o2 < 8; o2++) {
            float lo, hi;
            unpack2(hA2[o2], lo, hi);
            hbA[2 * o2]     = fmaxf(fmaf(lo, s2A, o2A), 0.0f);
            hbA[2 * o2 + 1] = fmaxf(fmaf(hi, s2A, o2A), 0.0f);
            unpack2(hB2[o2], lo, hi);
            hbB[2 * o2]     = fmaxf(fmaf(lo, s2B, o2B), 0.0f);
            hbB[2 * o2 + 1] = fmaxf(fmaf(hi, s2B, o2B), 0.0f);
        }

        // matvec2 packed
        unsigned long long sA2[4], sB2[4];
#pragma unroll
        for (int q2 = 0; q2 < 4; q2++) { sA2[q2] = 0ull; sB2[q2] = 0ull; }
#pragma unroll
        for (int o = 0; o < 16; o++) {
            unsigned long long adA = dup2(hbA[o]);
            unsigned long long adB = dup2(hbB[o]);
            ulonglong2 q0 = *(const ulonglong2*)&sw2p[o][0];
            ulonglong2 q1 = *(const ulonglong2*)&sw2p[o][2];
            fma2(sA2[0], q0.x, adA); fma2(sB2[0], q0.x, adB);
            fma2(sA2[1], q0.y, adA); fma2(sB2[1], q0.y, adB);
            fma2(sA2[2], q1.x, adA); fma2(sB2[2], q1.x, adB);
            fma2(sA2[3], q1.y, adA); fma2(sB2[3], q1.y, adB);
        }
        float* dA = &sc_s[pA * 74 + jj * 8];
        *(unsigned long long*)&dA[0] = sA2[0];
        *(unsigned long long*)&dA[2] = sA2[1];
        *(unsigned long long*)&dA[4] = sA2[2];
        *(unsigned long long*)&dA[6] = sA2[3];
        float* dB = &sc_s[pB * 74 + jj * 8];
        *(unsigned long long*)&dB[0] = sB2[0];
        *(unsigned long long*)&dB[2] = sB2[1];
        *(unsigned long long*)&dB[4] = sB2[2];
        *(unsigned long long*)&dB[6] = sB2[3];
    }
    __syncthreads();

    // ---- Phase 2+3 fused, two pixels per thread, thread=(q,pix) ----
    if (t < 256) {
        const int q = t >> 5;
        const float* y3 = yn + (size_t)(32 + q) * HW_;
        float* onb = out + (size_t)n * 64 * HW_;

#pragma unroll
        for (int half = 0; half < 2; half++) {
            const int p = pix + half * 32;
            const int hw = hw0 + p;
            const int h = hw / W_, w = hw % W_;

            const float* base = &sc_s[p * 74 + q];
            float v[9];
#pragma unroll
            for (int j = 0; j < 9; j++) v[j] = base[j * 8];
            float mx = v[0];
#pragma unroll
            for (int j = 1; j < 9; j++) mx = fmaxf(mx, v[j]);
            float sum = 0.0f;
#pragma unroll
            for (int j = 0; j < 9; j++) { v[j] = __expf(v[j] - mx); sum += v[j]; }
            float inv = 1.0f / sum;
#pragma unroll
            for (int j = 0; j < 9; j++) v[j] *= inv;

            float acc[8];
#pragma unroll
            for (int g = 0; g < 8; g++) acc[g] = 0.0f;
#pragma unroll
            for (int j = 0; j < 9; j++) {
                int nh = h + j / 3 - 1;
                nh = (nh < 0) ? -nh : ((nh >= H_) ? 2 * H_ - 2 - nh : nh);
                int nw = w + j % 3 - 1;
                nw = (nw < 0) ? -nw : ((nw >= W_) ? 2 * W_ - 2 - nw : nw);
                const int nhw = nh * W_ + nw;
                const float wj = v[j];
#pragma unroll
                for (int g = 0; g < 8; g++)
                    acc[g] = fmaf(wj, y3[(size_t)(g * 8) * HW_ + nhw], acc[g]);
            }
            float* on = onb + hw;
#pragma unroll
            for (int g = 0; g < 8; g++)
                on[(size_t)(g * 8 + q) * HW_] = acc[g];
        }
    }
}

// -------------------------------------------------------------------------
// Launcher.
// -------------------------------------------------------------------------
extern "C" void kernel_launch(void* const* d_in, const int* in_sizes, int n_in,
                              void* d_out, int out_size) {
    const float* x   = (const float*)d_in[0];
    const float* w1  = (const float*)d_in[1];
    const float* w2  = (const float*)d_in[2];
    const float* w3  = (const float*)d_in[3];
    const float* cp  = (const float*)d_in[4];
    const float* cw1 = (const float*)d_in[5];
    const float* cw2 = (const float*)d_in[6];
    const float* g1  = (const float*)d_in[7];
    const float* b1  = (const float*)d_in[8];
    const float* m1  = (const float*)d_in[9];
    const float* v1  = (const float*)d_in[10];
    const float* g2  = (const float*)d_in[11];
    const float* b2  = (const float*)d_in[12];
    const float* m2  = (const float*)d_in[13];
    const float* v2  = (const float*)d_in[14];
    float* out = (float*)d_out;

    cudaFuncSetAttribute(sam_gemm_mma,
                         cudaFuncAttributeMaxDynamicSharedMemorySize, SMEM_MMA);

    dim3 gg(25, N_);                  // 25 px tiles (last clamped) x 16 n
    sam_gemm_mma<<<gg, 256, SMEM_MMA>>>(x, w1, w2, w3);

    dim3 ga(HW_ / 64, N_);            // 49 x 16
    sam_attn_kernel<<<ga, 288>>>(cp, cw1, cw2,
                                 g1, b1, m1, v1,
                                 g2, b2, m2, v2, out);
}